// round 2
// baseline (speedup 1.0000x reference)
#include <cuda_runtime.h>
#include <math.h>
#include <stdint.h>

// Problem dims (fixed)
#define Bc 2
#define Tc 2048
#define Ec 1024
#define Hc 16
#define HDc 64
#define Mc (Bc*Tc)   // 4096

// -------- scratch (device globals; no allocation allowed) --------
__device__ float g_Q[Mc*Ec];
__device__ float g_K[Mc*Ec];
__device__ float g_V[Mc*Ec];
__device__ float g_G[Mc*Ec];
__device__ float g_O[Mc*Ec];
__device__ float g_Y[Mc*Ec];
__device__ float g_stats[Bc*Hc*2];
__device__ float g_rope_cos[Tc*HDc];
__device__ float g_rope_sin[Tc*HDc];

// ============================================================
// RoPE table: theta(t,dd) = t * 10000^{-(dd%32)/32}, fp64 accurate
// ============================================================
__global__ void rope_table_kernel() {
    int idx = blockIdx.x * blockDim.x + threadIdx.x;
    if (idx >= Tc*HDc) return;
    int t = idx / HDc;
    int dd = idx % HDc;
    double f = pow(10000.0, -(double)(dd & 31) / 32.0);
    double th = (double)t * f;
    g_rope_cos[idx] = (float)cos(th);
    g_rope_sin[idx] = (float)sin(th);
}

// Apply RoPE in place. One thread per (row, even-dim pair).
__global__ void rope_apply_kernel(float* __restrict__ X) {
    int idx = blockIdx.x * blockDim.x + threadIdx.x;
    if (idx >= Mc*Ec/2) return;
    int row = idx / (Ec/2);
    int p   = idx % (Ec/2);
    int e0  = 2*p;
    int dd0 = e0 % HDc;       // even dim inside head
    int t   = row % Tc;
    float x0 = X[(size_t)row*Ec + e0];
    float x1 = X[(size_t)row*Ec + e0 + 1];
    float c0 = g_rope_cos[t*HDc + dd0],     s0 = g_rope_sin[t*HDc + dd0];
    float c1 = g_rope_cos[t*HDc + dd0 + 1], s1 = g_rope_sin[t*HDc + dd0 + 1];
    X[(size_t)row*Ec + e0]     = x0*c0 - x1*s0;
    X[(size_t)row*Ec + e0 + 1] = x1*c1 + x0*s1;
}

// ============================================================
// SGEMM: C[m,n] = sum_k A[m,k]*W[n,k] + bias[n]
// A: (Md,Kd) rm, W: (Nd,Kd) rm. Tiles 128x128x8, 256 thr, 8x8/thread.
// ============================================================
__global__ void __launch_bounds__(256, 2)
sgemm_bias_kernel(const float* __restrict__ A, const float* __restrict__ W,
                  const float* __restrict__ bias, float* __restrict__ C,
                  int Md, int Nd, int Kd)
{
    __shared__ float As[8][128];
    __shared__ float Bs[8][128];
    int tid = threadIdx.x;
    int bm = blockIdx.y * 128, bn = blockIdx.x * 128;
    int lrow = tid >> 1;          // 0..127
    int lcol = (tid & 1) * 4;     // 0 or 4
    const float* Ap = A + (size_t)(bm + lrow)*Kd + lcol;
    const float* Bp = W + (size_t)(bn + lrow)*Kd + lcol;
    int ty = tid >> 4, tx = tid & 15;

    float4 ra = *(const float4*)Ap;
    float4 rb = *(const float4*)Bp;

    float acc[8][8];
    #pragma unroll
    for (int i = 0; i < 8; i++)
        #pragma unroll
        for (int j = 0; j < 8; j++) acc[i][j] = 0.f;

    for (int k0 = 0; k0 < Kd; k0 += 8) {
        As[lcol+0][lrow] = ra.x; As[lcol+1][lrow] = ra.y;
        As[lcol+2][lrow] = ra.z; As[lcol+3][lrow] = ra.w;
        Bs[lcol+0][lrow] = rb.x; Bs[lcol+1][lrow] = rb.y;
        Bs[lcol+2][lrow] = rb.z; Bs[lcol+3][lrow] = rb.w;
        __syncthreads();
        if (k0 + 8 < Kd) {
            ra = *(const float4*)(Ap + k0 + 8);
            rb = *(const float4*)(Bp + k0 + 8);
        }
        #pragma unroll
        for (int k = 0; k < 8; k++) {
            float4 a0 = *(const float4*)&As[k][ty*8];
            float4 a1 = *(const float4*)&As[k][ty*8 + 4];
            float4 b0 = *(const float4*)&Bs[k][tx*8];
            float4 b1 = *(const float4*)&Bs[k][tx*8 + 4];
            float aa[8] = {a0.x,a0.y,a0.z,a0.w,a1.x,a1.y,a1.z,a1.w};
            float bb[8] = {b0.x,b0.y,b0.z,b0.w,b1.x,b1.y,b1.z,b1.w};
            #pragma unroll
            for (int i = 0; i < 8; i++)
                #pragma unroll
                for (int j = 0; j < 8; j++)
                    acc[i][j] = fmaf(aa[i], bb[j], acc[i][j]);
        }
        __syncthreads();
    }

    #pragma unroll
    for (int i = 0; i < 8; i++) {
        int r = bm + ty*8 + i;
        #pragma unroll
        for (int j = 0; j < 8; j += 4) {
            int c = bn + tx*8 + j;
            float4 o;
            o.x = acc[i][j+0] + bias[c+0];
            o.y = acc[i][j+1] + bias[c+1];
            o.z = acc[i][j+2] + bias[c+2];
            o.w = acc[i][j+3] + bias[c+3];
            *(float4*)&C[(size_t)r*Nd + c] = o;
        }
    }
}

// ============================================================
// Retention (reference semantics, ANTI-causal):
//   O[b,h,i,:] = sum_{j>=i} gamma_h^{j-i} (Q_i.K_j/8) V_j
// grid = (T/64 i-tiles, B*H). 64x64 tiles, two-phase with smem-staged S.
// ============================================================
__global__ void __launch_bounds__(256)
retention_kernel(const float* __restrict__ Q, const float* __restrict__ K,
                 const float* __restrict__ V, float* __restrict__ O)
{
    extern __shared__ float sm[];
    float (*Qs)[68] = (float(*)[68])(sm);              // Qs[d][ii]
    float (*Ks)[68] = (float(*)[68])(sm + 64*68);      // Ks[d][jj]
    float (*Vs)[68] = (float(*)[68])(sm + 2*64*68);    // Vs[jj][d]
    float (*Ss)[68] = (float(*)[68])(sm + 3*64*68);    // Ss[ii][jj]

    int bh = blockIdx.y;
    int b = bh >> 4, h = bh & 15;
    int i0 = blockIdx.x * 64;
    int tid = threadIdx.x;
    int ty = tid >> 4, tx = tid & 15;

    const float* Qh = Q + (size_t)b*Tc*Ec + h*HDc;
    const float* Kh = K + (size_t)b*Tc*Ec + h*HDc;
    const float* Vh = V + (size_t)b*Tc*Ec + h*HDc;
    float*       Oh = O + (size_t)b*Tc*Ec + h*HDc;

    double gamma_d = 1.0 - ldexp(1.0, -(5 + h));
    float lg2 = (float)log2(gamma_d);   // negative

    // load Q tile transposed: Qs[d][ii]
    {
        int ii = tid >> 2;
        int d4 = (tid & 3) * 16;
        #pragma unroll
        for (int c = 0; c < 4; c++) {
            float4 v = *(const float4*)&Qh[(size_t)(i0 + ii)*Ec + d4 + c*4];
            Qs[d4 + c*4 + 0][ii] = v.x;
            Qs[d4 + c*4 + 1][ii] = v.y;
            Qs[d4 + c*4 + 2][ii] = v.z;
            Qs[d4 + c*4 + 3][ii] = v.w;
        }
    }

    // decay factors: dec(i,j) = gamma^{j-i} = gamma^{j0-i0} * gamma^{+jl} * gamma^{-il}
    float rowf[4], colf[4];
    #pragma unroll
    for (int a = 0; a < 4; a++) {
        rowf[a] = exp2f(-(float)(ty*4 + a) * lg2);   // gamma^{-il}
        colf[a] = exp2f( (float)(tx*4 + a) * lg2);   // gamma^{+jl}
    }

    float o[4][4];
    #pragma unroll
    for (int a = 0; a < 4; a++)
        #pragma unroll
        for (int c = 0; c < 4; c++) o[a][c] = 0.f;

    for (int jt = blockIdx.x; jt < Tc/64; jt++) {
        int j0 = jt * 64;
        // largest decay in tile = gamma^{max(0, j0-i0-63)}; beyond 2^-40 -> negligible
        if ((float)(j0 - i0 - 63) * lg2 < -40.0f) break;

        __syncthreads();   // prior phase-B done before we overwrite Ks/Vs
        {
            int jj = tid >> 2;
            int d4 = (tid & 3) * 16;
            #pragma unroll
            for (int c = 0; c < 4; c++) {
                float4 kv = *(const float4*)&Kh[(size_t)(j0 + jj)*Ec + d4 + c*4];
                Ks[d4 + c*4 + 0][jj] = kv.x;
                Ks[d4 + c*4 + 1][jj] = kv.y;
                Ks[d4 + c*4 + 2][jj] = kv.z;
                Ks[d4 + c*4 + 3][jj] = kv.w;
                float4 vv = *(const float4*)&Vh[(size_t)(j0 + jj)*Ec + d4 + c*4];
                *(float4*)&Vs[jj][d4 + c*4] = vv;
            }
        }
        __syncthreads();

        // Phase A: S = Q K^T
        float s[4][4];
        #pragma unroll
        for (int a = 0; a < 4; a++)
            #pragma unroll
            for (int bb = 0; bb < 4; bb++) s[a][bb] = 0.f;
        #pragma unroll 8
        for (int k = 0; k < 64; k++) {
            float4 qa = *(const float4*)&Qs[k][ty*4];
            float4 kb = *(const float4*)&Ks[k][tx*4];
            float qq[4] = {qa.x, qa.y, qa.z, qa.w};
            float kk[4] = {kb.x, kb.y, kb.z, kb.w};
            #pragma unroll
            for (int a = 0; a < 4; a++)
                #pragma unroll
                for (int bb = 0; bb < 4; bb++)
                    s[a][bb] = fmaf(qq[a], kk[bb], s[a][bb]);
        }
        // decay + mask (j >= i) + 1/sqrt(HD)
        float base = exp2f((float)(j0 - i0) * lg2) * 0.125f;
        #pragma unroll
        for (int a = 0; a < 4; a++) {
            int gi = i0 + ty*4 + a;
            #pragma unroll
            for (int bb = 0; bb < 4; bb++) {
                int gj = j0 + tx*4 + bb;
                float dec = (gj >= gi) ? base * rowf[a] * colf[bb] : 0.f;
                s[a][bb] *= dec;
            }
        }
        // stage S
        #pragma unroll
        for (int a = 0; a < 4; a++) {
            float4 sv = make_float4(s[a][0], s[a][1], s[a][2], s[a][3]);
            *(float4*)&Ss[ty*4 + a][tx*4] = sv;
        }
        __syncthreads();

        // Phase B: O += S @ V
        #pragma unroll 4
        for (int jj4 = 0; jj4 < 64; jj4 += 4) {
            float4 v0 = *(const float4*)&Vs[jj4 + 0][tx*4];
            float4 v1 = *(const float4*)&Vs[jj4 + 1][tx*4];
            float4 v2 = *(const float4*)&Vs[jj4 + 2][tx*4];
            float4 v3 = *(const float4*)&Vs[jj4 + 3][tx*4];
            #pragma unroll
            for (int a = 0; a < 4; a++) {
                float4 sa = *(const float4*)&Ss[ty*4 + a][jj4];
                o[a][0] = fmaf(sa.x, v0.x, o[a][0]);
                o[a][1] = fmaf(sa.x, v0.y, o[a][1]);
                o[a][2] = fmaf(sa.x, v0.z, o[a][2]);
                o[a][3] = fmaf(sa.x, v0.w, o[a][3]);
                o[a][0] = fmaf(sa.y, v1.x, o[a][0]);
                o[a][1] = fmaf(sa.y, v1.y, o[a][1]);
                o[a][2] = fmaf(sa.y, v1.z, o[a][2]);
                o[a][3] = fmaf(sa.y, v1.w, o[a][3]);
                o[a][0] = fmaf(sa.z, v2.x, o[a][0]);
                o[a][1] = fmaf(sa.z, v2.y, o[a][1]);
                o[a][2] = fmaf(sa.z, v2.z, o[a][2]);
                o[a][3] = fmaf(sa.z, v2.w, o[a][3]);
                o[a][0] = fmaf(sa.w, v3.x, o[a][0]);
                o[a][1] = fmaf(sa.w, v3.y, o[a][1]);
                o[a][2] = fmaf(sa.w, v3.z, o[a][2]);
                o[a][3] = fmaf(sa.w, v3.w, o[a][3]);
            }
        }
    }

    #pragma unroll
    for (int a = 0; a < 4; a++) {
        float4 ov = make_float4(o[a][0], o[a][1], o[a][2], o[a][3]);
        *(float4*)&Oh[(size_t)(i0 + ty*4 + a)*Ec + tx*4] = ov;
    }
}

// ============================================================
// GroupNorm stats: per (b,h) mean + rstd over T*HD elements (fp64 accum)
// ============================================================
__global__ void gn_stats_kernel(const float* __restrict__ O, float* __restrict__ stats) {
    int g = blockIdx.x;          // b*H + h
    int b = g / Hc, h = g % Hc;
    int tid = threadIdx.x;
    double s = 0.0, s2 = 0.0;
    for (int idx = tid; idx < Tc*HDc; idx += blockDim.x) {
        int t = idx / HDc, d = idx % HDc;
        float v = O[(size_t)(b*Tc + t)*Ec + h*HDc + d];
        s  += (double)v;
        s2 += (double)v * (double)v;
    }
    __shared__ double rs[256], rs2[256];
    rs[tid] = s; rs2[tid] = s2;
    __syncthreads();
    for (int off = 128; off > 0; off >>= 1) {
        if (tid < off) { rs[tid] += rs[tid+off]; rs2[tid] += rs2[tid+off]; }
        __syncthreads();
    }
    if (tid == 0) {
        double N = (double)(Tc*HDc);
        double mean = rs[0] / N;
        double var = rs2[0] / N - mean*mean;
        stats[g*2 + 0] = (float)mean;
        stats[g*2 + 1] = (float)(1.0 / sqrt(var + 1e-5));
    }
}

// ============================================================
// Y = silu(G) * ((O - mean)*rstd*gn_w + gn_b)
// ============================================================
__global__ void gate_norm_kernel(const float* __restrict__ O, const float* __restrict__ G,
                                 const float* __restrict__ gn_w, const float* __restrict__ gn_b,
                                 const float* __restrict__ stats, float* __restrict__ Y)
{
    int idx = blockIdx.x * blockDim.x + threadIdx.x;
    if (idx >= Mc*Ec) return;
    int row = idx / Ec, e = idx % Ec;
    int b = row / Tc;
    int g = b*Hc + e/HDc;
    float mean = stats[g*2 + 0];
    float rstd = stats[g*2 + 1];
    float on = (O[idx] - mean) * rstd * gn_w[e] + gn_b[e];
    float gt = G[idx];
    float si = gt / (1.0f + __expf(-gt));
    Y[idx] = si * on;
}

// ============================================================
extern "C" void kernel_launch(void* const* d_in, const int* in_sizes, int n_in,
                              void* d_out, int out_size)
{
    const float* x    = (const float*)d_in[0];
    const float* Wq   = (const float*)d_in[1];
    const float* bq   = (const float*)d_in[2];
    const float* Wk   = (const float*)d_in[3];
    const float* bk   = (const float*)d_in[4];
    const float* Wv   = (const float*)d_in[5];
    const float* bv   = (const float*)d_in[6];
    const float* Wg   = (const float*)d_in[7];
    const float* bg   = (const float*)d_in[8];
    const float* Wo   = (const float*)d_in[9];
    const float* bo   = (const float*)d_in[10];
    const float* gnw  = (const float*)d_in[11];
    const float* gnb  = (const float*)d_in[12];
    float* out = (float*)d_out;

    float *Qp, *Kp, *Vp, *Gp, *Op, *Yp, *Sp;
    cudaGetSymbolAddress((void**)&Qp, g_Q);
    cudaGetSymbolAddress((void**)&Kp, g_K);
    cudaGetSymbolAddress((void**)&Vp, g_V);
    cudaGetSymbolAddress((void**)&Gp, g_G);
    cudaGetSymbolAddress((void**)&Op, g_O);
    cudaGetSymbolAddress((void**)&Yp, g_Y);
    cudaGetSymbolAddress((void**)&Sp, g_stats);

    rope_table_kernel<<<(Tc*HDc + 255)/256, 256>>>();

    dim3 gg(Ec/128, Mc/128);
    sgemm_bias_kernel<<<gg, 256>>>(x, Wq, bq, Qp, Mc, Ec, Ec);
    sgemm_bias_kernel<<<gg, 256>>>(x, Wk, bk, Kp, Mc, Ec, Ec);
    sgemm_bias_kernel<<<gg, 256>>>(x, Wv, bv, Vp, Mc, Ec, Ec);
    sgemm_bias_kernel<<<gg, 256>>>(x, Wg, bg, Gp, Mc, Ec, Ec);

    int nPairs = Mc*Ec/2;
    rope_apply_kernel<<<(nPairs + 255)/256, 256>>>(Qp);
    rope_apply_kernel<<<(nPairs + 255)/256, 256>>>(Kp);

    size_t shmem = (size_t)4 * 64 * 68 * sizeof(float);
    cudaFuncSetAttribute(retention_kernel,
                         cudaFuncAttributeMaxDynamicSharedMemorySize, (int)shmem);
    retention_kernel<<<dim3(Tc/64, Bc*Hc), 256, shmem>>>(Qp, Kp, Vp, Op);

    gn_stats_kernel<<<Bc*Hc, 256>>>(Op, Sp);

    int nElems = Mc*Ec;
    gate_norm_kernel<<<(nElems + 255)/256, 256>>>(Op, Gp, gnw, gnb, Sp, Yp);

    sgemm_bias_kernel<<<gg, 256>>>(Yp, Wo, bo, out, Mc, Ec, Ec);
}

// round 4
// speedup vs baseline: 2.2969x; 2.2969x over previous
#include <cuda_runtime.h>
#include <cuda_bf16.h>
#include <math.h>
#include <stdint.h>

// Problem dims (fixed)
#define Bc 2
#define Tc 2048
#define Ec 1024
#define Hc 16
#define HDc 64
#define Mc (Bc*Tc)   // 4096

typedef unsigned short u16;
typedef unsigned int   u32;

// -------- scratch (device globals; no allocation allowed) --------
__device__ u16 g_xh[Mc*Ec], g_xl[Mc*Ec];
__device__ u16 g_Wh[5*Ec*Ec], g_Wl[5*Ec*Ec];   // q,k,v,g,o packed
__device__ u16 g_Qh[Mc*Ec], g_Ql[Mc*Ec];
__device__ u16 g_Kh[Mc*Ec], g_Kl[Mc*Ec];
__device__ u16 g_Vth[Mc*Ec], g_Vtl[Mc*Ec];     // V transposed: [b][e][t]
__device__ u16 g_Yh[Mc*Ec], g_Yl[Mc*Ec];
__device__ float g_G[Mc*Ec];
__device__ float g_O[Mc*Ec];
__device__ double g_part[Bc*Hc*8*2];
__device__ float g_stats[Bc*Hc*2];
__device__ float g_rc[Tc*HDc], g_rs[Tc*HDc];

// ------------------- helpers -------------------
__device__ __forceinline__ u32 smaddr(const void* p){ return (u32)__cvta_generic_to_shared(p); }
__device__ __forceinline__ void cp16(u32 d, const void* s){
  asm volatile("cp.async.cg.shared.global [%0], [%1], 16;\n"::"r"(d),"l"(s));
}
__device__ __forceinline__ void cpcommit(){ asm volatile("cp.async.commit_group;\n"); }
__device__ __forceinline__ void cpwait1(){ asm volatile("cp.async.wait_group 1;\n"); }
__device__ __forceinline__ void cpwait0(){ asm volatile("cp.async.wait_group 0;\n"); }
__device__ __forceinline__ void ldsm4(u32&r0,u32&r1,u32&r2,u32&r3,u32 a){
  asm volatile("ldmatrix.sync.aligned.m8n8.x4.shared.b16 {%0,%1,%2,%3},[%4];\n"
    :"=r"(r0),"=r"(r1),"=r"(r2),"=r"(r3):"r"(a));
}
__device__ __forceinline__ void mma_bf(float* c, const u32* a, u32 b0, u32 b1){
  asm volatile("mma.sync.aligned.m16n8k16.row.col.f32.bf16.bf16.f32 "
    "{%0,%1,%2,%3},{%4,%5,%6,%7},{%8,%9},{%0,%1,%2,%3};\n"
    :"+f"(c[0]),"+f"(c[1]),"+f"(c[2]),"+f"(c[3])
    :"r"(a[0]),"r"(a[1]),"r"(a[2]),"r"(a[3]),"r"(b0),"r"(b1));
}
__device__ __forceinline__ u16 f2bf(float x){
  __nv_bfloat16 h = __float2bfloat16_rn(x);
  return *reinterpret_cast<u16*>(&h);
}
__device__ __forceinline__ float bf2f(u16 u){
  __nv_bfloat16 h; *reinterpret_cast<u16*>(&h)=u; return __bfloat162float(h);
}
__device__ __forceinline__ void split_pack(float a, float b, u32& hi, u32& lo){
  u16 ha = f2bf(a), hb = f2bf(b);
  u16 la = f2bf(a - bf2f(ha)), lb = f2bf(b - bf2f(hb));
  hi = (u32)ha | ((u32)hb << 16);
  lo = (u32)la | ((u32)lb << 16);
}

// ------------------- rope table -------------------
__global__ void rope_table_kernel() {
  int idx = blockIdx.x * blockDim.x + threadIdx.x;
  if (idx >= Tc*HDc) return;
  int t = idx / HDc;
  int dd = idx % HDc;
  double f = pow(10000.0, -(double)(dd & 31) / 32.0);
  double th = (double)t * f;
  g_rc[idx] = (float)cos(th);
  g_rs[idx] = (float)sin(th);
}

// ------------------- fp32 -> split bf16 -------------------
__global__ void convert_kernel(const float* __restrict__ in, u16* __restrict__ h,
                               u16* __restrict__ l, int n){
  int i = blockIdx.x*blockDim.x + threadIdx.x;
  if(i >= n) return;
  float x = in[i];
  u16 hx = f2bf(x);
  h[i] = hx;
  l[i] = f2bf(x - bf2f(hx));
}

// ============================================================
// Split-bf16 tensor-core GEMM: C[m,n] = sum_k A[m,k]*B[n,k] + bias[n]
// tiles 128x128x32, 256 threads (8 warps, 2x4), warp tile 64x32.
// MODE 0: fp32 out + bias
// MODE 1: bias + RoPE + split-bf16 out (Q/K)
// MODE 2: bias + split-bf16 TRANSPOSED out (V -> [b][e][t])
// ============================================================
#define GPITCH 40   // halves per smem row (32 data + 8 pad) -> conflict-free
template<int MODE>
__global__ void __launch_bounds__(256)
gemm_bs(const u16* __restrict__ Ah, const u16* __restrict__ Al,
        const u16* __restrict__ Bh, const u16* __restrict__ Bl,
        const float* __restrict__ bias,
        float* __restrict__ outf, u16* __restrict__ outh, u16* __restrict__ outl)
{
  extern __shared__ u16 sm[];
  const int K = Ec;
  int tid = threadIdx.x, lane = tid & 31, wid = tid >> 5;
  int bm = blockIdx.y * 128, bn = blockIdx.x * 128;
  int wm = wid >> 2, wn = wid & 3;

  float acc[4][4][4];
  #pragma unroll
  for(int i=0;i<4;i++)
    #pragma unroll
    for(int j=0;j<4;j++)
      #pragma unroll
      for(int k=0;k<4;k++) acc[i][j][k] = 0.f;

  auto load_stage = [&](int s, int k0){
    u16* st = sm + s*20480;
    const u16* srcs[4] = { Ah + (size_t)bm*K + k0, Al + (size_t)bm*K + k0,
                           Bh + (size_t)bn*K + k0, Bl + (size_t)bn*K + k0 };
    #pragma unroll
    for(int tl=0; tl<4; tl++){
      #pragma unroll
      for(int i=0;i<2;i++){
        int c = tid*2 + i;          // 0..511
        int r = c >> 2, seg = c & 3;
        cp16(smaddr(st + tl*5120 + r*GPITCH + seg*8),
             srcs[tl] + (size_t)r*K + seg*8);
      }
    }
  };

  load_stage(0, 0); cpcommit();
  const int NK = K/32;   // 32
  for(int kt=0; kt<NK; kt++){
    if(kt+1 < NK) load_stage((kt+1)&1, (kt+1)*32);
    cpcommit(); cpwait1(); __syncthreads();
    u16* st  = sm + (kt&1)*20480;
    u16* sAh = st;          u16* sAl = st + 5120;
    u16* sBh = st + 10240;  u16* sBl = st + 15360;

    #pragma unroll
    for(int ks=0; ks<2; ks++){
      int koff = ks*16;
      u32 ah[4][4], al[4][4];
      #pragma unroll
      for(int mi=0; mi<4; mi++){
        int r = wm*64 + mi*16 + (lane & 15);
        int cc = koff + (lane >> 4)*8;
        ldsm4(ah[mi][0],ah[mi][1],ah[mi][2],ah[mi][3], smaddr(sAh + r*GPITCH + cc));
        ldsm4(al[mi][0],al[mi][1],al[mi][2],al[mi][3], smaddr(sAl + r*GPITCH + cc));
      }
      u32 bh[4][2], bl[4][2];
      #pragma unroll
      for(int np=0; np<2; np++){
        int r = wn*32 + np*16 + (lane & 7) + ((lane >> 4)*8);
        int cc = koff + ((lane >> 3) & 1)*8;
        u32 r0,r1,r2,r3;
        ldsm4(r0,r1,r2,r3, smaddr(sBh + r*GPITCH + cc));
        bh[np*2][0]=r0; bh[np*2][1]=r1; bh[np*2+1][0]=r2; bh[np*2+1][1]=r3;
        ldsm4(r0,r1,r2,r3, smaddr(sBl + r*GPITCH + cc));
        bl[np*2][0]=r0; bl[np*2][1]=r1; bl[np*2+1][0]=r2; bl[np*2+1][1]=r3;
      }
      #pragma unroll
      for(int mi=0; mi<4; mi++)
        #pragma unroll
        for(int nj=0; nj<4; nj++){
          mma_bf(acc[mi][nj], ah[mi], bh[nj][0], bh[nj][1]);
          mma_bf(acc[mi][nj], ah[mi], bl[nj][0], bl[nj][1]);
          mma_bf(acc[mi][nj], al[mi], bh[nj][0], bh[nj][1]);
        }
    }
    __syncthreads();
  }
  cpwait0();

  // epilogue
  #pragma unroll
  for(int mi=0; mi<4; mi++){
    int row0 = bm + wm*64 + mi*16 + (lane >> 2);
    #pragma unroll
    for(int nj=0; nj<4; nj++){
      int col = bn + wn*32 + nj*8 + (lane & 3)*2;
      float bv0 = bias[col], bv1 = bias[col+1];
      float v00 = acc[mi][nj][0] + bv0, v01 = acc[mi][nj][1] + bv1;
      float v10 = acc[mi][nj][2] + bv0, v11 = acc[mi][nj][3] + bv1;
      if (MODE == 0){
        *(float2*)&outf[(size_t)row0*Ec + col]     = make_float2(v00, v01);
        *(float2*)&outf[(size_t)(row0+8)*Ec + col] = make_float2(v10, v11);
      } else if (MODE == 1){
        int dd = col & 63;
        int t0 = row0 & (Tc-1), t1 = (row0+8) & (Tc-1);
        float c0 = g_rc[t0*HDc+dd],   s0 = g_rs[t0*HDc+dd];
        float c1 = g_rc[t0*HDc+dd+1], s1 = g_rs[t0*HDc+dd+1];
        float y0 = v00*c0 - v01*s0;
        float y1 = v01*c1 + v00*s1;
        u32 hi, lo; split_pack(y0, y1, hi, lo);
        ((u32*)outh)[((size_t)row0*Ec + col) >> 1] = hi;
        ((u32*)outl)[((size_t)row0*Ec + col) >> 1] = lo;
        float d0 = g_rc[t1*HDc+dd],   e0 = g_rs[t1*HDc+dd];
        float d1 = g_rc[t1*HDc+dd+1], e1 = g_rs[t1*HDc+dd+1];
        float z0 = v10*d0 - v11*e0;
        float z1 = v11*d1 + v10*e1;
        split_pack(z0, z1, hi, lo);
        ((u32*)outh)[((size_t)(row0+8)*Ec + col) >> 1] = hi;
        ((u32*)outl)[((size_t)(row0+8)*Ec + col) >> 1] = lo;
      } else { // MODE 2: transposed split V
        int bi0 = row0 >> 11; int t0 = row0 & (Tc-1);
        size_t i0s = (size_t)bi0*Ec*Tc + (size_t)col*Tc + t0;
        u16 h00 = f2bf(v00); outh[i0s]      = h00; outl[i0s]      = f2bf(v00 - bf2f(h00));
        u16 h01 = f2bf(v01); outh[i0s+Tc]   = h01; outl[i0s+Tc]   = f2bf(v01 - bf2f(h01));
        int row1 = row0 + 8;
        int bi1 = row1 >> 11; int t1 = row1 & (Tc-1);
        size_t i1s = (size_t)bi1*Ec*Tc + (size_t)col*Tc + t1;
        u16 h10 = f2bf(v10); outh[i1s]      = h10; outl[i1s]      = f2bf(v10 - bf2f(h10));
        u16 h11 = f2bf(v11); outh[i1s+Tc]   = h11; outl[i1s+Tc]   = f2bf(v11 - bf2f(h11));
      }
    }
  }
}

// ============================================================
// Retention, tensor cores, split-bf16:
//   O[b,h,i,:] = sum_{j>=i} gamma_h^{j-i} (Q_i.K_j/8) V_j
// block = 128 threads (4 warps, 2x2 over 64x64 S tile).
// ============================================================
#define RPITCH 72   // halves per row (64 data + 8 pad) -> conflict-free
__global__ void __launch_bounds__(128)
retention_mma(const u16* __restrict__ Qh_, const u16* __restrict__ Ql_,
              const u16* __restrict__ Kh_, const u16* __restrict__ Kl_,
              const u16* __restrict__ Vth, const u16* __restrict__ Vtl,
              float* __restrict__ O)
{
  extern __shared__ u16 sm[];
  // halves: Qh 0, Ql 4608, stage s at 9216 + s*18432 : Kh,Kl,Vh,Vl each +4608
  int tid = threadIdx.x, lane = tid & 31, wid = tid >> 5;
  int wi = wid >> 1, wj = wid & 1;
  int bh = blockIdx.y, b = bh >> 4, h = bh & 15;
  int it = blockIdx.x; int i0 = it*64;

  float lg2;
  { double g = 1.0 - ldexp(1.0, -(5+h)); lg2 = (float)log2(g); }

  // Q tile loads (once)
  {
    #pragma unroll
    for(int tl=0; tl<2; tl++){
      const u16* src = (tl ? Ql_ : Qh_) + (size_t)(b*Tc + i0)*Ec + h*64;
      u16* dst = sm + tl*4608;
      #pragma unroll
      for(int i=0;i<4;i++){
        int c = tid*4 + i;             // 0..511
        int r = c >> 3, seg = c & 7;
        cp16(smaddr(dst + r*RPITCH + seg*8), src + (size_t)r*Ec + seg*8);
      }
    }
  }
  auto load_stage = [&](int s, int j0){
    u16* st = sm + 9216 + s*18432;
    const u16* sK[2] = { Kh_ + (size_t)(b*Tc + j0)*Ec + h*64,
                         Kl_ + (size_t)(b*Tc + j0)*Ec + h*64 };
    const u16* sV[2] = { Vth + (size_t)b*Ec*Tc + (size_t)(h*64)*Tc + j0,
                         Vtl + (size_t)b*Ec*Tc + (size_t)(h*64)*Tc + j0 };
    #pragma unroll
    for(int tl=0; tl<4; tl++){
      #pragma unroll
      for(int i=0;i<4;i++){
        int c = tid*4 + i;
        int r = c >> 3, seg = c & 7;
        const u16* src = (tl < 2) ? sK[tl] + (size_t)r*Ec + seg*8
                                  : sV[tl-2] + (size_t)r*Tc + seg*8;
        cp16(smaddr(st + tl*4608 + r*RPITCH + seg*8), src);
      }
    }
  };

  float inv = -lg2;
  int jtEnd = (i0 + 63 + (int)(40.0f/inv)) / 64;
  if (jtEnd > Tc/64 - 1) jtEnd = Tc/64 - 1;

  load_stage(0, it*64);   // first (diagonal) tile: j0 == i0
  cpcommit();

  // decay factors
  float rowF[2][2], colF[4][2];
  int   ilv[2][2],  jlv[4][2];
  #pragma unroll
  for(int mi=0; mi<2; mi++)
    #pragma unroll
    for(int hf=0; hf<2; hf++){
      int il = wi*32 + mi*16 + (lane >> 2) + hf*8;
      ilv[mi][hf] = il;
      rowF[mi][hf] = exp2f(-(float)il * lg2);
    }
  #pragma unroll
  for(int nj=0; nj<4; nj++)
    #pragma unroll
    for(int cp=0; cp<2; cp++){
      int jl = wj*32 + nj*8 + (lane & 3)*2 + cp;
      jlv[nj][cp] = jl;
      colF[nj][cp] = exp2f((float)jl * lg2);
    }

  float oacc[2][8][4];
  #pragma unroll
  for(int i=0;i<2;i++)
    #pragma unroll
    for(int j=0;j<8;j++)
      #pragma unroll
      for(int k=0;k<4;k++) oacc[i][j][k]=0.f;

  u16* sQh = sm; u16* sQl = sm + 4608;

  for(int jt = it; jt <= jtEnd; jt++){
    if (jt+1 <= jtEnd) load_stage((jt-it+1)&1, (jt+1)*64);
    cpcommit(); cpwait1(); __syncthreads();
    u16* st  = sm + 9216 + ((jt-it)&1)*18432;
    u16 *sKh = st, *sKl = st+4608, *sVh = st+9216, *sVl = st+13824;

    // ---- phase A: S = Q K^T ----
    float sacc[2][4][4];
    #pragma unroll
    for(int i=0;i<2;i++)
      #pragma unroll
      for(int j=0;j<4;j++)
        #pragma unroll
        for(int k=0;k<4;k++) sacc[i][j][k]=0.f;

    #pragma unroll
    for(int ks=0; ks<4; ks++){
      int koff = ks*16;
      u32 qh[2][4], ql[2][4];
      #pragma unroll
      for(int mi=0; mi<2; mi++){
        int r = wi*32 + mi*16 + (lane & 15);
        int cc = koff + (lane >> 4)*8;
        ldsm4(qh[mi][0],qh[mi][1],qh[mi][2],qh[mi][3], smaddr(sQh + r*RPITCH + cc));
        ldsm4(ql[mi][0],ql[mi][1],ql[mi][2],ql[mi][3], smaddr(sQl + r*RPITCH + cc));
      }
      u32 kh[4][2], kl[4][2];
      #pragma unroll
      for(int np=0; np<2; np++){
        int r = wj*32 + np*16 + (lane & 7) + ((lane >> 4)*8);
        int cc = koff + ((lane >> 3) & 1)*8;
        u32 r0,r1,r2,r3;
        ldsm4(r0,r1,r2,r3, smaddr(sKh + r*RPITCH + cc));
        kh[np*2][0]=r0; kh[np*2][1]=r1; kh[np*2+1][0]=r2; kh[np*2+1][1]=r3;
        ldsm4(r0,r1,r2,r3, smaddr(sKl + r*RPITCH + cc));
        kl[np*2][0]=r0; kl[np*2][1]=r1; kl[np*2+1][0]=r2; kl[np*2+1][1]=r3;
      }
      #pragma unroll
      for(int mi=0; mi<2; mi++)
        #pragma unroll
        for(int nj=0; nj<4; nj++){
          mma_bf(sacc[mi][nj], qh[mi], kh[nj][0], kh[nj][1]);
          mma_bf(sacc[mi][nj], qh[mi], kl[nj][0], kl[nj][1]);
          mma_bf(sacc[mi][nj], ql[mi], kh[nj][0], kh[nj][1]);
        }
    }

    // ---- decay + mask + 1/8 ----
    float base = exp2f((float)((jt-it)*64) * lg2) * 0.125f;
    bool diag = (jt == it);
    #pragma unroll
    for(int mi=0; mi<2; mi++)
      #pragma unroll
      for(int nj=0; nj<4; nj++){
        float f00 = base*rowF[mi][0]*colF[nj][0];
        float f01 = base*rowF[mi][0]*colF[nj][1];
        float f10 = base*rowF[mi][1]*colF[nj][0];
        float f11 = base*rowF[mi][1]*colF[nj][1];
        if (diag){
          if (jlv[nj][0] < ilv[mi][0]) f00 = 0.f;
          if (jlv[nj][1] < ilv[mi][0]) f01 = 0.f;
          if (jlv[nj][0] < ilv[mi][1]) f10 = 0.f;
          if (jlv[nj][1] < ilv[mi][1]) f11 = 0.f;
        }
        sacc[mi][nj][0] *= f00; sacc[mi][nj][1] *= f01;
        sacc[mi][nj][2] *= f10; sacc[mi][nj][3] *= f11;
      }

    // ---- phase B: O += S V (register repack of S to A-frags) ----
    #pragma unroll
    for(int kt=0; kt<2; kt++){
      int koff = wj*32 + kt*16;
      u32 sh[2][4], sl[2][4];
      #pragma unroll
      for(int mi=0; mi<2; mi++){
        split_pack(sacc[mi][2*kt][0],   sacc[mi][2*kt][1],   sh[mi][0], sl[mi][0]);
        split_pack(sacc[mi][2*kt][2],   sacc[mi][2*kt][3],   sh[mi][1], sl[mi][1]);
        split_pack(sacc[mi][2*kt+1][0], sacc[mi][2*kt+1][1], sh[mi][2], sl[mi][2]);
        split_pack(sacc[mi][2*kt+1][2], sacc[mi][2*kt+1][3], sh[mi][3], sl[mi][3]);
      }
      u32 vh[8][2], vl[8][2];
      #pragma unroll
      for(int np=0; np<4; np++){
        int r = np*16 + (lane & 7) + ((lane >> 4)*8);
        int cc = koff + ((lane >> 3) & 1)*8;
        u32 r0,r1,r2,r3;
        ldsm4(r0,r1,r2,r3, smaddr(sVh + r*RPITCH + cc));
        vh[np*2][0]=r0; vh[np*2][1]=r1; vh[np*2+1][0]=r2; vh[np*2+1][1]=r3;
        ldsm4(r0,r1,r2,r3, smaddr(sVl + r*RPITCH + cc));
        vl[np*2][0]=r0; vl[np*2][1]=r1; vl[np*2+1][0]=r2; vl[np*2+1][1]=r3;
      }
      #pragma unroll
      for(int mi=0; mi<2; mi++)
        #pragma unroll
        for(int nd=0; nd<8; nd++){
          mma_bf(oacc[mi][nd], sh[mi], vh[nd][0], vh[nd][1]);
          mma_bf(oacc[mi][nd], sh[mi], vl[nd][0], vl[nd][1]);
          mma_bf(oacc[mi][nd], sl[mi], vh[nd][0], vh[nd][1]);
        }
    }
    __syncthreads();
  }
  cpwait0();

  // ---- cross-warp combine over wj halves (alias over Q area) ----
  float* Op = (float*)sm;     // 64 x pitch66
  if (wj == 0){
    #pragma unroll
    for(int mi=0; mi<2; mi++)
      #pragma unroll
      for(int nd=0; nd<8; nd++){
        int row = wi*32 + mi*16 + (lane >> 2);
        int d   = nd*8 + (lane & 3)*2;
        Op[row*66 + d]     = oacc[mi][nd][0];
        Op[row*66 + d + 1] = oacc[mi][nd][1];
        Op[(row+8)*66 + d]     = oacc[mi][nd][2];
        Op[(row+8)*66 + d + 1] = oacc[mi][nd][3];
      }
  }
  __syncthreads();
  if (wj == 1){
    #pragma unroll
    for(int mi=0; mi<2; mi++)
      #pragma unroll
      for(int nd=0; nd<8; nd++){
        int row = wi*32 + mi*16 + (lane >> 2);
        int d   = nd*8 + (lane & 3)*2;
        float a0 = oacc[mi][nd][0] + Op[row*66 + d];
        float a1 = oacc[mi][nd][1] + Op[row*66 + d + 1];
        float a2 = oacc[mi][nd][2] + Op[(row+8)*66 + d];
        float a3 = oacc[mi][nd][3] + Op[(row+8)*66 + d + 1];
        size_t r0 = (size_t)(b*Tc + i0 + row)*Ec + h*64 + d;
        size_t r1 = (size_t)(b*Tc + i0 + row + 8)*Ec + h*64 + d;
        *(float2*)&O[r0] = make_float2(a0, a1);
        *(float2*)&O[r1] = make_float2(a2, a3);
      }
  }
}

// ============================================================
// GroupNorm stats, 2-stage, fp64 accumulation
// ============================================================
__global__ void gn_part_kernel(const float* __restrict__ O){
  int g = blockIdx.x;           // 0..31
  int c = blockIdx.y;           // 0..7
  int b = g >> 4, h = g & 15, tid = threadIdx.x;
  int tbase = c * (Tc/8);
  double s = 0.0, s2 = 0.0;
  for(int idx = tid; idx < (Tc/8)*HDc; idx += 256){
    int t = tbase + (idx >> 6), d = idx & 63;
    float v = O[(size_t)(b*Tc + t)*Ec + h*64 + d];
    s += (double)v; s2 += (double)v * (double)v;
  }
  __shared__ double rs[256], rs2[256];
  rs[tid] = s; rs2[tid] = s2;
  __syncthreads();
  for(int off=128; off>0; off>>=1){
    if(tid < off){ rs[tid]+=rs[tid+off]; rs2[tid]+=rs2[tid+off]; }
    __syncthreads();
  }
  if(tid == 0){
    g_part[(g*8 + c)*2 + 0] = rs[0];
    g_part[(g*8 + c)*2 + 1] = rs2[0];
  }
}
__global__ void gn_final_kernel(){
  int g = threadIdx.x;
  if(g >= Bc*Hc) return;
  double s=0.0, s2=0.0;
  for(int c=0;c<8;c++){ s += g_part[(g*8+c)*2]; s2 += g_part[(g*8+c)*2+1]; }
  double N = (double)(Tc*HDc);
  double mean = s/N;
  double var  = s2/N - mean*mean;
  g_stats[g*2+0] = (float)mean;
  g_stats[g*2+1] = (float)(1.0 / sqrt(var + 1e-5));
}

// ============================================================
// Y = silu(G) * groupnorm(O)  -> split bf16
// ============================================================
__global__ void gate_norm_kernel(const float* __restrict__ O, const float* __restrict__ G,
                                 const float* __restrict__ w, const float* __restrict__ bb,
                                 u16* __restrict__ Yh, u16* __restrict__ Yl)
{
  int i2 = blockIdx.x*blockDim.x + threadIdx.x;
  if(i2 >= Mc*Ec/2) return;
  int idx = i2*2;
  int row = idx >> 10, e = idx & 1023;
  int b = row >> 11;
  int g = b*Hc + (e >> 6);
  float mean = g_stats[g*2+0], rstd = g_stats[g*2+1];
  float o0 = (O[idx]   - mean)*rstd*w[e]   + bb[e];
  float o1 = (O[idx+1] - mean)*rstd*w[e+1] + bb[e+1];
  float g0 = G[idx],   g1 = G[idx+1];
  float y0 = (g0 / (1.f + __expf(-g0))) * o0;
  float y1 = (g1 / (1.f + __expf(-g1))) * o1;
  u32 hi, lo; split_pack(y0, y1, hi, lo);
  ((u32*)Yh)[i2] = hi;
  ((u32*)Yl)[i2] = lo;
}

// ============================================================
extern "C" void kernel_launch(void* const* d_in, const int* in_sizes, int n_in,
                              void* d_out, int out_size)
{
  const float* x   = (const float*)d_in[0];
  const float* Wq  = (const float*)d_in[1];
  const float* bq  = (const float*)d_in[2];
  const float* Wk  = (const float*)d_in[3];
  const float* bk  = (const float*)d_in[4];
  const float* Wv  = (const float*)d_in[5];
  const float* bv  = (const float*)d_in[6];
  const float* Wg  = (const float*)d_in[7];
  const float* bg  = (const float*)d_in[8];
  const float* Wo  = (const float*)d_in[9];
  const float* bo  = (const float*)d_in[10];
  const float* gnw = (const float*)d_in[11];
  const float* gnb = (const float*)d_in[12];
  float* out = (float*)d_out;

  u16 *xh,*xl,*Wh,*Wl,*Qh,*Ql,*Kh,*Kl,*Vth,*Vtl,*Yh,*Yl;
  float *Gp,*Op;
  cudaGetSymbolAddress((void**)&xh, g_xh);   cudaGetSymbolAddress((void**)&xl, g_xl);
  cudaGetSymbolAddress((void**)&Wh, g_Wh);   cudaGetSymbolAddress((void**)&Wl, g_Wl);
  cudaGetSymbolAddress((void**)&Qh, g_Qh);   cudaGetSymbolAddress((void**)&Ql, g_Ql);
  cudaGetSymbolAddress((void**)&Kh, g_Kh);   cudaGetSymbolAddress((void**)&Kl, g_Kl);
  cudaGetSymbolAddress((void**)&Vth, g_Vth); cudaGetSymbolAddress((void**)&Vtl, g_Vtl);
  cudaGetSymbolAddress((void**)&Yh, g_Yh);   cudaGetSymbolAddress((void**)&Yl, g_Yl);
  cudaGetSymbolAddress((void**)&Gp, g_G);    cudaGetSymbolAddress((void**)&Op, g_O);

  rope_table_kernel<<<(Tc*HDc + 255)/256, 256>>>();

  // conversions
  convert_kernel<<<(Mc*Ec + 255)/256, 256>>>(x, xh, xl, Mc*Ec);
  const float* Ws[5] = {Wq, Wk, Wv, Wg, Wo};
  for(int i=0;i<5;i++)
    convert_kernel<<<(Ec*Ec + 255)/256, 256>>>(Ws[i], Wh + (size_t)i*Ec*Ec, Wl + (size_t)i*Ec*Ec, Ec*Ec);

  size_t gsm = 81920;
  cudaFuncSetAttribute(gemm_bs<0>, cudaFuncAttributeMaxDynamicSharedMemorySize, (int)gsm);
  cudaFuncSetAttribute(gemm_bs<1>, cudaFuncAttributeMaxDynamicSharedMemorySize, (int)gsm);
  cudaFuncSetAttribute(gemm_bs<2>, cudaFuncAttributeMaxDynamicSharedMemorySize, (int)gsm);

  dim3 gg(Ec/128, Mc/128);
  // Q, K: bias + RoPE + split out
  gemm_bs<1><<<gg, 256, gsm>>>(xh, xl, Wh + 0*Ec*Ec, Wl + 0*Ec*Ec, bq, nullptr, Qh, Ql);
  gemm_bs<1><<<gg, 256, gsm>>>(xh, xl, Wh + 1*(size_t)Ec*Ec, Wl + 1*(size_t)Ec*Ec, bk, nullptr, Kh, Kl);
  // V: bias + transposed split out
  gemm_bs<2><<<gg, 256, gsm>>>(xh, xl, Wh + 2*(size_t)Ec*Ec, Wl + 2*(size_t)Ec*Ec, bv, nullptr, Vth, Vtl);
  // G: fp32 out
  gemm_bs<0><<<gg, 256, gsm>>>(xh, xl, Wh + 3*(size_t)Ec*Ec, Wl + 3*(size_t)Ec*Ec, bg, Gp, nullptr, nullptr);

  size_t rsm = 92160;
  cudaFuncSetAttribute(retention_mma, cudaFuncAttributeMaxDynamicSharedMemorySize, (int)rsm);
  retention_mma<<<dim3(Tc/64, Bc*Hc), 128, rsm>>>(Qh, Ql, Kh, Kl, Vth, Vtl, Op);

  gn_part_kernel<<<dim3(Bc*Hc, 8), 256>>>(Op);
  gn_final_kernel<<<1, 32>>>();

  gate_norm_kernel<<<(Mc*Ec/2 + 255)/256, 256>>>(Op, Gp, gnw, gnb, Yh, Yl);

  // final: out = Y @ Wo^T + bo
  gemm_bs<0><<<gg, 256, gsm>>>(Yh, Yl, Wh + 4*(size_t)Ec*Ec, Wl + 4*(size_t)Ec*Ec, bo, out, nullptr, nullptr);
}

// round 7
// speedup vs baseline: 2.5042x; 1.0903x over previous
#include <cuda_runtime.h>
#include <cuda_bf16.h>
#include <math.h>
#include <stdint.h>

// Problem dims (fixed)
#define Bc 2
#define Tc 2048
#define Ec 1024
#define Hc 16
#define HDc 64
#define Mc (Bc*Tc)   // 4096

typedef unsigned short u16;
typedef unsigned int   u32;

// -------- scratch (device globals; no allocation allowed) --------
__device__ u16 g_xh[Mc*Ec], g_xl[Mc*Ec];
__device__ u16 g_Wh[5*Ec*Ec], g_Wl[5*Ec*Ec];   // q,k,v,g,o packed
__device__ u16 g_Qh[Mc*Ec], g_Ql[Mc*Ec];
__device__ u16 g_Kh[Mc*Ec], g_Kl[Mc*Ec];
__device__ u16 g_Vth[Mc*Ec], g_Vtl[Mc*Ec];     // V transposed: [b][e][t]
__device__ u16 g_Yh[Mc*Ec], g_Yl[Mc*Ec];
__device__ float g_G[Mc*Ec];
__device__ float g_O[Mc*Ec];
__device__ double g_part[Bc*Hc*8*2];
__device__ float g_stats[Bc*Hc*2];
__device__ float g_rc[Tc*HDc], g_rs[Tc*HDc];

// ------------------- helpers -------------------
__device__ __forceinline__ u32 smaddr(const void* p){ return (u32)__cvta_generic_to_shared(p); }
__device__ __forceinline__ void cp16(u32 d, const void* s){
  asm volatile("cp.async.cg.shared.global [%0], [%1], 16;\n"::"r"(d),"l"(s));
}
__device__ __forceinline__ void cpcommit(){ asm volatile("cp.async.commit_group;\n"); }
__device__ __forceinline__ void cpwait0(){ asm volatile("cp.async.wait_group 0;\n"); }
__device__ __forceinline__ void cpwait1(){ asm volatile("cp.async.wait_group 1;\n"); }
__device__ __forceinline__ void cpwait2(){ asm volatile("cp.async.wait_group 2;\n"); }
__device__ __forceinline__ void ldsm4(u32&r0,u32&r1,u32&r2,u32&r3,u32 a){
  asm volatile("ldmatrix.sync.aligned.m8n8.x4.shared.b16 {%0,%1,%2,%3},[%4];\n"
    :"=r"(r0),"=r"(r1),"=r"(r2),"=r"(r3):"r"(a));
}
__device__ __forceinline__ void mma_bf(float* c, const u32* a, u32 b0, u32 b1){
  asm volatile("mma.sync.aligned.m16n8k16.row.col.f32.bf16.bf16.f32 "
    "{%0,%1,%2,%3},{%4,%5,%6,%7},{%8,%9},{%0,%1,%2,%3};\n"
    :"+f"(c[0]),"+f"(c[1]),"+f"(c[2]),"+f"(c[3])
    :"r"(a[0]),"r"(a[1]),"r"(a[2]),"r"(a[3]),"r"(b0),"r"(b1));
}
__device__ __forceinline__ u16 f2bf(float x){
  __nv_bfloat16 h = __float2bfloat16_rn(x);
  return *reinterpret_cast<u16*>(&h);
}
__device__ __forceinline__ float bf2f(u16 u){
  __nv_bfloat16 h; *reinterpret_cast<u16*>(&h)=u; return __bfloat162float(h);
}
__device__ __forceinline__ void split_pack(float a, float b, u32& hi, u32& lo){
  u16 ha = f2bf(a), hb = f2bf(b);
  u16 la = f2bf(a - bf2f(ha)), lb = f2bf(b - bf2f(hb));
  hi = (u32)ha | ((u32)hb << 16);
  lo = (u32)la | ((u32)lb << 16);
}

// ------------------- rope table -------------------
__global__ void rope_table_kernel() {
  int idx = blockIdx.x * blockDim.x + threadIdx.x;
  if (idx >= Tc*HDc) return;
  int t = idx / HDc;
  int dd = idx % HDc;
  double f = pow(10000.0, -(double)(dd & 31) / 32.0);
  double th = (double)t * f;
  g_rc[idx] = (float)cos(th);
  g_rs[idx] = (float)sin(th);
}

// ------------------- fp32 -> split bf16 -------------------
__global__ void convert_kernel(const float* __restrict__ in, u16* __restrict__ h,
                               u16* __restrict__ l, int n){
  int i = blockIdx.x*blockDim.x + threadIdx.x;
  if(i >= n) return;
  float x = in[i];
  u16 hx = f2bf(x);
  h[i] = hx;
  l[i] = f2bf(x - bf2f(hx));
}
__global__ void convertW_kernel(const float* __restrict__ w0, const float* __restrict__ w1,
                                const float* __restrict__ w2, const float* __restrict__ w3,
                                const float* __restrict__ w4){
  int z = blockIdx.y;
  const float* src = (z==0)?w0:(z==1)?w1:(z==2)?w2:(z==3)?w3:w4;
  int i = blockIdx.x*blockDim.x + threadIdx.x;
  if(i >= Ec*Ec) return;
  float x = src[i];
  u16 hx = f2bf(x);
  g_Wh[(size_t)z*Ec*Ec + i] = hx;
  g_Wl[(size_t)z*Ec*Ec + i] = f2bf(x - bf2f(hx));
}

// ============================================================
// Split-bf16 tensor-core GEMM: C[m,n] = sum_k A[m,k]*W[n,k] + bias[n]
// tiles 128x128x32, 256 threads (8 warps, 2x4), warp tile 64x32.
// w = zoff + blockIdx.z selects weight slice + epilogue:
//   w=0: Q (bias+RoPE -> g_Qh/g_Ql)   w=1: K (bias+RoPE -> g_Kh/g_Kl)
//   w=2: V (bias -> transposed g_Vth/g_Vtl)
//   w=3: G (bias -> g_G fp32)         w=4: O (bias -> outf fp32)
// ============================================================
#define GPITCH 40   // halves per smem row (32 data + 8 pad) -> conflict-free
__global__ void __launch_bounds__(256)
gemm_bs(const u16* __restrict__ Ah, const u16* __restrict__ Al,
        const float* __restrict__ b0, const float* __restrict__ b1,
        const float* __restrict__ b2, const float* __restrict__ b3,
        int zoff, float* __restrict__ outf)
{
  extern __shared__ u16 sm[];
  const int K = Ec;
  int tid = threadIdx.x, lane = tid & 31, wid = tid >> 5;
  int bm = blockIdx.y * 128, bn = blockIdx.x * 128;
  int wm = wid >> 2, wn = wid & 3;
  int z = blockIdx.z, w = zoff + z;
  const u16* Bh = g_Wh + (size_t)w*Ec*Ec;
  const u16* Bl = g_Wl + (size_t)w*Ec*Ec;
  const float* bias = (z==0)?b0:(z==1)?b1:(z==2)?b2:b3;

  float acc[4][4][4];
  #pragma unroll
  for(int i=0;i<4;i++)
    #pragma unroll
    for(int j=0;j<4;j++)
      #pragma unroll
      for(int k=0;k<4;k++) acc[i][j][k] = 0.f;

  auto load_stage = [&](int s, int k0){
    u16* st = sm + s*20480;
    const u16* srcs[4] = { Ah + (size_t)bm*K + k0, Al + (size_t)bm*K + k0,
                           Bh + (size_t)bn*K + k0, Bl + (size_t)bn*K + k0 };
    #pragma unroll
    for(int tl=0; tl<4; tl++){
      #pragma unroll
      for(int i=0;i<2;i++){
        int c = tid*2 + i;          // 0..511
        int r = c >> 2, seg = c & 3;
        cp16(smaddr(st + tl*5120 + r*GPITCH + seg*8),
             srcs[tl] + (size_t)r*K + seg*8);
      }
    }
  };

  load_stage(0, 0); cpcommit();
  const int NK = K/32;   // 32
  for(int kt=0; kt<NK; kt++){
    if(kt+1 < NK) load_stage((kt+1)&1, (kt+1)*32);
    cpcommit(); cpwait1(); __syncthreads();
    u16* st  = sm + (kt&1)*20480;
    u16* sAh = st;          u16* sAl = st + 5120;
    u16* sBh = st + 10240;  u16* sBl = st + 15360;

    #pragma unroll
    for(int ks=0; ks<2; ks++){
      int koff = ks*16;
      u32 ah[4][4], al[4][4];
      #pragma unroll
      for(int mi=0; mi<4; mi++){
        int r = wm*64 + mi*16 + (lane & 15);
        int cc = koff + (lane >> 4)*8;
        ldsm4(ah[mi][0],ah[mi][1],ah[mi][2],ah[mi][3], smaddr(sAh + r*GPITCH + cc));
        ldsm4(al[mi][0],al[mi][1],al[mi][2],al[mi][3], smaddr(sAl + r*GPITCH + cc));
      }
      u32 bh[4][2], bl[4][2];
      #pragma unroll
      for(int np=0; np<2; np++){
        int r = wn*32 + np*16 + (lane & 7) + ((lane >> 4)*8);
        int cc = koff + ((lane >> 3) & 1)*8;
        u32 r0,r1,r2,r3;
        ldsm4(r0,r1,r2,r3, smaddr(sBh + r*GPITCH + cc));
        bh[np*2][0]=r0; bh[np*2][1]=r1; bh[np*2+1][0]=r2; bh[np*2+1][1]=r3;
        ldsm4(r0,r1,r2,r3, smaddr(sBl + r*GPITCH + cc));
        bl[np*2][0]=r0; bl[np*2][1]=r1; bl[np*2+1][0]=r2; bl[np*2+1][1]=r3;
      }
      #pragma unroll
      for(int mi=0; mi<4; mi++)
        #pragma unroll
        for(int nj=0; nj<4; nj++){
          mma_bf(acc[mi][nj], ah[mi], bh[nj][0], bh[nj][1]);
          mma_bf(acc[mi][nj], ah[mi], bl[nj][0], bl[nj][1]);
          mma_bf(acc[mi][nj], al[mi], bh[nj][0], bh[nj][1]);
        }
    }
    __syncthreads();
  }
  cpwait0();

  // epilogue
  int mode = (w < 2) ? 1 : ((w == 2) ? 2 : 0);
  #pragma unroll
  for(int mi=0; mi<4; mi++){
    int row0 = bm + wm*64 + mi*16 + (lane >> 2);
    #pragma unroll
    for(int nj=0; nj<4; nj++){
      int col = bn + wn*32 + nj*8 + (lane & 3)*2;
      float bv0 = bias[col], bv1 = bias[col+1];
      float v00 = acc[mi][nj][0] + bv0, v01 = acc[mi][nj][1] + bv1;
      float v10 = acc[mi][nj][2] + bv0, v11 = acc[mi][nj][3] + bv1;
      if (mode == 0){
        float* dst = (w == 3) ? g_G : outf;
        *(float2*)&dst[(size_t)row0*Ec + col]     = make_float2(v00, v01);
        *(float2*)&dst[(size_t)(row0+8)*Ec + col] = make_float2(v10, v11);
      } else if (mode == 1){
        u16* oh = (w == 0) ? g_Qh : g_Kh;
        u16* ol = (w == 0) ? g_Ql : g_Kl;
        int dd = col & 63;
        int t0 = row0 & (Tc-1), t1 = (row0+8) & (Tc-1);
        float c0 = g_rc[t0*HDc+dd],   s0 = g_rs[t0*HDc+dd];
        float c1 = g_rc[t0*HDc+dd+1], s1 = g_rs[t0*HDc+dd+1];
        float y0 = v00*c0 - v01*s0;
        float y1 = v01*c1 + v00*s1;
        u32 hi, lo; split_pack(y0, y1, hi, lo);
        ((u32*)oh)[((size_t)row0*Ec + col) >> 1] = hi;
        ((u32*)ol)[((size_t)row0*Ec + col) >> 1] = lo;
        float d0 = g_rc[t1*HDc+dd],   e0 = g_rs[t1*HDc+dd];
        float d1 = g_rc[t1*HDc+dd+1], e1 = g_rs[t1*HDc+dd+1];
        float z0 = v10*d0 - v11*e0;
        float z1 = v11*d1 + v10*e1;
        split_pack(z0, z1, hi, lo);
        ((u32*)oh)[((size_t)(row0+8)*Ec + col) >> 1] = hi;
        ((u32*)ol)[((size_t)(row0+8)*Ec + col) >> 1] = lo;
      } else { // mode 2: transposed split V
        int bi0 = row0 >> 11; int t0 = row0 & (Tc-1);
        size_t i0s = (size_t)bi0*Ec*Tc + (size_t)col*Tc + t0;
        u16 h00 = f2bf(v00); g_Vth[i0s]    = h00; g_Vtl[i0s]    = f2bf(v00 - bf2f(h00));
        u16 h01 = f2bf(v01); g_Vth[i0s+Tc] = h01; g_Vtl[i0s+Tc] = f2bf(v01 - bf2f(h01));
        int row1 = row0 + 8;
        int bi1 = row1 >> 11; int t1 = row1 & (Tc-1);
        size_t i1s = (size_t)bi1*Ec*Tc + (size_t)col*Tc + t1;
        u16 h10 = f2bf(v10); g_Vth[i1s]    = h10; g_Vtl[i1s]    = f2bf(v10 - bf2f(h10));
        u16 h11 = f2bf(v11); g_Vth[i1s+Tc] = h11; g_Vtl[i1s+Tc] = f2bf(v11 - bf2f(h11));
      }
    }
  }
}

// ============================================================
// Retention, mma.sync, split-bf16 (R4 math, new buffering):
//   O[b,h,i,:] = sum_{j>=i} gamma_h^{j-i} (Q_i.K_j/8) V_j
// smem: Q hi/lo (2x4608h), K stages 2x(hi+lo 9216h), V single (hi+lo 9216h)
// total 36864 halves = 73728 B -> 3 blocks/SM; launch_bounds(128,3).
// ============================================================
#define RPITCH 72
__global__ void __launch_bounds__(128, 3)
retention_mma(const u16* __restrict__ Qh_, const u16* __restrict__ Ql_,
              const u16* __restrict__ Kh_, const u16* __restrict__ Kl_,
              const u16* __restrict__ Vth, const u16* __restrict__ Vtl,
              float* __restrict__ O)
{
  extern __shared__ u16 sm[];
  // halves: Qh 0, Ql 4608, Kstage(s) 9216 + s*9216 (Kh, Kl +4608),
  //         Vh 27648, Vl 32256
  int tid = threadIdx.x, lane = tid & 31, wid = tid >> 5;
  int wi = wid >> 1, wj = wid & 1;
  int bh = blockIdx.y, b = bh >> 4, h = bh & 15;
  int it = blockIdx.x; int i0 = it*64;

  float lg2;
  { double g = 1.0 - ldexp(1.0, -(5+h)); lg2 = (float)log2(g); }

  // Q tile loads (once)
  {
    #pragma unroll
    for(int tl=0; tl<2; tl++){
      const u16* src = (tl ? Ql_ : Qh_) + (size_t)(b*Tc + i0)*Ec + h*64;
      u16* dst = sm + tl*4608;
      #pragma unroll
      for(int i=0;i<4;i++){
        int c = tid*4 + i;
        int r = c >> 3, seg = c & 7;
        cp16(smaddr(dst + r*RPITCH + seg*8), src + (size_t)r*Ec + seg*8);
      }
    }
  }
  auto load_K = [&](int s, int j0){
    u16* st = sm + 9216 + s*9216;
    const u16* sK[2] = { Kh_ + (size_t)(b*Tc + j0)*Ec + h*64,
                         Kl_ + (size_t)(b*Tc + j0)*Ec + h*64 };
    #pragma unroll
    for(int tl=0; tl<2; tl++){
      #pragma unroll
      for(int i=0;i<4;i++){
        int c = tid*4 + i;
        int r = c >> 3, seg = c & 7;
        cp16(smaddr(st + tl*4608 + r*RPITCH + seg*8), sK[tl] + (size_t)r*Ec + seg*8);
      }
    }
  };
  auto load_V = [&](int j0){
    u16* st = sm + 27648;
    const u16* sV[2] = { Vth + (size_t)b*Ec*Tc + (size_t)(h*64)*Tc + j0,
                         Vtl + (size_t)b*Ec*Tc + (size_t)(h*64)*Tc + j0 };
    #pragma unroll
    for(int tl=0; tl<2; tl++){
      #pragma unroll
      for(int i=0;i<4;i++){
        int c = tid*4 + i;
        int r = c >> 3, seg = c & 7;
        cp16(smaddr(st + tl*4608 + r*RPITCH + seg*8), sV[tl] + (size_t)r*Tc + seg*8);
      }
    }
  };

  float inv = -lg2;
  int jtEnd = (i0 + 63 + (int)(30.0f/inv)) / 64;
  if (jtEnd > Tc/64 - 1) jtEnd = Tc/64 - 1;

  load_K(0, it*64);   // diagonal K tile
  cpcommit();         // group: K[it]

  float rowF[2][2], colF[4][2];
  int   ilv[2][2],  jlv[4][2];
  #pragma unroll
  for(int mi=0; mi<2; mi++)
    #pragma unroll
    for(int hf=0; hf<2; hf++){
      int il = wi*32 + mi*16 + (lane >> 2) + hf*8;
      ilv[mi][hf] = il;
      rowF[mi][hf] = exp2f(-(float)il * lg2);
    }
  #pragma unroll
  for(int nj=0; nj<4; nj++)
    #pragma unroll
    for(int cp=0; cp<2; cp++){
      int jl = wj*32 + nj*8 + (lane & 3)*2 + cp;
      jlv[nj][cp] = jl;
      colF[nj][cp] = exp2f((float)jl * lg2);
    }

  float oacc[2][8][4];
  #pragma unroll
  for(int i=0;i<2;i++)
    #pragma unroll
    for(int j=0;j<8;j++)
      #pragma unroll
      for(int k=0;k<4;k++) oacc[i][j][k]=0.f;

  u16* sQh = sm; u16* sQl = sm + 4608;
  u16* sVh = sm + 27648; u16* sVl = sm + 32256;

  for(int jt = it; jt <= jtEnd; jt++){
    int s = (jt - it) & 1;
    // issue V for this tile (V buffer free: end-of-prev-iter sync passed)
    load_V(jt*64); cpcommit();                 // group: V[jt]
    bool havK = (jt + 1 <= jtEnd);
    if (havK){ load_K(s^1, (jt+1)*64); cpcommit(); }   // group: K[jt+1]
    // need K[jt] for phase A; allow V[jt] (and K[jt+1]) pending
    if (havK) cpwait2(); else cpwait1();
    __syncthreads();
    u16 *sKh = sm + 9216 + s*9216, *sKl = sKh + 4608;

    // ---- phase A: S = Q K^T ----
    float sacc[2][4][4];
    #pragma unroll
    for(int i=0;i<2;i++)
      #pragma unroll
      for(int j=0;j<4;j++)
        #pragma unroll
        for(int k=0;k<4;k++) sacc[i][j][k]=0.f;

    #pragma unroll
    for(int ks=0; ks<4; ks++){
      int koff = ks*16;
      u32 qh[2][4], ql[2][4];
      #pragma unroll
      for(int mi=0; mi<2; mi++){
        int r = wi*32 + mi*16 + (lane & 15);
        int cc = koff + (lane >> 4)*8;
        ldsm4(qh[mi][0],qh[mi][1],qh[mi][2],qh[mi][3], smaddr(sQh + r*RPITCH + cc));
        ldsm4(ql[mi][0],ql[mi][1],ql[mi][2],ql[mi][3], smaddr(sQl + r*RPITCH + cc));
      }
      u32 kh[4][2], kl[4][2];
      #pragma unroll
      for(int np=0; np<2; np++){
        int r = wj*32 + np*16 + (lane & 7) + ((lane >> 4)*8);
        int cc = koff + ((lane >> 3) & 1)*8;
        u32 r0,r1,r2,r3;
        ldsm4(r0,r1,r2,r3, smaddr(sKh + r*RPITCH + cc));
        kh[np*2][0]=r0; kh[np*2][1]=r1; kh[np*2+1][0]=r2; kh[np*2+1][1]=r3;
        ldsm4(r0,r1,r2,r3, smaddr(sKl + r*RPITCH + cc));
        kl[np*2][0]=r0; kl[np*2][1]=r1; kl[np*2+1][0]=r2; kl[np*2+1][1]=r3;
      }
      #pragma unroll
      for(int mi=0; mi<2; mi++)
        #pragma unroll
        for(int nj=0; nj<4; nj++){
          mma_bf(sacc[mi][nj], qh[mi], kh[nj][0], kh[nj][1]);
          mma_bf(sacc[mi][nj], qh[mi], kl[nj][0], kl[nj][1]);
          mma_bf(sacc[mi][nj], ql[mi], kh[nj][0], kh[nj][1]);
        }
    }

    // ---- decay + mask + 1/8 ----
    float base = exp2f((float)((jt-it)*64) * lg2) * 0.125f;
    bool diag = (jt == it);
    #pragma unroll
    for(int mi=0; mi<2; mi++)
      #pragma unroll
      for(int nj=0; nj<4; nj++){
        float f00 = base*rowF[mi][0]*colF[nj][0];
        float f01 = base*rowF[mi][0]*colF[nj][1];
        float f10 = base*rowF[mi][1]*colF[nj][0];
        float f11 = base*rowF[mi][1]*colF[nj][1];
        if (diag){
          if (jlv[nj][0] < ilv[mi][0]) f00 = 0.f;
          if (jlv[nj][1] < ilv[mi][0]) f01 = 0.f;
          if (jlv[nj][0] < ilv[mi][1]) f10 = 0.f;
          if (jlv[nj][1] < ilv[mi][1]) f11 = 0.f;
        }
        sacc[mi][nj][0] *= f00; sacc[mi][nj][1] *= f01;
        sacc[mi][nj][2] *= f10; sacc[mi][nj][3] *= f11;
      }

    // need V[jt] for phase B; allow K[jt+1] pending
    if (havK) cpwait1(); else cpwait0();
    __syncthreads();

    // ---- phase B: O += S V (register repack of S to A-frags) ----
    #pragma unroll
    for(int kt=0; kt<2; kt++){
      int koff = wj*32 + kt*16;
      u32 sh[2][4], sl[2][4];
      #pragma unroll
      for(int mi=0; mi<2; mi++){
        split_pack(sacc[mi][2*kt][0],   sacc[mi][2*kt][1],   sh[mi][0], sl[mi][0]);
        split_pack(sacc[mi][2*kt][2],   sacc[mi][2*kt][3],   sh[mi][1], sl[mi][1]);
        split_pack(sacc[mi][2*kt+1][0], sacc[mi][2*kt+1][1], sh[mi][2], sl[mi][2]);
        split_pack(sacc[mi][2*kt+1][2], sacc[mi][2*kt+1][3], sh[mi][3], sl[mi][3]);
      }
      u32 vh[8][2], vl[8][2];
      #pragma unroll
      for(int np=0; np<4; np++){
        int r = np*16 + (lane & 7) + ((lane >> 4)*8);
        int cc = koff + ((lane >> 3) & 1)*8;
        u32 r0,r1,r2,r3;
        ldsm4(r0,r1,r2,r3, smaddr(sVh + r*RPITCH + cc));
        vh[np*2][0]=r0; vh[np*2][1]=r1; vh[np*2+1][0]=r2; vh[np*2+1][1]=r3;
        ldsm4(r0,r1,r2,r3, smaddr(sVl + r*RPITCH + cc));
        vl[np*2][0]=r0; vl[np*2][1]=r1; vl[np*2+1][0]=r2; vl[np*2+1][1]=r3;
      }
      #pragma unroll
      for(int mi=0; mi<2; mi++)
        #pragma unroll
        for(int nd=0; nd<8; nd++){
          mma_bf(oacc[mi][nd], sh[mi], vh[nd][0], vh[nd][1]);
          mma_bf(oacc[mi][nd], sh[mi], vl[nd][0], vl[nd][1]);
          mma_bf(oacc[mi][nd], sl[mi], vh[nd][0], vh[nd][1]);
        }
    }
    __syncthreads();   // V buffer free for next iter
  }
  cpwait0();

  // ---- cross-warp combine over wj halves (alias over Q area) ----
  float* Op = (float*)sm;     // 64 x pitch66
  if (wj == 0){
    #pragma unroll
    for(int mi=0; mi<2; mi++)
      #pragma unroll
      for(int nd=0; nd<8; nd++){
        int row = wi*32 + mi*16 + (lane >> 2);
        int d   = nd*8 + (lane & 3)*2;
        Op[row*66 + d]     = oacc[mi][nd][0];
        Op[row*66 + d + 1] = oacc[mi][nd][1];
        Op[(row+8)*66 + d]     = oacc[mi][nd][2];
        Op[(row+8)*66 + d + 1] = oacc[mi][nd][3];
      }
  }
  __syncthreads();
  if (wj == 1){
    #pragma unroll
    for(int mi=0; mi<2; mi++)
      #pragma unroll
      for(int nd=0; nd<8; nd++){
        int row = wi*32 + mi*16 + (lane >> 2);
        int d   = nd*8 + (lane & 3)*2;
        float a0 = oacc[mi][nd][0] + Op[row*66 + d];
        float a1 = oacc[mi][nd][1] + Op[row*66 + d + 1];
        float a2 = oacc[mi][nd][2] + Op[(row+8)*66 + d];
        float a3 = oacc[mi][nd][3] + Op[(row+8)*66 + d + 1];
        size_t r0 = (size_t)(b*Tc + i0 + row)*Ec + h*64 + d;
        size_t r1 = (size_t)(b*Tc + i0 + row + 8)*Ec + h*64 + d;
        *(float2*)&O[r0] = make_float2(a0, a1);
        *(float2*)&O[r1] = make_float2(a2, a3);
      }
  }
}

// ============================================================
// GroupNorm stats, 2-stage, fp64 accumulation
// ============================================================
__global__ void gn_part_kernel(const float* __restrict__ O){
  int g = blockIdx.x;
  int c = blockIdx.y;
  int b = g >> 4, h = g & 15, tid = threadIdx.x;
  int tbase = c * (Tc/8);
  double s = 0.0, s2 = 0.0;
  for(int idx = tid; idx < (Tc/8)*HDc; idx += 256){
    int t = tbase + (idx >> 6), d = idx & 63;
    float v = O[(size_t)(b*Tc + t)*Ec + h*64 + d];
    s += (double)v; s2 += (double)v * (double)v;
  }
  __shared__ double rs[256], rs2[256];
  rs[tid] = s; rs2[tid] = s2;
  __syncthreads();
  for(int off=128; off>0; off>>=1){
    if(tid < off){ rs[tid]+=rs[tid+off]; rs2[tid]+=rs2[tid+off]; }
    __syncthreads();
  }
  if(tid == 0){
    g_part[(g*8 + c)*2 + 0] = rs[0];
    g_part[(g*8 + c)*2 + 1] = rs2[0];
  }
}
__global__ void gn_final_kernel(){
  int g = threadIdx.x;
  if(g >= Bc*Hc) return;
  double s=0.0, s2=0.0;
  for(int c=0;c<8;c++){ s += g_part[(g*8+c)*2]; s2 += g_part[(g*8+c)*2+1]; }
  double N = (double)(Tc*HDc);
  double mean = s/N;
  double var  = s2/N - mean*mean;
  g_stats[g*2+0] = (float)mean;
  g_stats[g*2+1] = (float)(1.0 / sqrt(var + 1e-5));
}

// ============================================================
// Y = silu(G) * groupnorm(O)  -> split bf16
// ============================================================
__global__ void gate_norm_kernel(const float* __restrict__ O, const float* __restrict__ G,
                                 const float* __restrict__ w, const float* __restrict__ bb,
                                 u16* __restrict__ Yh, u16* __restrict__ Yl)
{
  int i2 = blockIdx.x*blockDim.x + threadIdx.x;
  if(i2 >= Mc*Ec/2) return;
  int idx = i2*2;
  int row = idx >> 10, e = idx & 1023;
  int b = row >> 11;
  int g = b*Hc + (e >> 6);
  float mean = g_stats[g*2+0], rstd = g_stats[g*2+1];
  float o0 = (O[idx]   - mean)*rstd*w[e]   + bb[e];
  float o1 = (O[idx+1] - mean)*rstd*w[e+1] + bb[e+1];
  float g0 = G[idx],   g1 = G[idx+1];
  float y0 = (g0 / (1.f + __expf(-g0))) * o0;
  float y1 = (g1 / (1.f + __expf(-g1))) * o1;
  u32 hi, lo; split_pack(y0, y1, hi, lo);
  ((u32*)Yh)[i2] = hi;
  ((u32*)Yl)[i2] = lo;
}

// ============================================================
extern "C" void kernel_launch(void* const* d_in, const int* in_sizes, int n_in,
                              void* d_out, int out_size)
{
  const float* x   = (const float*)d_in[0];
  const float* Wq  = (const float*)d_in[1];
  const float* bq  = (const float*)d_in[2];
  const float* Wk  = (const float*)d_in[3];
  const float* bk  = (const float*)d_in[4];
  const float* Wv  = (const float*)d_in[5];
  const float* bv  = (const float*)d_in[6];
  const float* Wg  = (const float*)d_in[7];
  const float* bg  = (const float*)d_in[8];
  const float* Wo  = (const float*)d_in[9];
  const float* bo  = (const float*)d_in[10];
  const float* gnw = (const float*)d_in[11];
  const float* gnb = (const float*)d_in[12];
  float* out = (float*)d_out;

  u16 *xh,*xl,*Qh,*Ql,*Kh,*Kl,*Vth,*Vtl,*Yh,*Yl;
  float *Gp,*Op;
  cudaGetSymbolAddress((void**)&xh, g_xh);   cudaGetSymbolAddress((void**)&xl, g_xl);
  cudaGetSymbolAddress((void**)&Qh, g_Qh);   cudaGetSymbolAddress((void**)&Ql, g_Ql);
  cudaGetSymbolAddress((void**)&Kh, g_Kh);   cudaGetSymbolAddress((void**)&Kl, g_Kl);
  cudaGetSymbolAddress((void**)&Vth, g_Vth); cudaGetSymbolAddress((void**)&Vtl, g_Vtl);
  cudaGetSymbolAddress((void**)&Yh, g_Yh);   cudaGetSymbolAddress((void**)&Yl, g_Yl);
  cudaGetSymbolAddress((void**)&Gp, g_G);    cudaGetSymbolAddress((void**)&Op, g_O);

  // launches 1..5, so retention is launch #6 (ncu -s 5 -c 1 captures it)
  rope_table_kernel<<<(Tc*HDc + 255)/256, 256>>>();                          // 1
  int half = Mc*Ec/2;
  convert_kernel<<<(half + 255)/256, 256>>>(x, xh, xl, half);                // 2
  convert_kernel<<<(half + 255)/256, 256>>>(x + half, xh + half, xl + half, half); // 3
  convertW_kernel<<<dim3((Ec*Ec + 255)/256, 5), 256>>>(Wq, Wk, Wv, Wg, Wo);  // 4

  size_t gsm = 81920;
  cudaFuncSetAttribute(gemm_bs, cudaFuncAttributeMaxDynamicSharedMemorySize, (int)gsm);
  // batched projections: z -> {Q, K, V, G}                                  // 5
  gemm_bs<<<dim3(Ec/128, Mc/128, 4), 256, gsm>>>(xh, xl, bq, bk, bv, bg, 0, nullptr);

  size_t rsm = 73728;
  cudaFuncSetAttribute(retention_mma, cudaFuncAttributeMaxDynamicSharedMemorySize, (int)rsm);
  retention_mma<<<dim3(Tc/64, Bc*Hc), 128, rsm>>>(Qh, Ql, Kh, Kl, Vth, Vtl, Op);  // 6

  gn_part_kernel<<<dim3(Bc*Hc, 8), 256>>>(Op);
  gn_final_kernel<<<1, 32>>>();

  gate_norm_kernel<<<(Mc*Ec/2 + 255)/256, 256>>>(Op, Gp, gnw, gnb, Yh, Yl);

  // final: out = Y @ Wo^T + bo   (w = 4)
  gemm_bs<<<dim3(Ec/128, Mc/128, 1), 256, gsm>>>(Yh, Yl, bo, bo, bo, bo, 4, out);
}

// round 8
// speedup vs baseline: 2.6007x; 1.0385x over previous
#include <cuda_runtime.h>
#include <cuda_bf16.h>
#include <math.h>
#include <stdint.h>

// Problem dims (fixed)
#define Bc 2
#define Tc 2048
#define Ec 1024
#define Hc 16
#define HDc 64
#define Mc (Bc*Tc)   // 4096

typedef unsigned short u16;
typedef unsigned int   u32;

// -------- scratch (device globals; no allocation allowed) --------
__device__ u16 g_xh[Mc*Ec], g_xl[Mc*Ec];
__device__ u16 g_Wh[5*Ec*Ec], g_Wl[5*Ec*Ec];   // q,k,v,g,o packed
__device__ u16 g_Qh[Mc*Ec], g_Ql[Mc*Ec];
__device__ u16 g_Kh[Mc*Ec], g_Kl[Mc*Ec];
__device__ u16 g_Vth[Mc*Ec], g_Vtl[Mc*Ec];     // V transposed: [b][e][t]
__device__ u16 g_Yh[Mc*Ec], g_Yl[Mc*Ec];
__device__ float g_G[Mc*Ec];
__device__ float g_O[Mc*Ec];
__device__ double g_part[Bc*Hc*8*2];
__device__ float g_stats[Bc*Hc*2];
__device__ float g_rc[Tc*HDc], g_rs[Tc*HDc];

// ------------------- helpers -------------------
__device__ __forceinline__ u32 smaddr(const void* p){ return (u32)__cvta_generic_to_shared(p); }
__device__ __forceinline__ void cp16(u32 d, const void* s){
  asm volatile("cp.async.cg.shared.global [%0], [%1], 16;\n"::"r"(d),"l"(s));
}
__device__ __forceinline__ void cpcommit(){ asm volatile("cp.async.commit_group;\n"); }
__device__ __forceinline__ void cpwait0(){ asm volatile("cp.async.wait_group 0;\n"); }
__device__ __forceinline__ void cpwait1(){ asm volatile("cp.async.wait_group 1;\n"); }
__device__ __forceinline__ void cpwait2(){ asm volatile("cp.async.wait_group 2;\n"); }
__device__ __forceinline__ void ldsm4(u32&r0,u32&r1,u32&r2,u32&r3,u32 a){
  asm volatile("ldmatrix.sync.aligned.m8n8.x4.shared.b16 {%0,%1,%2,%3},[%4];\n"
    :"=r"(r0),"=r"(r1),"=r"(r2),"=r"(r3):"r"(a));
}
__device__ __forceinline__ void mma_bf(float* c, const u32* a, u32 b0, u32 b1){
  asm volatile("mma.sync.aligned.m16n8k16.row.col.f32.bf16.bf16.f32 "
    "{%0,%1,%2,%3},{%4,%5,%6,%7},{%8,%9},{%0,%1,%2,%3};\n"
    :"+f"(c[0]),"+f"(c[1]),"+f"(c[2]),"+f"(c[3])
    :"r"(a[0]),"r"(a[1]),"r"(a[2]),"r"(a[3]),"r"(b0),"r"(b1));
}
__device__ __forceinline__ u16 f2bf(float x){
  __nv_bfloat16 h = __float2bfloat16_rn(x);
  return *reinterpret_cast<u16*>(&h);
}
__device__ __forceinline__ float bf2f(u16 u){
  __nv_bfloat16 h; *reinterpret_cast<u16*>(&h)=u; return __bfloat162float(h);
}
__device__ __forceinline__ void split_pack(float a, float b, u32& hi, u32& lo){
  u16 ha = f2bf(a), hb = f2bf(b);
  u16 la = f2bf(a - bf2f(ha)), lb = f2bf(b - bf2f(hb));
  hi = (u32)ha | ((u32)hb << 16);
  lo = (u32)la | ((u32)lb << 16);
}

// ------------------- rope table -------------------
__global__ void rope_table_kernel() {
  int idx = blockIdx.x * blockDim.x + threadIdx.x;
  if (idx >= Tc*HDc) return;
  int t = idx / HDc;
  int dd = idx % HDc;
  double f = pow(10000.0, -(double)(dd & 31) / 32.0);
  double th = (double)t * f;
  g_rc[idx] = (float)cos(th);
  g_rs[idx] = (float)sin(th);
}

// ------------------- fp32 -> split bf16, 4-wide -------------------
__global__ void convert4_kernel(const float* __restrict__ in, u16* __restrict__ h,
                                u16* __restrict__ l, int n4){
  int i = blockIdx.x*blockDim.x + threadIdx.x;
  if(i >= n4) return;
  float4 x = ((const float4*)in)[i];
  u16 h0=f2bf(x.x), h1=f2bf(x.y), h2=f2bf(x.z), h3=f2bf(x.w);
  u16 l0=f2bf(x.x-bf2f(h0)), l1=f2bf(x.y-bf2f(h1));
  u16 l2=f2bf(x.z-bf2f(h2)), l3=f2bf(x.w-bf2f(h3));
  uint2 hv, lv;
  hv.x = (u32)h0 | ((u32)h1<<16); hv.y = (u32)h2 | ((u32)h3<<16);
  lv.x = (u32)l0 | ((u32)l1<<16); lv.y = (u32)l2 | ((u32)l3<<16);
  ((uint2*)h)[i] = hv;
  ((uint2*)l)[i] = lv;
}
__global__ void convertW4_kernel(const float* __restrict__ w0, const float* __restrict__ w1,
                                 const float* __restrict__ w2, const float* __restrict__ w3,
                                 const float* __restrict__ w4){
  int z = blockIdx.y;
  const float* src = (z==0)?w0:(z==1)?w1:(z==2)?w2:(z==3)?w3:w4;
  int i = blockIdx.x*blockDim.x + threadIdx.x;
  if(i >= Ec*Ec/4) return;
  float4 x = ((const float4*)src)[i];
  u16 h0=f2bf(x.x), h1=f2bf(x.y), h2=f2bf(x.z), h3=f2bf(x.w);
  u16 l0=f2bf(x.x-bf2f(h0)), l1=f2bf(x.y-bf2f(h1));
  u16 l2=f2bf(x.z-bf2f(h2)), l3=f2bf(x.w-bf2f(h3));
  uint2 hv, lv;
  hv.x = (u32)h0 | ((u32)h1<<16); hv.y = (u32)h2 | ((u32)h3<<16);
  lv.x = (u32)l0 | ((u32)l1<<16); lv.y = (u32)l2 | ((u32)l3<<16);
  size_t base = (size_t)z*(Ec*Ec/4);
  ((uint2*)g_Wh)[base + i] = hv;
  ((uint2*)g_Wl)[base + i] = lv;
}

// ============================================================
// Split-bf16 tensor-core GEMM: C[m,n] = sum_k A[m,k]*W[n,k] + bias[n]
// tiles 128x128x32, 256 threads (8 warps, 2x4), warp tile 64x32.
// w = zoff + blockIdx.z selects weight slice + epilogue:
//   w=0: Q (bias+RoPE -> g_Qh/g_Ql)   w=1: K (bias+RoPE -> g_Kh/g_Kl)
//   w=2: V (bias -> transposed g_Vth/g_Vtl)
//   w=3: G (bias -> g_G fp32)         w=4: O (bias -> outf fp32)
// ============================================================
#define GPITCH 40   // halves per smem row (32 data + 8 pad) -> conflict-free
__global__ void __launch_bounds__(256, 2)
gemm_bs(const u16* __restrict__ Ah, const u16* __restrict__ Al,
        const float* __restrict__ b0, const float* __restrict__ b1,
        const float* __restrict__ b2, const float* __restrict__ b3,
        int zoff, float* __restrict__ outf)
{
  extern __shared__ u16 sm[];
  const int K = Ec;
  int tid = threadIdx.x, lane = tid & 31, wid = tid >> 5;
  int bm = blockIdx.y * 128, bn = blockIdx.x * 128;
  int wm = wid >> 2, wn = wid & 3;
  int z = blockIdx.z, w = zoff + z;
  const u16* Bh = g_Wh + (size_t)w*Ec*Ec;
  const u16* Bl = g_Wl + (size_t)w*Ec*Ec;
  const float* bias = (z==0)?b0:(z==1)?b1:(z==2)?b2:b3;

  float acc[4][4][4];
  #pragma unroll
  for(int i=0;i<4;i++)
    #pragma unroll
    for(int j=0;j<4;j++)
      #pragma unroll
      for(int k=0;k<4;k++) acc[i][j][k] = 0.f;

  auto load_stage = [&](int s, int k0){
    u16* st = sm + s*20480;
    const u16* srcs[4] = { Ah + (size_t)bm*K + k0, Al + (size_t)bm*K + k0,
                           Bh + (size_t)bn*K + k0, Bl + (size_t)bn*K + k0 };
    #pragma unroll
    for(int tl=0; tl<4; tl++){
      #pragma unroll
      for(int i=0;i<2;i++){
        int c = tid*2 + i;          // 0..511
        int r = c >> 2, seg = c & 3;
        cp16(smaddr(st + tl*5120 + r*GPITCH + seg*8),
             srcs[tl] + (size_t)r*K + seg*8);
      }
    }
  };

  load_stage(0, 0); cpcommit();
  const int NK = K/32;   // 32
  for(int kt=0; kt<NK; kt++){
    if(kt+1 < NK) load_stage((kt+1)&1, (kt+1)*32);
    cpcommit(); cpwait1(); __syncthreads();
    u16* st  = sm + (kt&1)*20480;
    u16* sAh = st;          u16* sAl = st + 5120;
    u16* sBh = st + 10240;  u16* sBl = st + 15360;

    #pragma unroll
    for(int ks=0; ks<2; ks++){
      int koff = ks*16;
      u32 ah[4][4], al[4][4];
      #pragma unroll
      for(int mi=0; mi<4; mi++){
        int r = wm*64 + mi*16 + (lane & 15);
        int cc = koff + (lane >> 4)*8;
        ldsm4(ah[mi][0],ah[mi][1],ah[mi][2],ah[mi][3], smaddr(sAh + r*GPITCH + cc));
        ldsm4(al[mi][0],al[mi][1],al[mi][2],al[mi][3], smaddr(sAl + r*GPITCH + cc));
      }
      u32 bh[4][2], bl[4][2];
      #pragma unroll
      for(int np=0; np<2; np++){
        int r = wn*32 + np*16 + (lane & 7) + ((lane >> 4)*8);
        int cc = koff + ((lane >> 3) & 1)*8;
        u32 r0,r1,r2,r3;
        ldsm4(r0,r1,r2,r3, smaddr(sBh + r*GPITCH + cc));
        bh[np*2][0]=r0; bh[np*2][1]=r1; bh[np*2+1][0]=r2; bh[np*2+1][1]=r3;
        ldsm4(r0,r1,r2,r3, smaddr(sBl + r*GPITCH + cc));
        bl[np*2][0]=r0; bl[np*2][1]=r1; bl[np*2+1][0]=r2; bl[np*2+1][1]=r3;
      }
      #pragma unroll
      for(int mi=0; mi<4; mi++)
        #pragma unroll
        for(int nj=0; nj<4; nj++){
          mma_bf(acc[mi][nj], ah[mi], bh[nj][0], bh[nj][1]);
          mma_bf(acc[mi][nj], ah[mi], bl[nj][0], bl[nj][1]);
          mma_bf(acc[mi][nj], al[mi], bh[nj][0], bh[nj][1]);
        }
    }
    __syncthreads();
  }
  cpwait0();

  // epilogue
  int mode = (w < 2) ? 1 : ((w == 2) ? 2 : 0);
  #pragma unroll
  for(int mi=0; mi<4; mi++){
    int row0 = bm + wm*64 + mi*16 + (lane >> 2);
    #pragma unroll
    for(int nj=0; nj<4; nj++){
      int col = bn + wn*32 + nj*8 + (lane & 3)*2;
      float bv0 = bias[col], bv1 = bias[col+1];
      float v00 = acc[mi][nj][0] + bv0, v01 = acc[mi][nj][1] + bv1;
      float v10 = acc[mi][nj][2] + bv0, v11 = acc[mi][nj][3] + bv1;
      if (mode == 0){
        float* dst = (w == 3) ? g_G : outf;
        *(float2*)&dst[(size_t)row0*Ec + col]     = make_float2(v00, v01);
        *(float2*)&dst[(size_t)(row0+8)*Ec + col] = make_float2(v10, v11);
      } else if (mode == 1){
        u16* oh = (w == 0) ? g_Qh : g_Kh;
        u16* ol = (w == 0) ? g_Ql : g_Kl;
        int dd = col & 63;
        int t0 = row0 & (Tc-1), t1 = (row0+8) & (Tc-1);
        float c0 = g_rc[t0*HDc+dd],   s0 = g_rs[t0*HDc+dd];
        float c1 = g_rc[t0*HDc+dd+1], s1 = g_rs[t0*HDc+dd+1];
        float y0 = v00*c0 - v01*s0;
        float y1 = v01*c1 + v00*s1;
        u32 hi, lo; split_pack(y0, y1, hi, lo);
        ((u32*)oh)[((size_t)row0*Ec + col) >> 1] = hi;
        ((u32*)ol)[((size_t)row0*Ec + col) >> 1] = lo;
        float d0 = g_rc[t1*HDc+dd],   e0 = g_rs[t1*HDc+dd];
        float d1 = g_rc[t1*HDc+dd+1], e1 = g_rs[t1*HDc+dd+1];
        float z0 = v10*d0 - v11*e0;
        float z1 = v11*d1 + v10*e1;
        split_pack(z0, z1, hi, lo);
        ((u32*)oh)[((size_t)(row0+8)*Ec + col) >> 1] = hi;
        ((u32*)ol)[((size_t)(row0+8)*Ec + col) >> 1] = lo;
      } else { // mode 2: transposed split V
        int bi0 = row0 >> 11; int t0 = row0 & (Tc-1);
        size_t i0s = (size_t)bi0*Ec*Tc + (size_t)col*Tc + t0;
        u16 h00 = f2bf(v00); g_Vth[i0s]    = h00; g_Vtl[i0s]    = f2bf(v00 - bf2f(h00));
        u16 h01 = f2bf(v01); g_Vth[i0s+Tc] = h01; g_Vtl[i0s+Tc] = f2bf(v01 - bf2f(h01));
        int row1 = row0 + 8;
        int bi1 = row1 >> 11; int t1 = row1 & (Tc-1);
        size_t i1s = (size_t)bi1*Ec*Tc + (size_t)col*Tc + t1;
        u16 h10 = f2bf(v10); g_Vth[i1s]    = h10; g_Vtl[i1s]    = f2bf(v10 - bf2f(h10));
        u16 h11 = f2bf(v11); g_Vth[i1s+Tc] = h11; g_Vtl[i1s+Tc] = f2bf(v11 - bf2f(h11));
      }
    }
  }
}

// ============================================================
// Retention, mma.sync, split-bf16:
//   O[b,h,i,:] = sum_{j>=i} gamma_h^{j-i} (Q_i.K_j/8) V_j
// smem: Q hi/lo (2x4608h), K stages 2x(hi+lo 9216h), V single (hi+lo 9216h)
// total 36864 halves = 73728 B -> 3 blocks/SM; launch_bounds(128,3).
// ============================================================
#define RPITCH 72
__global__ void __launch_bounds__(128, 3)
retention_mma(const u16* __restrict__ Qh_, const u16* __restrict__ Ql_,
              const u16* __restrict__ Kh_, const u16* __restrict__ Kl_,
              const u16* __restrict__ Vth, const u16* __restrict__ Vtl,
              float* __restrict__ O)
{
  extern __shared__ u16 sm[];
  int tid = threadIdx.x, lane = tid & 31, wid = tid >> 5;
  int wi = wid >> 1, wj = wid & 1;
  int bh = blockIdx.y, b = bh >> 4, h = bh & 15;
  int it = blockIdx.x; int i0 = it*64;

  float lg2;
  { double g = 1.0 - ldexp(1.0, -(5+h)); lg2 = (float)log2(g); }

  // Q tile loads (once)
  {
    #pragma unroll
    for(int tl=0; tl<2; tl++){
      const u16* src = (tl ? Ql_ : Qh_) + (size_t)(b*Tc + i0)*Ec + h*64;
      u16* dst = sm + tl*4608;
      #pragma unroll
      for(int i=0;i<4;i++){
        int c = tid*4 + i;
        int r = c >> 3, seg = c & 7;
        cp16(smaddr(dst + r*RPITCH + seg*8), src + (size_t)r*Ec + seg*8);
      }
    }
  }
  auto load_K = [&](int s, int j0){
    u16* st = sm + 9216 + s*9216;
    const u16* sK[2] = { Kh_ + (size_t)(b*Tc + j0)*Ec + h*64,
                         Kl_ + (size_t)(b*Tc + j0)*Ec + h*64 };
    #pragma unroll
    for(int tl=0; tl<2; tl++){
      #pragma unroll
      for(int i=0;i<4;i++){
        int c = tid*4 + i;
        int r = c >> 3, seg = c & 7;
        cp16(smaddr(st + tl*4608 + r*RPITCH + seg*8), sK[tl] + (size_t)r*Ec + seg*8);
      }
    }
  };
  auto load_V = [&](int j0){
    u16* st = sm + 27648;
    const u16* sV[2] = { Vth + (size_t)b*Ec*Tc + (size_t)(h*64)*Tc + j0,
                         Vtl + (size_t)b*Ec*Tc + (size_t)(h*64)*Tc + j0 };
    #pragma unroll
    for(int tl=0; tl<2; tl++){
      #pragma unroll
      for(int i=0;i<4;i++){
        int c = tid*4 + i;
        int r = c >> 3, seg = c & 7;
        cp16(smaddr(st + tl*4608 + r*RPITCH + seg*8), sV[tl] + (size_t)r*Tc + seg*8);
      }
    }
  };

  float inv = -lg2;
  int jtEnd = (i0 + 63 + (int)(20.0f/inv)) / 64;
  if (jtEnd > Tc/64 - 1) jtEnd = Tc/64 - 1;

  load_K(0, it*64);   // diagonal K tile
  cpcommit();         // group: K[it]

  float rowF[2][2], colF[4][2];
  int   ilv[2][2],  jlv[4][2];
  #pragma unroll
  for(int mi=0; mi<2; mi++)
    #pragma unroll
    for(int hf=0; hf<2; hf++){
      int il = wi*32 + mi*16 + (lane >> 2) + hf*8;
      ilv[mi][hf] = il;
      rowF[mi][hf] = exp2f(-(float)il * lg2);
    }
  #pragma unroll
  for(int nj=0; nj<4; nj++)
    #pragma unroll
    for(int cp=0; cp<2; cp++){
      int jl = wj*32 + nj*8 + (lane & 3)*2 + cp;
      jlv[nj][cp] = jl;
      colF[nj][cp] = exp2f((float)jl * lg2);
    }

  float oacc[2][8][4];
  #pragma unroll
  for(int i=0;i<2;i++)
    #pragma unroll
    for(int j=0;j<8;j++)
      #pragma unroll
      for(int k=0;k<4;k++) oacc[i][j][k]=0.f;

  u16* sQh = sm; u16* sQl = sm + 4608;
  u16* sVh = sm + 27648; u16* sVl = sm + 32256;

  for(int jt = it; jt <= jtEnd; jt++){
    int s = (jt - it) & 1;
    load_V(jt*64); cpcommit();                 // group: V[jt]
    bool havK = (jt + 1 <= jtEnd);
    if (havK){ load_K(s^1, (jt+1)*64); cpcommit(); }   // group: K[jt+1]
    if (havK) cpwait2(); else cpwait1();
    __syncthreads();
    u16 *sKh = sm + 9216 + s*9216, *sKl = sKh + 4608;

    // ---- phase A: S = Q K^T ----
    float sacc[2][4][4];
    #pragma unroll
    for(int i=0;i<2;i++)
      #pragma unroll
      for(int j=0;j<4;j++)
        #pragma unroll
        for(int k=0;k<4;k++) sacc[i][j][k]=0.f;

    #pragma unroll
    for(int ks=0; ks<4; ks++){
      int koff = ks*16;
      u32 qh[2][4], ql[2][4];
      #pragma unroll
      for(int mi=0; mi<2; mi++){
        int r = wi*32 + mi*16 + (lane & 15);
        int cc = koff + (lane >> 4)*8;
        ldsm4(qh[mi][0],qh[mi][1],qh[mi][2],qh[mi][3], smaddr(sQh + r*RPITCH + cc));
        ldsm4(ql[mi][0],ql[mi][1],ql[mi][2],ql[mi][3], smaddr(sQl + r*RPITCH + cc));
      }
      u32 kh[4][2], kl[4][2];
      #pragma unroll
      for(int np=0; np<2; np++){
        int r = wj*32 + np*16 + (lane & 7) + ((lane >> 4)*8);
        int cc = koff + ((lane >> 3) & 1)*8;
        u32 r0,r1,r2,r3;
        ldsm4(r0,r1,r2,r3, smaddr(sKh + r*RPITCH + cc));
        kh[np*2][0]=r0; kh[np*2][1]=r1; kh[np*2+1][0]=r2; kh[np*2+1][1]=r3;
        ldsm4(r0,r1,r2,r3, smaddr(sKl + r*RPITCH + cc));
        kl[np*2][0]=r0; kl[np*2][1]=r1; kl[np*2+1][0]=r2; kl[np*2+1][1]=r3;
      }
      #pragma unroll
      for(int mi=0; mi<2; mi++)
        #pragma unroll
        for(int nj=0; nj<4; nj++){
          mma_bf(sacc[mi][nj], qh[mi], kh[nj][0], kh[nj][1]);
          mma_bf(sacc[mi][nj], qh[mi], kl[nj][0], kl[nj][1]);
          mma_bf(sacc[mi][nj], ql[mi], kh[nj][0], kh[nj][1]);
        }
    }

    // ---- decay + mask + 1/8 ----
    float base = exp2f((float)((jt-it)*64) * lg2) * 0.125f;
    bool diag = (jt == it);
    #pragma unroll
    for(int mi=0; mi<2; mi++)
      #pragma unroll
      for(int nj=0; nj<4; nj++){
        float f00 = base*rowF[mi][0]*colF[nj][0];
        float f01 = base*rowF[mi][0]*colF[nj][1];
        float f10 = base*rowF[mi][1]*colF[nj][0];
        float f11 = base*rowF[mi][1]*colF[nj][1];
        if (diag){
          if (jlv[nj][0] < ilv[mi][0]) f00 = 0.f;
          if (jlv[nj][1] < ilv[mi][0]) f01 = 0.f;
          if (jlv[nj][0] < ilv[mi][1]) f10 = 0.f;
          if (jlv[nj][1] < ilv[mi][1]) f11 = 0.f;
        }
        sacc[mi][nj][0] *= f00; sacc[mi][nj][1] *= f01;
        sacc[mi][nj][2] *= f10; sacc[mi][nj][3] *= f11;
      }

    // need V[jt] for phase B; allow K[jt+1] pending
    if (havK) cpwait1(); else cpwait0();
    __syncthreads();

    // ---- phase B: O += S V (register repack of S to A-frags) ----
    #pragma unroll
    for(int kt=0; kt<2; kt++){
      int koff = wj*32 + kt*16;
      u32 sh[2][4], sl[2][4];
      #pragma unroll
      for(int mi=0; mi<2; mi++){
        split_pack(sacc[mi][2*kt][0],   sacc[mi][2*kt][1],   sh[mi][0], sl[mi][0]);
        split_pack(sacc[mi][2*kt][2],   sacc[mi][2*kt][3],   sh[mi][1], sl[mi][1]);
        split_pack(sacc[mi][2*kt+1][0], sacc[mi][2*kt+1][1], sh[mi][2], sl[mi][2]);
        split_pack(sacc[mi][2*kt+1][2], sacc[mi][2*kt+1][3], sh[mi][3], sl[mi][3]);
      }
      u32 vh[8][2], vl[8][2];
      #pragma unroll
      for(int np=0; np<4; np++){
        int r = np*16 + (lane & 7) + ((lane >> 4)*8);
        int cc = koff + ((lane >> 3) & 1)*8;
        u32 r0,r1,r2,r3;
        ldsm4(r0,r1,r2,r3, smaddr(sVh + r*RPITCH + cc));
        vh[np*2][0]=r0; vh[np*2][1]=r1; vh[np*2+1][0]=r2; vh[np*2+1][1]=r3;
        ldsm4(r0,r1,r2,r3, smaddr(sVl + r*RPITCH + cc));
        vl[np*2][0]=r0; vl[np*2][1]=r1; vl[np*2+1][0]=r2; vl[np*2+1][1]=r3;
      }
      #pragma unroll
      for(int mi=0; mi<2; mi++)
        #pragma unroll
        for(int nd=0; nd<8; nd++){
          mma_bf(oacc[mi][nd], sh[mi], vh[nd][0], vh[nd][1]);
          mma_bf(oacc[mi][nd], sh[mi], vl[nd][0], vl[nd][1]);
          mma_bf(oacc[mi][nd], sl[mi], vh[nd][0], vh[nd][1]);
        }
    }
    __syncthreads();   // V buffer free for next iter
  }
  cpwait0();

  // ---- cross-warp combine over wj halves (alias over Q area) ----
  float* Op = (float*)sm;     // 64 x pitch66
  if (wj == 0){
    #pragma unroll
    for(int mi=0; mi<2; mi++)
      #pragma unroll
      for(int nd=0; nd<8; nd++){
        int row = wi*32 + mi*16 + (lane >> 2);
        int d   = nd*8 + (lane & 3)*2;
        Op[row*66 + d]     = oacc[mi][nd][0];
        Op[row*66 + d + 1] = oacc[mi][nd][1];
        Op[(row+8)*66 + d]     = oacc[mi][nd][2];
        Op[(row+8)*66 + d + 1] = oacc[mi][nd][3];
      }
  }
  __syncthreads();
  if (wj == 1){
    #pragma unroll
    for(int mi=0; mi<2; mi++)
      #pragma unroll
      for(int nd=0; nd<8; nd++){
        int row = wi*32 + mi*16 + (lane >> 2);
        int d   = nd*8 + (lane & 3)*2;
        float a0 = oacc[mi][nd][0] + Op[row*66 + d];
        float a1 = oacc[mi][nd][1] + Op[row*66 + d + 1];
        float a2 = oacc[mi][nd][2] + Op[(row+8)*66 + d];
        float a3 = oacc[mi][nd][3] + Op[(row+8)*66 + d + 1];
        size_t r0 = (size_t)(b*Tc + i0 + row)*Ec + h*64 + d;
        size_t r1 = (size_t)(b*Tc + i0 + row + 8)*Ec + h*64 + d;
        *(float2*)&O[r0] = make_float2(a0, a1);
        *(float2*)&O[r1] = make_float2(a2, a3);
      }
  }
}

// ============================================================
// GroupNorm stats, 2-stage, fp64 accumulation
// ============================================================
__global__ void gn_part_kernel(const float* __restrict__ O){
  int g = blockIdx.x;
  int c = blockIdx.y;
  int b = g >> 4, h = g & 15, tid = threadIdx.x;
  int tbase = c * (Tc/8);
  double s = 0.0, s2 = 0.0;
  for(int idx = tid; idx < (Tc/8)*HDc/4; idx += 256){
    int t = tbase + (idx >> 4), d4 = (idx & 15)*4;
    float4 v = *(const float4*)&O[(size_t)(b*Tc + t)*Ec + h*64 + d4];
    s += (double)v.x + (double)v.y + (double)v.z + (double)v.w;
    s2 += (double)v.x*v.x + (double)v.y*v.y + (double)v.z*v.z + (double)v.w*v.w;
  }
  __shared__ double rs[256], rs2[256];
  rs[tid] = s; rs2[tid] = s2;
  __syncthreads();
  for(int off=128; off>0; off>>=1){
    if(tid < off){ rs[tid]+=rs[tid+off]; rs2[tid]+=rs2[tid+off]; }
    __syncthreads();
  }
  if(tid == 0){
    g_part[(g*8 + c)*2 + 0] = rs[0];
    g_part[(g*8 + c)*2 + 1] = rs2[0];
  }
}
__global__ void gn_final_kernel(){
  int g = threadIdx.x;
  if(g >= Bc*Hc) return;
  double s=0.0, s2=0.0;
  for(int c=0;c<8;c++){ s += g_part[(g*8+c)*2]; s2 += g_part[(g*8+c)*2+1]; }
  double N = (double)(Tc*HDc);
  double mean = s/N;
  double var  = s2/N - mean*mean;
  g_stats[g*2+0] = (float)mean;
  g_stats[g*2+1] = (float)(1.0 / sqrt(var + 1e-5));
}

// ============================================================
// Y = silu(G) * groupnorm(O)  -> split bf16, 4-wide
// ============================================================
__global__ void gate_norm4_kernel(const float* __restrict__ O, const float* __restrict__ G,
                                  const float* __restrict__ w, const float* __restrict__ bb,
                                  u16* __restrict__ Yh, u16* __restrict__ Yl)
{
  int i4 = blockIdx.x*blockDim.x + threadIdx.x;
  if(i4 >= Mc*Ec/4) return;
  int idx = i4*4;
  int row = idx >> 10, e = idx & 1023;
  int b = row >> 11;
  int g = b*Hc + (e >> 6);
  float mean = g_stats[g*2+0], rstd = g_stats[g*2+1];
  float4 ov = ((const float4*)O)[i4];
  float4 gv = ((const float4*)G)[i4];
  float4 wv = *(const float4*)&w[e];
  float4 bv = *(const float4*)&bb[e];
  float o0 = (ov.x - mean)*rstd*wv.x + bv.x;
  float o1 = (ov.y - mean)*rstd*wv.y + bv.y;
  float o2 = (ov.z - mean)*rstd*wv.z + bv.z;
  float o3 = (ov.w - mean)*rstd*wv.w + bv.w;
  float y0 = (gv.x / (1.f + __expf(-gv.x))) * o0;
  float y1 = (gv.y / (1.f + __expf(-gv.y))) * o1;
  float y2 = (gv.z / (1.f + __expf(-gv.z))) * o2;
  float y3 = (gv.w / (1.f + __expf(-gv.w))) * o3;
  u32 h01,l01,h23,l23;
  split_pack(y0, y1, h01, l01);
  split_pack(y2, y3, h23, l23);
  uint2 hv = make_uint2(h01, h23), lv = make_uint2(l01, l23);
  ((uint2*)Yh)[i4] = hv;
  ((uint2*)Yl)[i4] = lv;
}

// ============================================================
extern "C" void kernel_launch(void* const* d_in, const int* in_sizes, int n_in,
                              void* d_out, int out_size)
{
  const float* x   = (const float*)d_in[0];
  const float* Wq  = (const float*)d_in[1];
  const float* bq  = (const float*)d_in[2];
  const float* Wk  = (const float*)d_in[3];
  const float* bk  = (const float*)d_in[4];
  const float* Wv  = (const float*)d_in[5];
  const float* bv  = (const float*)d_in[6];
  const float* Wg  = (const float*)d_in[7];
  const float* bg  = (const float*)d_in[8];
  const float* Wo  = (const float*)d_in[9];
  const float* bo  = (const float*)d_in[10];
  const float* gnw = (const float*)d_in[11];
  const float* gnb = (const float*)d_in[12];
  float* out = (float*)d_out;

  u16 *xh,*xl,*Qh,*Ql,*Kh,*Kl,*Vth,*Vtl,*Yh,*Yl;
  float *Gp,*Op;
  cudaGetSymbolAddress((void**)&xh, g_xh);   cudaGetSymbolAddress((void**)&xl, g_xl);
  cudaGetSymbolAddress((void**)&Qh, g_Qh);   cudaGetSymbolAddress((void**)&Ql, g_Ql);
  cudaGetSymbolAddress((void**)&Kh, g_Kh);   cudaGetSymbolAddress((void**)&Kl, g_Kl);
  cudaGetSymbolAddress((void**)&Vth, g_Vth); cudaGetSymbolAddress((void**)&Vtl, g_Vtl);
  cudaGetSymbolAddress((void**)&Yh, g_Yh);   cudaGetSymbolAddress((void**)&Yl, g_Yl);
  cudaGetSymbolAddress((void**)&Gp, g_G);    cudaGetSymbolAddress((void**)&Op, g_O);

  // launch order puts gemm_bs at #4 and retention at #5 for ncu capture
  convertW4_kernel<<<dim3((Ec*Ec/4 + 255)/256, 5), 256>>>(Wq, Wk, Wv, Wg, Wo); // 1
  convert4_kernel<<<(Mc*Ec/4 + 255)/256, 256>>>(x, xh, xl, Mc*Ec/4);           // 2
  rope_table_kernel<<<(Tc*HDc + 255)/256, 256>>>();                            // 3

  size_t gsm = 81920;
  cudaFuncSetAttribute(gemm_bs, cudaFuncAttributeMaxDynamicSharedMemorySize, (int)gsm);
  // batched projections: z -> {Q, K, V, G}                                    // 4
  gemm_bs<<<dim3(Ec/128, Mc/128, 4), 256, gsm>>>(xh, xl, bq, bk, bv, bg, 0, nullptr);

  size_t rsm = 73728;
  cudaFuncSetAttribute(retention_mma, cudaFuncAttributeMaxDynamicSharedMemorySize, (int)rsm);
  retention_mma<<<dim3(Tc/64, Bc*Hc), 128, rsm>>>(Qh, Ql, Kh, Kl, Vth, Vtl, Op);  // 5

  gn_part_kernel<<<dim3(Bc*Hc, 8), 256>>>(Op);                                 // 6
  gn_final_kernel<<<1, 32>>>();                                                // 7

  gate_norm4_kernel<<<(Mc*Ec/4 + 255)/256, 256>>>(Op, Gp, gnw, gnb, Yh, Yl);   // 8

  // final: out = Y @ Wo^T + bo   (w = 4)                                      // 9
  gemm_bs<<<dim3(Ec/128, Mc/128, 1), 256, gsm>>>(Yh, Yl, bo, bo, bo, bo, 4, out);
}

// round 10
// speedup vs baseline: 2.7641x; 1.0629x over previous
#include <cuda_runtime.h>
#include <cuda_bf16.h>
#include <math.h>
#include <stdint.h>

// Problem dims (fixed)
#define Bc 2
#define Tc 2048
#define Ec 1024
#define Hc 16
#define HDc 64
#define Mc (Bc*Tc)   // 4096

typedef unsigned short u16;
typedef unsigned int   u32;

// -------- scratch (device globals; no allocation allowed) --------
__device__ u16 g_xh[Mc*Ec], g_xl[Mc*Ec];
__device__ u16 g_Wh[5*Ec*Ec], g_Wl[5*Ec*Ec];   // q,k,v,g,o packed
__device__ u16 g_Qh[Mc*Ec], g_Ql[Mc*Ec];
__device__ u16 g_Kh[Mc*Ec], g_Kl[Mc*Ec];
__device__ u16 g_Vth[Mc*Ec], g_Vtl[Mc*Ec];     // V transposed: [b][e][t]
__device__ u16 g_Yh[Mc*Ec], g_Yl[Mc*Ec];
__device__ float g_G[Mc*Ec];
__device__ float g_O[Mc*Ec];
__device__ double g_part[Bc*Hc*8*2];
__device__ float g_stats[Bc*Hc*2];
__device__ float g_rc[Tc*HDc], g_rs[Tc*HDc];

// ------------------- helpers -------------------
__device__ __forceinline__ u32 smaddr(const void* p){ return (u32)__cvta_generic_to_shared(p); }
__device__ __forceinline__ void cp16(u32 d, const void* s){
  asm volatile("cp.async.cg.shared.global [%0], [%1], 16;\n"::"r"(d),"l"(s));
}
__device__ __forceinline__ void cpcommit(){ asm volatile("cp.async.commit_group;\n"); }
__device__ __forceinline__ void cpwait0(){ asm volatile("cp.async.wait_group 0;\n"); }
__device__ __forceinline__ void cpwait1(){ asm volatile("cp.async.wait_group 1;\n"); }
__device__ __forceinline__ void cpwait2(){ asm volatile("cp.async.wait_group 2;\n"); }
__device__ __forceinline__ void ldsm4(u32&r0,u32&r1,u32&r2,u32&r3,u32 a){
  asm volatile("ldmatrix.sync.aligned.m8n8.x4.shared.b16 {%0,%1,%2,%3},[%4];\n"
    :"=r"(r0),"=r"(r1),"=r"(r2),"=r"(r3):"r"(a));
}
__device__ __forceinline__ void mma_bf(float* c, const u32* a, u32 b0, u32 b1){
  asm volatile("mma.sync.aligned.m16n8k16.row.col.f32.bf16.bf16.f32 "
    "{%0,%1,%2,%3},{%4,%5,%6,%7},{%8,%9},{%0,%1,%2,%3};\n"
    :"+f"(c[0]),"+f"(c[1]),"+f"(c[2]),"+f"(c[3])
    :"r"(a[0]),"r"(a[1]),"r"(a[2]),"r"(a[3]),"r"(b0),"r"(b1));
}
__device__ __forceinline__ u16 f2bf(float x){
  __nv_bfloat16 h = __float2bfloat16_rn(x);
  return *reinterpret_cast<u16*>(&h);
}
__device__ __forceinline__ float bf2f(u16 u){
  __nv_bfloat16 h; *reinterpret_cast<u16*>(&h)=u; return __bfloat162float(h);
}
__device__ __forceinline__ void split_pack(float a, float b, u32& hi, u32& lo){
  u16 ha = f2bf(a), hb = f2bf(b);
  u16 la = f2bf(a - bf2f(ha)), lb = f2bf(b - bf2f(hb));
  hi = (u32)ha | ((u32)hb << 16);
  lo = (u32)la | ((u32)lb << 16);
}

// ------------------- rope table -------------------
__global__ void rope_table_kernel() {
  int idx = blockIdx.x * blockDim.x + threadIdx.x;
  if (idx >= Tc*HDc) return;
  int t = idx / HDc;
  int dd = idx % HDc;
  double f = pow(10000.0, -(double)(dd & 31) / 32.0);
  double th = (double)t * f;
  g_rc[idx] = (float)cos(th);
  g_rs[idx] = (float)sin(th);
}

// ------------------- fp32 -> split bf16, 4-wide -------------------
__global__ void convert4_kernel(const float* __restrict__ in, u16* __restrict__ h,
                                u16* __restrict__ l, int n4){
  int i = blockIdx.x*blockDim.x + threadIdx.x;
  if(i >= n4) return;
  float4 x = ((const float4*)in)[i];
  u16 h0=f2bf(x.x), h1=f2bf(x.y), h2=f2bf(x.z), h3=f2bf(x.w);
  u16 l0=f2bf(x.x-bf2f(h0)), l1=f2bf(x.y-bf2f(h1));
  u16 l2=f2bf(x.z-bf2f(h2)), l3=f2bf(x.w-bf2f(h3));
  uint2 hv, lv;
  hv.x = (u32)h0 | ((u32)h1<<16); hv.y = (u32)h2 | ((u32)h3<<16);
  lv.x = (u32)l0 | ((u32)l1<<16); lv.y = (u32)l2 | ((u32)l3<<16);
  ((uint2*)h)[i] = hv;
  ((uint2*)l)[i] = lv;
}
__global__ void convertW4_kernel(const float* __restrict__ w0, const float* __restrict__ w1,
                                 const float* __restrict__ w2, const float* __restrict__ w3,
                                 const float* __restrict__ w4){
  int z = blockIdx.y;
  const float* src = (z==0)?w0:(z==1)?w1:(z==2)?w2:(z==3)?w3:w4;
  int i = blockIdx.x*blockDim.x + threadIdx.x;
  if(i >= Ec*Ec/4) return;
  float4 x = ((const float4*)src)[i];
  u16 h0=f2bf(x.x), h1=f2bf(x.y), h2=f2bf(x.z), h3=f2bf(x.w);
  u16 l0=f2bf(x.x-bf2f(h0)), l1=f2bf(x.y-bf2f(h1));
  u16 l2=f2bf(x.z-bf2f(h2)), l3=f2bf(x.w-bf2f(h3));
  uint2 hv, lv;
  hv.x = (u32)h0 | ((u32)h1<<16); hv.y = (u32)h2 | ((u32)h3<<16);
  lv.x = (u32)l0 | ((u32)l1<<16); lv.y = (u32)l2 | ((u32)l3<<16);
  size_t base = (size_t)z*(Ec*Ec/4);
  ((uint2*)g_Wh)[base + i] = hv;
  ((uint2*)g_Wl)[base + i] = lv;
}

// ============================================================
// Split-bf16 tensor-core GEMM: C[m,n] = sum_k A[m,k]*W[n,k] + bias[n]
// tiles 128x128x32, 256 threads (8 warps, 2x4), warp tile 64x32.
// w = zoff + blockIdx.z selects weight slice + epilogue:
//   w=0: Q (bias+RoPE -> g_Qh/g_Ql)   w=1: K (bias+RoPE -> g_Kh/g_Kl)
//   w=2: V (bias -> transposed g_Vth/g_Vtl)
//   w=3: G (bias -> g_G fp32)         w=4: O (bias -> outf fp32)
// ============================================================
#define GPITCH 40   // halves per smem row (32 data + 8 pad) -> conflict-free
__global__ void __launch_bounds__(256, 2)
gemm_bs(const u16* __restrict__ Ah, const u16* __restrict__ Al,
        const float* __restrict__ b0, const float* __restrict__ b1,
        const float* __restrict__ b2, const float* __restrict__ b3,
        int zoff, float* __restrict__ outf)
{
  extern __shared__ u16 sm[];
  const int K = Ec;
  int tid = threadIdx.x, lane = tid & 31, wid = tid >> 5;
  int bm = blockIdx.y * 128, bn = blockIdx.x * 128;
  int wm = wid >> 2, wn = wid & 3;
  int z = blockIdx.z, w = zoff + z;
  const u16* Bh = g_Wh + (size_t)w*Ec*Ec;
  const u16* Bl = g_Wl + (size_t)w*Ec*Ec;
  const float* bias = (z==0)?b0:(z==1)?b1:(z==2)?b2:b3;

  float acc[4][4][4];
  #pragma unroll
  for(int i=0;i<4;i++)
    #pragma unroll
    for(int j=0;j<4;j++)
      #pragma unroll
      for(int k=0;k<4;k++) acc[i][j][k] = 0.f;

  auto load_stage = [&](int s, int k0){
    u16* st = sm + s*20480;
    const u16* srcs[4] = { Ah + (size_t)bm*K + k0, Al + (size_t)bm*K + k0,
                           Bh + (size_t)bn*K + k0, Bl + (size_t)bn*K + k0 };
    #pragma unroll
    for(int tl=0; tl<4; tl++){
      #pragma unroll
      for(int i=0;i<2;i++){
        int c = tid*2 + i;          // 0..511
        int r = c >> 2, seg = c & 3;
        cp16(smaddr(st + tl*5120 + r*GPITCH + seg*8),
             srcs[tl] + (size_t)r*K + seg*8);
      }
    }
  };

  load_stage(0, 0); cpcommit();
  const int NK = K/32;   // 32
  for(int kt=0; kt<NK; kt++){
    if(kt+1 < NK) load_stage((kt+1)&1, (kt+1)*32);
    cpcommit(); cpwait1(); __syncthreads();
    u16* st  = sm + (kt&1)*20480;
    u16* sAh = st;          u16* sAl = st + 5120;
    u16* sBh = st + 10240;  u16* sBl = st + 15360;

    #pragma unroll
    for(int ks=0; ks<2; ks++){
      int koff = ks*16;
      u32 ah[4][4], al[4][4];
      #pragma unroll
      for(int mi=0; mi<4; mi++){
        int r = wm*64 + mi*16 + (lane & 15);
        int cc = koff + (lane >> 4)*8;
        ldsm4(ah[mi][0],ah[mi][1],ah[mi][2],ah[mi][3], smaddr(sAh + r*GPITCH + cc));
        ldsm4(al[mi][0],al[mi][1],al[mi][2],al[mi][3], smaddr(sAl + r*GPITCH + cc));
      }
      u32 bh[4][2], bl[4][2];
      #pragma unroll
      for(int np=0; np<2; np++){
        int r = wn*32 + np*16 + (lane & 7) + ((lane >> 4)*8);
        int cc = koff + ((lane >> 3) & 1)*8;
        u32 r0,r1,r2,r3;
        ldsm4(r0,r1,r2,r3, smaddr(sBh + r*GPITCH + cc));
        bh[np*2][0]=r0; bh[np*2][1]=r1; bh[np*2+1][0]=r2; bh[np*2+1][1]=r3;
        ldsm4(r0,r1,r2,r3, smaddr(sBl + r*GPITCH + cc));
        bl[np*2][0]=r0; bl[np*2][1]=r1; bl[np*2+1][0]=r2; bl[np*2+1][1]=r3;
      }
      #pragma unroll
      for(int mi=0; mi<4; mi++)
        #pragma unroll
        for(int nj=0; nj<4; nj++){
          mma_bf(acc[mi][nj], ah[mi], bh[nj][0], bh[nj][1]);
          mma_bf(acc[mi][nj], ah[mi], bl[nj][0], bl[nj][1]);
          mma_bf(acc[mi][nj], al[mi], bh[nj][0], bh[nj][1]);
        }
    }
    __syncthreads();
  }
  cpwait0();

  // epilogue
  int mode = (w < 2) ? 1 : ((w == 2) ? 2 : 0);
  #pragma unroll
  for(int mi=0; mi<4; mi++){
    int row0 = bm + wm*64 + mi*16 + (lane >> 2);
    #pragma unroll
    for(int nj=0; nj<4; nj++){
      int col = bn + wn*32 + nj*8 + (lane & 3)*2;
      float bv0 = bias[col], bv1 = bias[col+1];
      float v00 = acc[mi][nj][0] + bv0, v01 = acc[mi][nj][1] + bv1;
      float v10 = acc[mi][nj][2] + bv0, v11 = acc[mi][nj][3] + bv1;
      if (mode == 0){
        float* dst = (w == 3) ? g_G : outf;
        *(float2*)&dst[(size_t)row0*Ec + col]     = make_float2(v00, v01);
        *(float2*)&dst[(size_t)(row0+8)*Ec + col] = make_float2(v10, v11);
      } else if (mode == 1){
        u16* oh = (w == 0) ? g_Qh : g_Kh;
        u16* ol = (w == 0) ? g_Ql : g_Kl;
        int dd = col & 63;
        int t0 = row0 & (Tc-1), t1 = (row0+8) & (Tc-1);
        float c0 = g_rc[t0*HDc+dd],   s0 = g_rs[t0*HDc+dd];
        float c1 = g_rc[t0*HDc+dd+1], s1 = g_rs[t0*HDc+dd+1];
        float y0 = v00*c0 - v01*s0;
        float y1 = v01*c1 + v00*s1;
        u32 hi, lo; split_pack(y0, y1, hi, lo);
        ((u32*)oh)[((size_t)row0*Ec + col) >> 1] = hi;
        ((u32*)ol)[((size_t)row0*Ec + col) >> 1] = lo;
        float d0 = g_rc[t1*HDc+dd],   e0 = g_rs[t1*HDc+dd];
        float d1 = g_rc[t1*HDc+dd+1], e1 = g_rs[t1*HDc+dd+1];
        float z0 = v10*d0 - v11*e0;
        float z1 = v11*d1 + v10*e1;
        split_pack(z0, z1, hi, lo);
        ((u32*)oh)[((size_t)(row0+8)*Ec + col) >> 1] = hi;
        ((u32*)ol)[((size_t)(row0+8)*Ec + col) >> 1] = lo;
      } else { // mode 2: transposed split V
        int bi0 = row0 >> 11; int t0 = row0 & (Tc-1);
        size_t i0s = (size_t)bi0*Ec*Tc + (size_t)col*Tc + t0;
        u16 h00 = f2bf(v00); g_Vth[i0s]    = h00; g_Vtl[i0s]    = f2bf(v00 - bf2f(h00));
        u16 h01 = f2bf(v01); g_Vth[i0s+Tc] = h01; g_Vtl[i0s+Tc] = f2bf(v01 - bf2f(h01));
        int row1 = row0 + 8;
        int bi1 = row1 >> 11; int t1 = row1 & (Tc-1);
        size_t i1s = (size_t)bi1*Ec*Tc + (size_t)col*Tc + t1;
        u16 h10 = f2bf(v10); g_Vth[i1s]    = h10; g_Vtl[i1s]    = f2bf(v10 - bf2f(h10));
        u16 h11 = f2bf(v11); g_Vth[i1s+Tc] = h11; g_Vtl[i1s+Tc] = f2bf(v11 - bf2f(h11));
      }
    }
  }
}

// ============================================================
// Retention, mma.sync, split-bf16, 8 warps (warp tile 16x32):
//   O[b,h,i,:] = sum_{j>=i} gamma_h^{j-i} (Q_i.K_j/8) V_j
// smem: Q hi/lo (2x4608h), K stages 2x(hi+lo 9216h), V single (hi+lo 9216h)
// total 36864 halves = 73728 B -> 2 blocks/SM of 256 thr = 16 warps/SM.
// grid.y mapped so longest-work blocks (high h, low it) launch first.
// ============================================================
#define RPITCH 72
__global__ void __launch_bounds__(256, 2)
retention_mma(const u16* __restrict__ Qh_, const u16* __restrict__ Ql_,
              const u16* __restrict__ Kh_, const u16* __restrict__ Kl_,
              const u16* __restrict__ Vth, const u16* __restrict__ Vtl,
              float* __restrict__ O)
{
  extern __shared__ u16 sm[];
  int tid = threadIdx.x, lane = tid & 31, wid = tid >> 5;
  int wi = wid >> 1, wj = wid & 1;           // wi 0..3 (16 rows each), wj 0..1 (32 cols)
  int yy = blockIdx.y;
  int h = 15 - (yy >> 1), b = yy & 1;        // longest (h=15) first
  int it = blockIdx.x; int i0 = it*64;

  float lg2;
  { double g = 1.0 - ldexp(1.0, -(5+h)); lg2 = (float)log2(g); }

  // Q tile loads (once)
  {
    #pragma unroll
    for(int tl=0; tl<2; tl++){
      const u16* src = (tl ? Ql_ : Qh_) + (size_t)(b*Tc + i0)*Ec + h*64;
      u16* dst = sm + tl*4608;
      #pragma unroll
      for(int i=0;i<2;i++){
        int c = tid*2 + i;                   // 0..511
        int r = c >> 3, seg = c & 7;
        cp16(smaddr(dst + r*RPITCH + seg*8), src + (size_t)r*Ec + seg*8);
      }
    }
  }
  auto load_K = [&](int s, int j0){
    u16* st = sm + 9216 + s*9216;
    const u16* sK[2] = { Kh_ + (size_t)(b*Tc + j0)*Ec + h*64,
                         Kl_ + (size_t)(b*Tc + j0)*Ec + h*64 };
    #pragma unroll
    for(int tl=0; tl<2; tl++){
      #pragma unroll
      for(int i=0;i<2;i++){
        int c = tid*2 + i;
        int r = c >> 3, seg = c & 7;
        cp16(smaddr(st + tl*4608 + r*RPITCH + seg*8), sK[tl] + (size_t)r*Ec + seg*8);
      }
    }
  };
  auto load_V = [&](int j0){
    u16* st = sm + 27648;
    const u16* sV[2] = { Vth + (size_t)b*Ec*Tc + (size_t)(h*64)*Tc + j0,
                         Vtl + (size_t)b*Ec*Tc + (size_t)(h*64)*Tc + j0 };
    #pragma unroll
    for(int tl=0; tl<2; tl++){
      #pragma unroll
      for(int i=0;i<2;i++){
        int c = tid*2 + i;
        int r = c >> 3, seg = c & 7;
        cp16(smaddr(st + tl*4608 + r*RPITCH + seg*8), sV[tl] + (size_t)r*Tc + seg*8);
      }
    }
  };

  float inv = -lg2;
  int jtEnd = (i0 + 63 + (int)(20.0f/inv)) / 64;
  if (jtEnd > Tc/64 - 1) jtEnd = Tc/64 - 1;

  load_K(0, it*64);   // diagonal K tile
  cpcommit();         // group: K[it]

  float rowF[2], colF[4][2];
  int   ilv[2],  jlv[4][2];
  #pragma unroll
  for(int hf=0; hf<2; hf++){
    int il = wi*16 + (lane >> 2) + hf*8;
    ilv[hf] = il;
    rowF[hf] = exp2f(-(float)il * lg2);
  }
  #pragma unroll
  for(int nj=0; nj<4; nj++)
    #pragma unroll
    for(int cp=0; cp<2; cp++){
      int jl = wj*32 + nj*8 + (lane & 3)*2 + cp;
      jlv[nj][cp] = jl;
      colF[nj][cp] = exp2f((float)jl * lg2);
    }

  float oacc[8][4];
  #pragma unroll
  for(int j=0;j<8;j++)
    #pragma unroll
    for(int k=0;k<4;k++) oacc[j][k]=0.f;

  u16* sQh = sm; u16* sQl = sm + 4608;
  u16* sVh = sm + 27648; u16* sVl = sm + 32256;

  for(int jt = it; jt <= jtEnd; jt++){
    int s = (jt - it) & 1;
    load_V(jt*64); cpcommit();                 // group: V[jt]
    bool havK = (jt + 1 <= jtEnd);
    if (havK){ load_K(s^1, (jt+1)*64); cpcommit(); }   // group: K[jt+1]
    if (havK) cpwait2(); else cpwait1();
    __syncthreads();
    u16 *sKh = sm + 9216 + s*9216, *sKl = sKh + 4608;

    // ---- phase A: S = Q K^T (warp rows wi*16..+16, cols wj*32..+32) ----
    float sacc[4][4];
    #pragma unroll
    for(int j=0;j<4;j++)
      #pragma unroll
      for(int k=0;k<4;k++) sacc[j][k]=0.f;

    #pragma unroll
    for(int ks=0; ks<4; ks++){
      int koff = ks*16;
      u32 qh[4], ql[4];
      {
        int r = wi*16 + (lane & 15);
        int cc = koff + (lane >> 4)*8;
        ldsm4(qh[0],qh[1],qh[2],qh[3], smaddr(sQh + r*RPITCH + cc));
        ldsm4(ql[0],ql[1],ql[2],ql[3], smaddr(sQl + r*RPITCH + cc));
      }
      u32 kh[4][2], kl[4][2];
      #pragma unroll
      for(int np=0; np<2; np++){
        int r = wj*32 + np*16 + (lane & 7) + ((lane >> 4)*8);
        int cc = koff + ((lane >> 3) & 1)*8;
        u32 r0,r1,r2,r3;
        ldsm4(r0,r1,r2,r3, smaddr(sKh + r*RPITCH + cc));
        kh[np*2][0]=r0; kh[np*2][1]=r1; kh[np*2+1][0]=r2; kh[np*2+1][1]=r3;
        ldsm4(r0,r1,r2,r3, smaddr(sKl + r*RPITCH + cc));
        kl[np*2][0]=r0; kl[np*2][1]=r1; kl[np*2+1][0]=r2; kl[np*2+1][1]=r3;
      }
      #pragma unroll
      for(int nj=0; nj<4; nj++){
        mma_bf(sacc[nj], qh, kh[nj][0], kh[nj][1]);
        mma_bf(sacc[nj], qh, kl[nj][0], kl[nj][1]);
        mma_bf(sacc[nj], ql, kh[nj][0], kh[nj][1]);
      }
    }

    // ---- decay + mask + 1/8 ----
    float base = exp2f((float)((jt-it)*64) * lg2) * 0.125f;
    bool diag = (jt == it);
    #pragma unroll
    for(int nj=0; nj<4; nj++){
      float f00 = base*rowF[0]*colF[nj][0];
      float f01 = base*rowF[0]*colF[nj][1];
      float f10 = base*rowF[1]*colF[nj][0];
      float f11 = base*rowF[1]*colF[nj][1];
      if (diag){
        if (jlv[nj][0] < ilv[0]) f00 = 0.f;
        if (jlv[nj][1] < ilv[0]) f01 = 0.f;
        if (jlv[nj][0] < ilv[1]) f10 = 0.f;
        if (jlv[nj][1] < ilv[1]) f11 = 0.f;
      }
      sacc[nj][0] *= f00; sacc[nj][1] *= f01;
      sacc[nj][2] *= f10; sacc[nj][3] *= f11;
    }

    // need V[jt] for phase B; allow K[jt+1] pending
    if (havK) cpwait1(); else cpwait0();
    __syncthreads();

    // ---- phase B: O += S V (register repack of S to A-frags) ----
    #pragma unroll
    for(int kt=0; kt<2; kt++){
      int koff = wj*32 + kt*16;
      u32 sh[4], sl[4];
      split_pack(sacc[2*kt][0],   sacc[2*kt][1],   sh[0], sl[0]);
      split_pack(sacc[2*kt][2],   sacc[2*kt][3],   sh[1], sl[1]);
      split_pack(sacc[2*kt+1][0], sacc[2*kt+1][1], sh[2], sl[2]);
      split_pack(sacc[2*kt+1][2], sacc[2*kt+1][3], sh[3], sl[3]);
      u32 vh[8][2], vl[8][2];
      #pragma unroll
      for(int np=0; np<4; np++){
        int r = np*16 + (lane & 7) + ((lane >> 4)*8);
        int cc = koff + ((lane >> 3) & 1)*8;
        u32 r0,r1,r2,r3;
        ldsm4(r0,r1,r2,r3, smaddr(sVh + r*RPITCH + cc));
        vh[np*2][0]=r0; vh[np*2][1]=r1; vh[np*2+1][0]=r2; vh[np*2+1][1]=r3;
        ldsm4(r0,r1,r2,r3, smaddr(sVl + r*RPITCH + cc));
        vl[np*2][0]=r0; vl[np*2][1]=r1; vl[np*2+1][0]=r2; vl[np*2+1][1]=r3;
      }
      #pragma unroll
      for(int nd=0; nd<8; nd++){
        mma_bf(oacc[nd], sh, vh[nd][0], vh[nd][1]);
        mma_bf(oacc[nd], sh, vl[nd][0], vl[nd][1]);
        mma_bf(oacc[nd], sl, vh[nd][0], vh[nd][1]);
      }
    }
    __syncthreads();   // V buffer free for next iter
  }
  cpwait0();

  // ---- cross-warp combine over wj halves (alias over Q area) ----
  float* Op = (float*)sm;     // 64 x pitch66
  if (wj == 0){
    #pragma unroll
    for(int nd=0; nd<8; nd++){
      int row = wi*16 + (lane >> 2);
      int d   = nd*8 + (lane & 3)*2;
      Op[row*66 + d]     = oacc[nd][0];
      Op[row*66 + d + 1] = oacc[nd][1];
      Op[(row+8)*66 + d]     = oacc[nd][2];
      Op[(row+8)*66 + d + 1] = oacc[nd][3];
    }
  }
  __syncthreads();
  if (wj == 1){
    #pragma unroll
    for(int nd=0; nd<8; nd++){
      int row = wi*16 + (lane >> 2);
      int d   = nd*8 + (lane & 3)*2;
      float a0 = oacc[nd][0] + Op[row*66 + d];
      float a1 = oacc[nd][1] + Op[row*66 + d + 1];
      float a2 = oacc[nd][2] + Op[(row+8)*66 + d];
      float a3 = oacc[nd][3] + Op[(row+8)*66 + d + 1];
      size_t r0 = (size_t)(b*Tc + i0 + row)*Ec + h*64 + d;
      size_t r1 = (size_t)(b*Tc + i0 + row + 8)*Ec + h*64 + d;
      *(float2*)&O[r0] = make_float2(a0, a1);
      *(float2*)&O[r1] = make_float2(a2, a3);
    }
  }
}

// ============================================================
// GroupNorm stats, 2-stage, fp64 accumulation
// ============================================================
__global__ void gn_part_kernel(const float* __restrict__ O){
  int g = blockIdx.x;
  int c = blockIdx.y;
  int b = g >> 4, h = g & 15, tid = threadIdx.x;
  int tbase = c * (Tc/8);
  double s = 0.0, s2 = 0.0;
  for(int idx = tid; idx < (Tc/8)*HDc/4; idx += 256){
    int t = tbase + (idx >> 4), d4 = (idx & 15)*4;
    float4 v = *(const float4*)&O[(size_t)(b*Tc + t)*Ec + h*64 + d4];
    s += (double)v.x + (double)v.y + (double)v.z + (double)v.w;
    s2 += (double)v.x*v.x + (double)v.y*v.y + (double)v.z*v.z + (double)v.w*v.w;
  }
  __shared__ double rs[256], rs2[256];
  rs[tid] = s; rs2[tid] = s2;
  __syncthreads();
  for(int off=128; off>0; off>>=1){
    if(tid < off){ rs[tid]+=rs[tid+off]; rs2[tid]+=rs2[tid+off]; }
    __syncthreads();
  }
  if(tid == 0){
    g_part[(g*8 + c)*2 + 0] = rs[0];
    g_part[(g*8 + c)*2 + 1] = rs2[0];
  }
}
__global__ void gn_final_kernel(){
  int g = threadIdx.x;
  if(g >= Bc*Hc) return;
  double s=0.0, s2=0.0;
  for(int c=0;c<8;c++){ s += g_part[(g*8+c)*2]; s2 += g_part[(g*8+c)*2+1]; }
  double N = (double)(Tc*HDc);
  double mean = s/N;
  double var  = s2/N - mean*mean;
  g_stats[g*2+0] = (float)mean;
  g_stats[g*2+1] = (float)(1.0 / sqrt(var + 1e-5));
}

// ============================================================
// Y = silu(G) * groupnorm(O)  -> split bf16, 4-wide
// ============================================================
__global__ void gate_norm4_kernel(const float* __restrict__ O, const float* __restrict__ G,
                                  const float* __restrict__ w, const float* __restrict__ bb,
                                  u16* __restrict__ Yh, u16* __restrict__ Yl)
{
  int i4 = blockIdx.x*blockDim.x + threadIdx.x;
  if(i4 >= Mc*Ec/4) return;
  int idx = i4*4;
  int row = idx >> 10, e = idx & 1023;
  int b = row >> 11;
  int g = b*Hc + (e >> 6);
  float mean = g_stats[g*2+0], rstd = g_stats[g*2+1];
  float4 ov = ((const float4*)O)[i4];
  float4 gv = ((const float4*)G)[i4];
  float4 wv = *(const float4*)&w[e];
  float4 bv = *(const float4*)&bb[e];
  float o0 = (ov.x - mean)*rstd*wv.x + bv.x;
  float o1 = (ov.y - mean)*rstd*wv.y + bv.y;
  float o2 = (ov.z - mean)*rstd*wv.z + bv.z;
  float o3 = (ov.w - mean)*rstd*wv.w + bv.w;
  float y0 = (gv.x / (1.f + __expf(-gv.x))) * o0;
  float y1 = (gv.y / (1.f + __expf(-gv.y))) * o1;
  float y2 = (gv.z / (1.f + __expf(-gv.z))) * o2;
  float y3 = (gv.w / (1.f + __expf(-gv.w))) * o3;
  u32 h01,l01,h23,l23;
  split_pack(y0, y1, h01, l01);
  split_pack(y2, y3, h23, l23);
  uint2 hv = make_uint2(h01, h23), lv = make_uint2(l01, l23);
  ((uint2*)Yh)[i4] = hv;
  ((uint2*)Yl)[i4] = lv;
}

// ============================================================
extern "C" void kernel_launch(void* const* d_in, const int* in_sizes, int n_in,
                              void* d_out, int out_size)
{
  const float* x   = (const float*)d_in[0];
  const float* Wq  = (const float*)d_in[1];
  const float* bq  = (const float*)d_in[2];
  const float* Wk  = (const float*)d_in[3];
  const float* bk  = (const float*)d_in[4];
  const float* Wv  = (const float*)d_in[5];
  const float* bv  = (const float*)d_in[6];
  const float* Wg  = (const float*)d_in[7];
  const float* bg  = (const float*)d_in[8];
  const float* Wo  = (const float*)d_in[9];
  const float* bo  = (const float*)d_in[10];
  const float* gnw = (const float*)d_in[11];
  const float* gnb = (const float*)d_in[12];
  float* out = (float*)d_out;

  u16 *xh,*xl,*Qh,*Ql,*Kh,*Kl,*Vth,*Vtl,*Yh,*Yl;
  float *Gp,*Op;
  cudaGetSymbolAddress((void**)&xh, g_xh);   cudaGetSymbolAddress((void**)&xl, g_xl);
  cudaGetSymbolAddress((void**)&Qh, g_Qh);   cudaGetSymbolAddress((void**)&Ql, g_Ql);
  cudaGetSymbolAddress((void**)&Kh, g_Kh);   cudaGetSymbolAddress((void**)&Kl, g_Kl);
  cudaGetSymbolAddress((void**)&Vth, g_Vth); cudaGetSymbolAddress((void**)&Vtl, g_Vtl);
  cudaGetSymbolAddress((void**)&Yh, g_Yh);   cudaGetSymbolAddress((void**)&Yl, g_Yl);
  cudaGetSymbolAddress((void**)&Gp, g_G);    cudaGetSymbolAddress((void**)&Op, g_O);

  // launch order puts gemm_bs at #4 and retention at #5 for ncu capture
  convertW4_kernel<<<dim3((Ec*Ec/4 + 255)/256, 5), 256>>>(Wq, Wk, Wv, Wg, Wo); // 1
  convert4_kernel<<<(Mc*Ec/4 + 255)/256, 256>>>(x, xh, xl, Mc*Ec/4);           // 2
  rope_table_kernel<<<(Tc*HDc + 255)/256, 256>>>();                            // 3

  size_t gsm = 81920;
  cudaFuncSetAttribute(gemm_bs, cudaFuncAttributeMaxDynamicSharedMemorySize, (int)gsm);
  // batched projections: z -> {Q, K, V, G}                                    // 4
  gemm_bs<<<dim3(Ec/128, Mc/128, 4), 256, gsm>>>(xh, xl, bq, bk, bv, bg, 0, nullptr);

  size_t rsm = 73728;
  cudaFuncSetAttribute(retention_mma, cudaFuncAttributeMaxDynamicSharedMemorySize, (int)rsm);
  retention_mma<<<dim3(Tc/64, Bc*Hc), 256, rsm>>>(Qh, Ql, Kh, Kl, Vth, Vtl, Op);  // 5

  gn_part_kernel<<<dim3(Bc*Hc, 8), 256>>>(Op);                                 // 6
  gn_final_kernel<<<1, 32>>>();                                                // 7

  gate_norm4_kernel<<<(Mc*Ec/4 + 255)/256, 256>>>(Op, Gp, gnw, gnb, Yh, Yl);   // 8

  // final: out = Y @ Wo^T + bo   (w = 4)                                      // 9
  gemm_bs<<<dim3(Ec/128, Mc/128, 1), 256, gsm>>>(Yh, Yl, bo, bo, bo, bo, 4, out);
}

// round 12
// speedup vs baseline: 2.7746x; 1.0038x over previous
#include <cuda_runtime.h>
#include <cuda_bf16.h>
#include <math.h>
#include <stdint.h>

// Problem dims (fixed)
#define Bc 2
#define Tc 2048
#define Ec 1024
#define Hc 16
#define HDc 64
#define Mc (Bc*Tc)   // 4096

typedef unsigned short u16;
typedef unsigned int   u32;

// -------- scratch (device globals; no allocation allowed) --------
__device__ u16 g_xh[Mc*Ec], g_xl[Mc*Ec];
__device__ u16 g_Wh[5*Ec*Ec], g_Wl[5*Ec*Ec];   // q,k,v,g,o packed
__device__ u16 g_Qh[Mc*Ec], g_Ql[Mc*Ec];
__device__ u16 g_Kh[Mc*Ec], g_Kl[Mc*Ec];
__device__ u16 g_Vth[Mc*Ec], g_Vtl[Mc*Ec];     // V transposed: [b][e][t]
__device__ u16 g_Yh[Mc*Ec], g_Yl[Mc*Ec];
__device__ float g_G[Mc*Ec];
__device__ float g_O[Mc*Ec];
__device__ double g_part[Bc*Hc*8*2];
__device__ float g_stats[Bc*Hc*2];
__device__ float g_rc[Tc*HDc], g_rs[Tc*HDc];

// ------------------- helpers -------------------
__device__ __forceinline__ u32 smaddr(const void* p){ return (u32)__cvta_generic_to_shared(p); }
__device__ __forceinline__ void cp16(u32 d, const void* s){
  asm volatile("cp.async.cg.shared.global [%0], [%1], 16;\n"::"r"(d),"l"(s));
}
__device__ __forceinline__ void cpcommit(){ asm volatile("cp.async.commit_group;\n"); }
__device__ __forceinline__ void cpwait0(){ asm volatile("cp.async.wait_group 0;\n"); }
__device__ __forceinline__ void cpwait1(){ asm volatile("cp.async.wait_group 1;\n"); }
__device__ __forceinline__ void cpwait2(){ asm volatile("cp.async.wait_group 2;\n"); }
__device__ __forceinline__ void ldsm4(u32&r0,u32&r1,u32&r2,u32&r3,u32 a){
  asm volatile("ldmatrix.sync.aligned.m8n8.x4.shared.b16 {%0,%1,%2,%3},[%4];\n"
    :"=r"(r0),"=r"(r1),"=r"(r2),"=r"(r3):"r"(a));
}
__device__ __forceinline__ void mma_bf(float* c, const u32* a, u32 b0, u32 b1){
  asm volatile("mma.sync.aligned.m16n8k16.row.col.f32.bf16.bf16.f32 "
    "{%0,%1,%2,%3},{%4,%5,%6,%7},{%8,%9},{%0,%1,%2,%3};\n"
    :"+f"(c[0]),"+f"(c[1]),"+f"(c[2]),"+f"(c[3])
    :"r"(a[0]),"r"(a[1]),"r"(a[2]),"r"(a[3]),"r"(b0),"r"(b1));
}
__device__ __forceinline__ u16 f2bf(float x){
  __nv_bfloat16 h = __float2bfloat16_rn(x);
  return *reinterpret_cast<u16*>(&h);
}
__device__ __forceinline__ float bf2f(u16 u){
  __nv_bfloat16 h; *reinterpret_cast<u16*>(&h)=u; return __bfloat162float(h);
}
__device__ __forceinline__ void split_pack(float a, float b, u32& hi, u32& lo){
  u16 ha = f2bf(a), hb = f2bf(b);
  u16 la = f2bf(a - bf2f(ha)), lb = f2bf(b - bf2f(hb));
  hi = (u32)ha | ((u32)hb << 16);
  lo = (u32)la | ((u32)lb << 16);
}

// ------------------- rope table -------------------
__global__ void rope_table_kernel() {
  int idx = blockIdx.x * blockDim.x + threadIdx.x;
  if (idx >= Tc*HDc) return;
  int t = idx / HDc;
  int dd = idx % HDc;
  double f = pow(10000.0, -(double)(dd & 31) / 32.0);
  double th = (double)t * f;
  g_rc[idx] = (float)cos(th);
  g_rs[idx] = (float)sin(th);
}

// ------------------- fp32 -> split bf16, 8-wide -------------------
__global__ void convert8_kernel(const float* __restrict__ in, u16* __restrict__ h,
                                u16* __restrict__ l, int n8){
  int i = blockIdx.x*blockDim.x + threadIdx.x;
  if(i >= n8) return;
  float4 x0 = ((const float4*)in)[i*2];
  float4 x1 = ((const float4*)in)[i*2+1];
  u16 ha[8], la[8];
  float xs[8] = {x0.x,x0.y,x0.z,x0.w,x1.x,x1.y,x1.z,x1.w};
  #pragma unroll
  for(int k=0;k<8;k++){ ha[k]=f2bf(xs[k]); la[k]=f2bf(xs[k]-bf2f(ha[k])); }
  uint4 hv, lv;
  hv.x=(u32)ha[0]|((u32)ha[1]<<16); hv.y=(u32)ha[2]|((u32)ha[3]<<16);
  hv.z=(u32)ha[4]|((u32)ha[5]<<16); hv.w=(u32)ha[6]|((u32)ha[7]<<16);
  lv.x=(u32)la[0]|((u32)la[1]<<16); lv.y=(u32)la[2]|((u32)la[3]<<16);
  lv.z=(u32)la[4]|((u32)la[5]<<16); lv.w=(u32)la[6]|((u32)la[7]<<16);
  ((uint4*)h)[i] = hv;
  ((uint4*)l)[i] = lv;
}
__global__ void convertW8_kernel(const float* __restrict__ w0, const float* __restrict__ w1,
                                 const float* __restrict__ w2, const float* __restrict__ w3,
                                 const float* __restrict__ w4){
  int z = blockIdx.y;
  const float* src = (z==0)?w0:(z==1)?w1:(z==2)?w2:(z==3)?w3:w4;
  int i = blockIdx.x*blockDim.x + threadIdx.x;
  if(i >= Ec*Ec/8) return;
  float4 x0 = ((const float4*)src)[i*2];
  float4 x1 = ((const float4*)src)[i*2+1];
  u16 ha[8], la[8];
  float xs[8] = {x0.x,x0.y,x0.z,x0.w,x1.x,x1.y,x1.z,x1.w};
  #pragma unroll
  for(int k=0;k<8;k++){ ha[k]=f2bf(xs[k]); la[k]=f2bf(xs[k]-bf2f(ha[k])); }
  uint4 hv, lv;
  hv.x=(u32)ha[0]|((u32)ha[1]<<16); hv.y=(u32)ha[2]|((u32)ha[3]<<16);
  hv.z=(u32)ha[4]|((u32)ha[5]<<16); hv.w=(u32)ha[6]|((u32)ha[7]<<16);
  lv.x=(u32)la[0]|((u32)la[1]<<16); lv.y=(u32)la[2]|((u32)la[3]<<16);
  lv.z=(u32)la[4]|((u32)la[5]<<16); lv.w=(u32)la[6]|((u32)la[7]<<16);
  size_t base = (size_t)z*(Ec*Ec/8);
  ((uint4*)g_Wh)[base + i] = hv;
  ((uint4*)g_Wl)[base + i] = lv;
}

// ============================================================
// Split-bf16 tensor-core GEMM: C[m,n] = sum_k A[m,k]*W[n,k] + bias[n]
// tiles 128x128x32, 256 threads (8 warps, 2x4), warp tile 64x32.
// w = zoff + blockIdx.z selects weight slice + epilogue:
//   w=0: Q (bias+RoPE -> g_Qh/g_Ql)   w=1: K (bias+RoPE -> g_Kh/g_Kl)
//   w=2: V (bias -> transposed g_Vth/g_Vtl, smem-restaged)
//   w=3: G (bias -> g_G fp32)         w=4: O (bias -> outf fp32)
// ============================================================
#define GPITCH 40   // halves per smem row (32 data + 8 pad) -> conflict-free
#define VP 136      // V-restage smem pitch in halves (272B = 17*16B)
__global__ void __launch_bounds__(256, 2)
gemm_bs(const u16* __restrict__ Ah, const u16* __restrict__ Al,
        const float* __restrict__ b0, const float* __restrict__ b1,
        const float* __restrict__ b2, const float* __restrict__ b3,
        int zoff, float* __restrict__ outf)
{
  extern __shared__ u16 sm[];
  const int K = Ec;
  int tid = threadIdx.x, lane = tid & 31, wid = tid >> 5;
  int bm = blockIdx.y * 128, bn = blockIdx.x * 128;
  int wm = wid >> 2, wn = wid & 3;
  int z = blockIdx.z, w = zoff + z;
  const u16* Bh = g_Wh + (size_t)w*Ec*Ec;
  const u16* Bl = g_Wl + (size_t)w*Ec*Ec;
  const float* bias = (z==0)?b0:(z==1)?b1:(z==2)?b2:b3;

  float acc[4][4][4];
  #pragma unroll
  for(int i=0;i<4;i++)
    #pragma unroll
    for(int j=0;j<4;j++)
      #pragma unroll
      for(int k=0;k<4;k++) acc[i][j][k] = 0.f;

  auto load_stage = [&](int s, int k0){
    u16* st = sm + s*20480;
    const u16* srcs[4] = { Ah + (size_t)bm*K + k0, Al + (size_t)bm*K + k0,
                           Bh + (size_t)bn*K + k0, Bl + (size_t)bn*K + k0 };
    #pragma unroll
    for(int tl=0; tl<4; tl++){
      #pragma unroll
      for(int i=0;i<2;i++){
        int c = tid*2 + i;          // 0..511
        int r = c >> 2, seg = c & 3;
        cp16(smaddr(st + tl*5120 + r*GPITCH + seg*8),
             srcs[tl] + (size_t)r*K + seg*8);
      }
    }
  };

  load_stage(0, 0); cpcommit();
  const int NK = K/32;   // 32
  for(int kt=0; kt<NK; kt++){
    if(kt+1 < NK) load_stage((kt+1)&1, (kt+1)*32);
    cpcommit(); cpwait1(); __syncthreads();
    u16* st  = sm + (kt&1)*20480;
    u16* sAh = st;          u16* sAl = st + 5120;
    u16* sBh = st + 10240;  u16* sBl = st + 15360;

    #pragma unroll
    for(int ks=0; ks<2; ks++){
      int koff = ks*16;
      u32 ah[4][4], al[4][4];
      #pragma unroll
      for(int mi=0; mi<4; mi++){
        int r = wm*64 + mi*16 + (lane & 15);
        int cc = koff + (lane >> 4)*8;
        ldsm4(ah[mi][0],ah[mi][1],ah[mi][2],ah[mi][3], smaddr(sAh + r*GPITCH + cc));
        ldsm4(al[mi][0],al[mi][1],al[mi][2],al[mi][3], smaddr(sAl + r*GPITCH + cc));
      }
      u32 bh[4][2], bl[4][2];
      #pragma unroll
      for(int np=0; np<2; np++){
        int r = wn*32 + np*16 + (lane & 7) + ((lane >> 4)*8);
        int cc = koff + ((lane >> 3) & 1)*8;
        u32 r0,r1,r2,r3;
        ldsm4(r0,r1,r2,r3, smaddr(sBh + r*GPITCH + cc));
        bh[np*2][0]=r0; bh[np*2][1]=r1; bh[np*2+1][0]=r2; bh[np*2+1][1]=r3;
        ldsm4(r0,r1,r2,r3, smaddr(sBl + r*GPITCH + cc));
        bl[np*2][0]=r0; bl[np*2][1]=r1; bl[np*2+1][0]=r2; bl[np*2+1][1]=r3;
      }
      // 3 passes: dependency chains per accumulator are 16 instructions apart
      #pragma unroll
      for(int mi=0; mi<4; mi++)
        #pragma unroll
        for(int nj=0; nj<4; nj++)
          mma_bf(acc[mi][nj], ah[mi], bh[nj][0], bh[nj][1]);
      #pragma unroll
      for(int mi=0; mi<4; mi++)
        #pragma unroll
        for(int nj=0; nj<4; nj++)
          mma_bf(acc[mi][nj], ah[mi], bl[nj][0], bl[nj][1]);
      #pragma unroll
      for(int mi=0; mi<4; mi++)
        #pragma unroll
        for(int nj=0; nj<4; nj++)
          mma_bf(acc[mi][nj], al[mi], bh[nj][0], bh[nj][1]);
    }
    __syncthreads();
  }
  cpwait0();

  // epilogue
  int mode = (w < 2) ? 1 : ((w == 2) ? 2 : 0);
  if (mode == 2){
    // restage V tile through smem -> coalesced transposed stores
    __syncthreads();   // all warps done reading stage smem
    u16* svh = sm;                 // [col 0..127][row 0..127], pitch VP
    u16* svl = sm + 128*VP;
    #pragma unroll
    for(int mi=0; mi<4; mi++){
      int r0l = wm*64 + mi*16 + (lane >> 2);
      #pragma unroll
      for(int nj=0; nj<4; nj++){
        int cl = wn*32 + nj*8 + (lane & 3)*2;
        int colg = bn + cl;
        float bv0 = bias[colg], bv1 = bias[colg+1];
        float v00 = acc[mi][nj][0] + bv0, v01 = acc[mi][nj][1] + bv1;
        float v10 = acc[mi][nj][2] + bv0, v11 = acc[mi][nj][3] + bv1;
        u16 h00=f2bf(v00), h01=f2bf(v01), h10=f2bf(v10), h11=f2bf(v11);
        svh[cl*VP + r0l]         = h00;  svl[cl*VP + r0l]         = f2bf(v00 - bf2f(h00));
        svh[(cl+1)*VP + r0l]     = h01;  svl[(cl+1)*VP + r0l]     = f2bf(v01 - bf2f(h01));
        svh[cl*VP + r0l + 8]     = h10;  svl[cl*VP + r0l + 8]     = f2bf(v10 - bf2f(h10));
        svh[(cl+1)*VP + r0l + 8] = h11;  svl[(cl+1)*VP + r0l + 8] = f2bf(v11 - bf2f(h11));
      }
    }
    __syncthreads();
    int bi = bm >> 11;
    int tbase = bm & (Tc-1);
    int colIdx = tid >> 1, half = tid & 1;   // 128 cols x 2 halves of 64
    size_t gbase = (size_t)bi*Ec*Tc + (size_t)(bn + colIdx)*Tc + tbase + half*64;
    const uint4* sh = (const uint4*)(svh + colIdx*VP + half*64);
    const uint4* sl = (const uint4*)(svl + colIdx*VP + half*64);
    uint4* dh = (uint4*)(g_Vth + gbase);
    uint4* dl = (uint4*)(g_Vtl + gbase);
    #pragma unroll
    for(int i=0;i<8;i++) dh[i] = sh[i];
    #pragma unroll
    for(int i=0;i<8;i++) dl[i] = sl[i];
  } else {
    #pragma unroll
    for(int mi=0; mi<4; mi++){
      int row0 = bm + wm*64 + mi*16 + (lane >> 2);
      #pragma unroll
      for(int nj=0; nj<4; nj++){
        int col = bn + wn*32 + nj*8 + (lane & 3)*2;
        float bv0 = bias[col], bv1 = bias[col+1];
        float v00 = acc[mi][nj][0] + bv0, v01 = acc[mi][nj][1] + bv1;
        float v10 = acc[mi][nj][2] + bv0, v11 = acc[mi][nj][3] + bv1;
        if (mode == 0){
          float* dst = (w == 3) ? g_G : outf;
          *(float2*)&dst[(size_t)row0*Ec + col]     = make_float2(v00, v01);
          *(float2*)&dst[(size_t)(row0+8)*Ec + col] = make_float2(v10, v11);
        } else { // mode 1: RoPE + split
          u16* oh = (w == 0) ? g_Qh : g_Kh;
          u16* ol = (w == 0) ? g_Ql : g_Kl;
          int dd = col & 63;
          int t0 = row0 & (Tc-1), t1 = (row0+8) & (Tc-1);
          float c0 = g_rc[t0*HDc+dd],   s0 = g_rs[t0*HDc+dd];
          float c1 = g_rc[t0*HDc+dd+1], s1 = g_rs[t0*HDc+dd+1];
          float y0 = v00*c0 - v01*s0;
          float y1 = v01*c1 + v00*s1;
          u32 hi, lo; split_pack(y0, y1, hi, lo);
          ((u32*)oh)[((size_t)row0*Ec + col) >> 1] = hi;
          ((u32*)ol)[((size_t)row0*Ec + col) >> 1] = lo;
          float d0 = g_rc[t1*HDc+dd],   e0 = g_rs[t1*HDc+dd];
          float d1 = g_rc[t1*HDc+dd+1], e1 = g_rs[t1*HDc+dd+1];
          float z0 = v10*d0 - v11*e0;
          float z1 = v11*d1 + v10*e1;
          split_pack(z0, z1, hi, lo);
          ((u32*)oh)[((size_t)(row0+8)*Ec + col) >> 1] = hi;
          ((u32*)ol)[((size_t)(row0+8)*Ec + col) >> 1] = lo;
        }
      }
    }
  }
}

// ============================================================
// Retention, mma.sync, split-bf16, 8 warps (warp tile 16x32):
//   O[b,h,i,:] = sum_{j>=i} gamma_h^{j-i} (Q_i.K_j/8) V_j
// smem: Q hi/lo (2x4608h), K stages 2x(hi+lo 9216h), V single (hi+lo 9216h)
// total 36864 halves = 73728 B -> 2 blocks/SM of 256 thr = 16 warps/SM.
// grid.y mapped so longest-work blocks (high h, low it) launch first.
// ============================================================
#define RPITCH 72
__global__ void __launch_bounds__(256, 2)
retention_mma(const u16* __restrict__ Qh_, const u16* __restrict__ Ql_,
              const u16* __restrict__ Kh_, const u16* __restrict__ Kl_,
              const u16* __restrict__ Vth, const u16* __restrict__ Vtl,
              float* __restrict__ O)
{
  extern __shared__ u16 sm[];
  int tid = threadIdx.x, lane = tid & 31, wid = tid >> 5;
  int wi = wid >> 1, wj = wid & 1;           // wi 0..3 (16 rows each), wj 0..1 (32 cols)
  int yy = blockIdx.y;
  int h = 15 - (yy >> 1), b = yy & 1;        // longest (h=15) first
  int it = blockIdx.x; int i0 = it*64;

  float lg2;
  { double g = 1.0 - ldexp(1.0, -(5+h)); lg2 = (float)log2(g); }

  // Q tile loads (once)
  {
    #pragma unroll
    for(int tl=0; tl<2; tl++){
      const u16* src = (tl ? Ql_ : Qh_) + (size_t)(b*Tc + i0)*Ec + h*64;
      u16* dst = sm + tl*4608;
      #pragma unroll
      for(int i=0;i<2;i++){
        int c = tid*2 + i;                   // 0..511
        int r = c >> 3, seg = c & 7;
        cp16(smaddr(dst + r*RPITCH + seg*8), src + (size_t)r*Ec + seg*8);
      }
    }
  }
  auto load_K = [&](int s, int j0){
    u16* st = sm + 9216 + s*9216;
    const u16* sK[2] = { Kh_ + (size_t)(b*Tc + j0)*Ec + h*64,
                         Kl_ + (size_t)(b*Tc + j0)*Ec + h*64 };
    #pragma unroll
    for(int tl=0; tl<2; tl++){
      #pragma unroll
      for(int i=0;i<2;i++){
        int c = tid*2 + i;
        int r = c >> 3, seg = c & 7;
        cp16(smaddr(st + tl*4608 + r*RPITCH + seg*8), sK[tl] + (size_t)r*Ec + seg*8);
      }
    }
  };
  auto load_V = [&](int j0){
    u16* st = sm + 27648;
    const u16* sV[2] = { Vth + (size_t)b*Ec*Tc + (size_t)(h*64)*Tc + j0,
                         Vtl + (size_t)b*Ec*Tc + (size_t)(h*64)*Tc + j0 };
    #pragma unroll
    for(int tl=0; tl<2; tl++){
      #pragma unroll
      for(int i=0;i<2;i++){
        int c = tid*2 + i;
        int r = c >> 3, seg = c & 7;
        cp16(smaddr(st + tl*4608 + r*RPITCH + seg*8), sV[tl] + (size_t)r*Tc + seg*8);
      }
    }
  };

  float inv = -lg2;
  int jtEnd = (i0 + 63 + (int)(20.0f/inv)) / 64;
  if (jtEnd > Tc/64 - 1) jtEnd = Tc/64 - 1;

  load_K(0, it*64);   // diagonal K tile
  cpcommit();         // group: K[it]

  float rowF[2], colF[4][2];
  int   ilv[2],  jlv[4][2];
  #pragma unroll
  for(int hf=0; hf<2; hf++){
    int il = wi*16 + (lane >> 2) + hf*8;
    ilv[hf] = il;
    rowF[hf] = exp2f(-(float)il * lg2);
  }
  #pragma unroll
  for(int nj=0; nj<4; nj++)
    #pragma unroll
    for(int cp=0; cp<2; cp++){
      int jl = wj*32 + nj*8 + (lane & 3)*2 + cp;
      jlv[nj][cp] = jl;
      colF[nj][cp] = exp2f((float)jl * lg2);
    }

  float oacc[8][4];
  #pragma unroll
  for(int j=0;j<8;j++)
    #pragma unroll
    for(int k=0;k<4;k++) oacc[j][k]=0.f;

  u16* sQh = sm; u16* sQl = sm + 4608;
  u16* sVh = sm + 27648; u16* sVl = sm + 32256;

  for(int jt = it; jt <= jtEnd; jt++){
    int s = (jt - it) & 1;
    load_V(jt*64); cpcommit();                 // group: V[jt]
    bool havK = (jt + 1 <= jtEnd);
    if (havK){ load_K(s^1, (jt+1)*64); cpcommit(); }   // group: K[jt+1]
    if (havK) cpwait2(); else cpwait1();
    __syncthreads();
    u16 *sKh = sm + 9216 + s*9216, *sKl = sKh + 4608;

    // ---- phase A: S = Q K^T (warp rows wi*16..+16, cols wj*32..+32) ----
    float sacc[4][4];
    #pragma unroll
    for(int j=0;j<4;j++)
      #pragma unroll
      for(int k=0;k<4;k++) sacc[j][k]=0.f;

    #pragma unroll
    for(int ks=0; ks<4; ks++){
      int koff = ks*16;
      u32 qh[4], ql[4];
      {
        int r = wi*16 + (lane & 15);
        int cc = koff + (lane >> 4)*8;
        ldsm4(qh[0],qh[1],qh[2],qh[3], smaddr(sQh + r*RPITCH + cc));
        ldsm4(ql[0],ql[1],ql[2],ql[3], smaddr(sQl + r*RPITCH + cc));
      }
      u32 kh[4][2], kl[4][2];
      #pragma unroll
      for(int np=0; np<2; np++){
        int r = wj*32 + np*16 + (lane & 7) + ((lane >> 4)*8);
        int cc = koff + ((lane >> 3) & 1)*8;
        u32 r0,r1,r2,r3;
        ldsm4(r0,r1,r2,r3, smaddr(sKh + r*RPITCH + cc));
        kh[np*2][0]=r0; kh[np*2][1]=r1; kh[np*2+1][0]=r2; kh[np*2+1][1]=r3;
        ldsm4(r0,r1,r2,r3, smaddr(sKl + r*RPITCH + cc));
        kl[np*2][0]=r0; kl[np*2][1]=r1; kl[np*2+1][0]=r2; kl[np*2+1][1]=r3;
      }
      // 3 passes to decouple accumulator chains
      #pragma unroll
      for(int nj=0; nj<4; nj++) mma_bf(sacc[nj], qh, kh[nj][0], kh[nj][1]);
      #pragma unroll
      for(int nj=0; nj<4; nj++) mma_bf(sacc[nj], qh, kl[nj][0], kl[nj][1]);
      #pragma unroll
      for(int nj=0; nj<4; nj++) mma_bf(sacc[nj], ql, kh[nj][0], kh[nj][1]);
    }

    // ---- decay + mask + 1/8 ----
    float base = exp2f((float)((jt-it)*64) * lg2) * 0.125f;
    bool diag = (jt == it);
    #pragma unroll
    for(int nj=0; nj<4; nj++){
      float f00 = base*rowF[0]*colF[nj][0];
      float f01 = base*rowF[0]*colF[nj][1];
      float f10 = base*rowF[1]*colF[nj][0];
      float f11 = base*rowF[1]*colF[nj][1];
      if (diag){
        if (jlv[nj][0] < ilv[0]) f00 = 0.f;
        if (jlv[nj][1] < ilv[0]) f01 = 0.f;
        if (jlv[nj][0] < ilv[1]) f10 = 0.f;
        if (jlv[nj][1] < ilv[1]) f11 = 0.f;
      }
      sacc[nj][0] *= f00; sacc[nj][1] *= f01;
      sacc[nj][2] *= f10; sacc[nj][3] *= f11;
    }

    // need V[jt] for phase B; allow K[jt+1] pending
    if (havK) cpwait1(); else cpwait0();
    __syncthreads();

    // ---- phase B: O += S V (register repack of S to A-frags) ----
    #pragma unroll
    for(int kt=0; kt<2; kt++){
      int koff = wj*32 + kt*16;
      u32 sh[4], sl[4];
      split_pack(sacc[2*kt][0],   sacc[2*kt][1],   sh[0], sl[0]);
      split_pack(sacc[2*kt][2],   sacc[2*kt][3],   sh[1], sl[1]);
      split_pack(sacc[2*kt+1][0], sacc[2*kt+1][1], sh[2], sl[2]);
      split_pack(sacc[2*kt+1][2], sacc[2*kt+1][3], sh[3], sl[3]);
      u32 vh[8][2], vl[8][2];
      #pragma unroll
      for(int np=0; np<4; np++){
        int r = np*16 + (lane & 7) + ((lane >> 4)*8);
        int cc = koff + ((lane >> 3) & 1)*8;
        u32 r0,r1,r2,r3;
        ldsm4(r0,r1,r2,r3, smaddr(sVh + r*RPITCH + cc));
        vh[np*2][0]=r0; vh[np*2][1]=r1; vh[np*2+1][0]=r2; vh[np*2+1][1]=r3;
        ldsm4(r0,r1,r2,r3, smaddr(sVl + r*RPITCH + cc));
        vl[np*2][0]=r0; vl[np*2][1]=r1; vl[np*2+1][0]=r2; vl[np*2+1][1]=r3;
      }
      // 3 passes
      #pragma unroll
      for(int nd=0; nd<8; nd++) mma_bf(oacc[nd], sh, vh[nd][0], vh[nd][1]);
      #pragma unroll
      for(int nd=0; nd<8; nd++) mma_bf(oacc[nd], sh, vl[nd][0], vl[nd][1]);
      #pragma unroll
      for(int nd=0; nd<8; nd++) mma_bf(oacc[nd], sl, vh[nd][0], vh[nd][1]);
    }
    __syncthreads();   // V buffer free for next iter
  }
  cpwait0();

  // ---- cross-warp combine over wj halves (alias over Q area) ----
  float* Op = (float*)sm;     // 64 x pitch66
  if (wj == 0){
    #pragma unroll
    for(int nd=0; nd<8; nd++){
      int row = wi*16 + (lane >> 2);
      int d   = nd*8 + (lane & 3)*2;
      Op[row*66 + d]     = oacc[nd][0];
      Op[row*66 + d + 1] = oacc[nd][1];
      Op[(row+8)*66 + d]     = oacc[nd][2];
      Op[(row+8)*66 + d + 1] = oacc[nd][3];
    }
  }
  __syncthreads();
  if (wj == 1){
    #pragma unroll
    for(int nd=0; nd<8; nd++){
      int row = wi*16 + (lane >> 2);
      int d   = nd*8 + (lane & 3)*2;
      float a0 = oacc[nd][0] + Op[row*66 + d];
      float a1 = oacc[nd][1] + Op[row*66 + d + 1];
      float a2 = oacc[nd][2] + Op[(row+8)*66 + d];
      float a3 = oacc[nd][3] + Op[(row+8)*66 + d + 1];
      size_t r0 = (size_t)(b*Tc + i0 + row)*Ec + h*64 + d;
      size_t r1 = (size_t)(b*Tc + i0 + row + 8)*Ec + h*64 + d;
      *(float2*)&O[r0] = make_float2(a0, a1);
      *(float2*)&O[r1] = make_float2(a2, a3);
    }
  }
}

// ============================================================
// GroupNorm stats, 2-stage, fp64 accumulation
// ============================================================
__global__ void gn_part_kernel(const float* __restrict__ O){
  int g = blockIdx.x;
  int c = blockIdx.y;
  int b = g >> 4, h = g & 15, tid = threadIdx.x;
  int tbase = c * (Tc/8);
  double s = 0.0, s2 = 0.0;
  for(int idx = tid; idx < (Tc/8)*HDc/4; idx += 256){
    int t = tbase + (idx >> 4), d4 = (idx & 15)*4;
    float4 v = *(const float4*)&O[(size_t)(b*Tc + t)*Ec + h*64 + d4];
    s += (double)v.x + (double)v.y + (double)v.z + (double)v.w;
    s2 += (double)v.x*v.x + (double)v.y*v.y + (double)v.z*v.z + (double)v.w*v.w;
  }
  __shared__ double rs[256], rs2[256];
  rs[tid] = s; rs2[tid] = s2;
  __syncthreads();
  for(int off=128; off>0; off>>=1){
    if(tid < off){ rs[tid]+=rs[tid+off]; rs2[tid]+=rs2[tid+off]; }
    __syncthreads();
  }
  if(tid == 0){
    g_part[(g*8 + c)*2 + 0] = rs[0];
    g_part[(g*8 + c)*2 + 1] = rs2[0];
  }
}
__global__ void gn_final_kernel(){
  int g = threadIdx.x;
  if(g >= Bc*Hc) return;
  double s=0.0, s2=0.0;
  for(int c=0;c<8;c++){ s += g_part[(g*8+c)*2]; s2 += g_part[(g*8+c)*2+1]; }
  double N = (double)(Tc*HDc);
  double mean = s/N;
  double var  = s2/N - mean*mean;
  g_stats[g*2+0] = (float)mean;
  g_stats[g*2+1] = (float)(1.0 / sqrt(var + 1e-5));
}

// ============================================================
// Y = silu(G) * groupnorm(O)  -> split bf16, 4-wide
// ============================================================
__global__ void gate_norm4_kernel(const float* __restrict__ O, const float* __restrict__ G,
                                  const float* __restrict__ w, const float* __restrict__ bb,
                                  u16* __restrict__ Yh, u16* __restrict__ Yl)
{
  int i4 = blockIdx.x*blockDim.x + threadIdx.x;
  if(i4 >= Mc*Ec/4) return;
  int idx = i4*4;
  int row = idx >> 10, e = idx & 1023;
  int b = row >> 11;
  int g = b*Hc + (e >> 6);
  float mean = g_stats[g*2+0], rstd = g_stats[g*2+1];
  float4 ov = ((const float4*)O)[i4];
  float4 gv = ((const float4*)G)[i4];
  float4 wv = *(const float4*)&w[e];
  float4 bv = *(const float4*)&bb[e];
  float o0 = (ov.x - mean)*rstd*wv.x + bv.x;
  float o1 = (ov.y - mean)*rstd*wv.y + bv.y;
  float o2 = (ov.z - mean)*rstd*wv.z + bv.z;
  float o3 = (ov.w - mean)*rstd*wv.w + bv.w;
  float y0 = (gv.x / (1.f + __expf(-gv.x))) * o0;
  float y1 = (gv.y / (1.f + __expf(-gv.y))) * o1;
  float y2 = (gv.z / (1.f + __expf(-gv.z))) * o2;
  float y3 = (gv.w / (1.f + __expf(-gv.w))) * o3;
  u32 h01,l01,h23,l23;
  split_pack(y0, y1, h01, l01);
  split_pack(y2, y3, h23, l23);
  uint2 hv = make_uint2(h01, h23), lv = make_uint2(l01, l23);
  ((uint2*)Yh)[i4] = hv;
  ((uint2*)Yl)[i4] = lv;
}

// ============================================================
extern "C" void kernel_launch(void* const* d_in, const int* in_sizes, int n_in,
                              void* d_out, int out_size)
{
  const float* x   = (const float*)d_in[0];
  const float* Wq  = (const float*)d_in[1];
  const float* bq  = (const float*)d_in[2];
  const float* Wk  = (const float*)d_in[3];
  const float* bk  = (const float*)d_in[4];
  const float* Wv  = (const float*)d_in[5];
  const float* bv  = (const float*)d_in[6];
  const float* Wg  = (const float*)d_in[7];
  const float* bg  = (const float*)d_in[8];
  const float* Wo  = (const float*)d_in[9];
  const float* bo  = (const float*)d_in[10];
  const float* gnw = (const float*)d_in[11];
  const float* gnb = (const float*)d_in[12];
  float* out = (float*)d_out;

  u16 *xh,*xl,*Qh,*Ql,*Kh,*Kl,*Vth,*Vtl,*Yh,*Yl;
  float *Gp,*Op;
  cudaGetSymbolAddress((void**)&xh, g_xh);   cudaGetSymbolAddress((void**)&xl, g_xl);
  cudaGetSymbolAddress((void**)&Qh, g_Qh);   cudaGetSymbolAddress((void**)&Ql, g_Ql);
  cudaGetSymbolAddress((void**)&Kh, g_Kh);   cudaGetSymbolAddress((void**)&Kl, g_Kl);
  cudaGetSymbolAddress((void**)&Vth, g_Vth); cudaGetSymbolAddress((void**)&Vtl, g_Vtl);
  cudaGetSymbolAddress((void**)&Yh, g_Yh);   cudaGetSymbolAddress((void**)&Yl, g_Yl);
  cudaGetSymbolAddress((void**)&Gp, g_G);    cudaGetSymbolAddress((void**)&Op, g_O);

  // launch order puts gemm_bs at #4 and retention at #5 for ncu capture
  convertW8_kernel<<<dim3((Ec*Ec/8 + 255)/256, 5), 256>>>(Wq, Wk, Wv, Wg, Wo); // 1
  convert8_kernel<<<(Mc*Ec/8 + 255)/256, 256>>>(x, xh, xl, Mc*Ec/8);           // 2
  rope_table_kernel<<<(Tc*HDc + 255)/256, 256>>>();                            // 3

  size_t gsm = 81920;
  cudaFuncSetAttribute(gemm_bs, cudaFuncAttributeMaxDynamicSharedMemorySize, (int)gsm);
  // batched projections: z -> {Q, K, V, G}                                    // 4
  gemm_bs<<<dim3(Ec/128, Mc/128, 4), 256, gsm>>>(xh, xl, bq, bk, bv, bg, 0, nullptr);

  size_t rsm = 73728;
  cudaFuncSetAttribute(retention_mma, cudaFuncAttributeMaxDynamicSharedMemorySize, (int)rsm);
  retention_mma<<<dim3(Tc/64, Bc*Hc), 256, rsm>>>(Qh, Ql, Kh, Kl, Vth, Vtl, Op);  // 5

  gn_part_kernel<<<dim3(Bc*Hc, 8), 256>>>(Op);                                 // 6
  gn_final_kernel<<<1, 32>>>();                                                // 7

  gate_norm4_kernel<<<(Mc*Ec/4 + 255)/256, 256>>>(Op, Gp, gnw, gnb, Yh, Yl);   // 8

  // final: out = Y @ Wo^T + bo   (w = 4)                                      // 9
  gemm_bs<<<dim3(Ec/128, Mc/128, 1), 256, gsm>>>(Yh, Yl, bo, bo, bo, bo, 4, out);
}

// round 13
// speedup vs baseline: 3.0036x; 1.0825x over previous
#include <cuda_runtime.h>
#include <cuda_bf16.h>
#include <cuda_fp16.h>
#include <math.h>
#include <stdint.h>

// Problem dims (fixed)
#define Bc 2
#define Tc 2048
#define Ec 1024
#define Hc 16
#define HDc 64
#define Mc (Bc*Tc)   // 4096

typedef unsigned short u16;
typedef unsigned int   u32;

// -------- scratch (device globals; no allocation allowed) --------
__device__ u16 g_xh[Mc*Ec], g_xl[Mc*Ec];         // x bf16 split
__device__ u16 g_x16h[Mc*Ec], g_x16l[Mc*Ec];     // x fp16 split
__device__ u16 g_Wh[5*Ec*Ec], g_Wl[5*Ec*Ec];     // Wq,Wk,Wv bf16 split (slices 0..2)
__device__ u16 g_W16[2*Ec*Ec];                   // Wg, Wo single fp16
__device__ u16 g_Qh[Mc*Ec], g_Ql[Mc*Ec];
__device__ u16 g_Kh[Mc*Ec], g_Kl[Mc*Ec];
__device__ u16 g_Vth[Mc*Ec], g_Vtl[Mc*Ec];       // V transposed: [b][e][t]
__device__ u16 g_Yh[Mc*Ec], g_Yl[Mc*Ec];         // Y fp16 split
__device__ float g_G[Mc*Ec];
__device__ float g_O[Mc*Ec];
__device__ double g_part2[Bc*Hc*2];
__device__ float g_stats[Bc*Hc*2];
__device__ float g_rc[Tc*HDc], g_rs[Tc*HDc];

// ------------------- helpers -------------------
__device__ __forceinline__ u32 smaddr(const void* p){ return (u32)__cvta_generic_to_shared(p); }
__device__ __forceinline__ void cp16(u32 d, const void* s){
  asm volatile("cp.async.cg.shared.global [%0], [%1], 16;\n"::"r"(d),"l"(s));
}
__device__ __forceinline__ void cpcommit(){ asm volatile("cp.async.commit_group;\n"); }
__device__ __forceinline__ void cpwait0(){ asm volatile("cp.async.wait_group 0;\n"); }
__device__ __forceinline__ void cpwait1(){ asm volatile("cp.async.wait_group 1;\n"); }
__device__ __forceinline__ void cpwait2(){ asm volatile("cp.async.wait_group 2;\n"); }
__device__ __forceinline__ void ldsm4(u32&r0,u32&r1,u32&r2,u32&r3,u32 a){
  asm volatile("ldmatrix.sync.aligned.m8n8.x4.shared.b16 {%0,%1,%2,%3},[%4];\n"
    :"=r"(r0),"=r"(r1),"=r"(r2),"=r"(r3):"r"(a));
}
__device__ __forceinline__ void mma_bf(float* c, const u32* a, u32 b0, u32 b1){
  asm volatile("mma.sync.aligned.m16n8k16.row.col.f32.bf16.bf16.f32 "
    "{%0,%1,%2,%3},{%4,%5,%6,%7},{%8,%9},{%0,%1,%2,%3};\n"
    :"+f"(c[0]),"+f"(c[1]),"+f"(c[2]),"+f"(c[3])
    :"r"(a[0]),"r"(a[1]),"r"(a[2]),"r"(a[3]),"r"(b0),"r"(b1));
}
__device__ __forceinline__ void mma_f16(float* c, const u32* a, u32 b0, u32 b1){
  asm volatile("mma.sync.aligned.m16n8k16.row.col.f32.f16.f16.f32 "
    "{%0,%1,%2,%3},{%4,%5,%6,%7},{%8,%9},{%0,%1,%2,%3};\n"
    :"+f"(c[0]),"+f"(c[1]),"+f"(c[2]),"+f"(c[3])
    :"r"(a[0]),"r"(a[1]),"r"(a[2]),"r"(a[3]),"r"(b0),"r"(b1));
}
__device__ __forceinline__ u16 f2bf(float x){
  __nv_bfloat16 h = __float2bfloat16_rn(x);
  return *reinterpret_cast<u16*>(&h);
}
__device__ __forceinline__ float bf2f(u16 u){
  __nv_bfloat16 h; *reinterpret_cast<u16*>(&h)=u; return __bfloat162float(h);
}
__device__ __forceinline__ u16 f2h(float x){
  __half h = __float2half_rn(x);
  return *reinterpret_cast<u16*>(&h);
}
__device__ __forceinline__ float h2f(u16 u){
  __half h; *reinterpret_cast<u16*>(&h)=u; return __half2float(h);
}
__device__ __forceinline__ void split_pack(float a, float b, u32& hi, u32& lo){
  u16 ha = f2bf(a), hb = f2bf(b);
  u16 la = f2bf(a - bf2f(ha)), lb = f2bf(b - bf2f(hb));
  hi = (u32)ha | ((u32)hb << 16);
  lo = (u32)la | ((u32)lb << 16);
}
__device__ __forceinline__ void split_pack_h(float a, float b, u32& hi, u32& lo){
  u16 ha = f2h(a), hb = f2h(b);
  u16 la = f2h(a - h2f(ha)), lb = f2h(b - h2f(hb));
  hi = (u32)ha | ((u32)hb << 16);
  lo = (u32)la | ((u32)lb << 16);
}

// ------------------- rope table + zero gn partials -------------------
__global__ void rope_table_kernel() {
  int idx = blockIdx.x * blockDim.x + threadIdx.x;
  if (idx < Bc*Hc*2) g_part2[idx] = 0.0;
  if (idx >= Tc*HDc) return;
  int t = idx / HDc;
  int dd = idx % HDc;
  double f = pow(10000.0, -(double)(dd & 31) / 32.0);
  double th = (double)t * f;
  g_rc[idx] = (float)cos(th);
  g_rs[idx] = (float)sin(th);
}

// ------------------- x -> bf16 split + fp16 split, 8-wide -------------------
__global__ void convertX8_kernel(const float* __restrict__ in, int n8){
  int i = blockIdx.x*blockDim.x + threadIdx.x;
  if(i >= n8) return;
  float4 x0 = ((const float4*)in)[i*2];
  float4 x1 = ((const float4*)in)[i*2+1];
  float xs[8] = {x0.x,x0.y,x0.z,x0.w,x1.x,x1.y,x1.z,x1.w};
  u16 ha[8], la[8], h2a[8], l2a[8];
  #pragma unroll
  for(int k=0;k<8;k++){
    ha[k]=f2bf(xs[k]); la[k]=f2bf(xs[k]-bf2f(ha[k]));
    h2a[k]=f2h(xs[k]); l2a[k]=f2h(xs[k]-h2f(h2a[k]));
  }
  uint4 hv, lv, hv2, lv2;
  hv.x=(u32)ha[0]|((u32)ha[1]<<16); hv.y=(u32)ha[2]|((u32)ha[3]<<16);
  hv.z=(u32)ha[4]|((u32)ha[5]<<16); hv.w=(u32)ha[6]|((u32)ha[7]<<16);
  lv.x=(u32)la[0]|((u32)la[1]<<16); lv.y=(u32)la[2]|((u32)la[3]<<16);
  lv.z=(u32)la[4]|((u32)la[5]<<16); lv.w=(u32)la[6]|((u32)la[7]<<16);
  hv2.x=(u32)h2a[0]|((u32)h2a[1]<<16); hv2.y=(u32)h2a[2]|((u32)h2a[3]<<16);
  hv2.z=(u32)h2a[4]|((u32)h2a[5]<<16); hv2.w=(u32)h2a[6]|((u32)h2a[7]<<16);
  lv2.x=(u32)l2a[0]|((u32)l2a[1]<<16); lv2.y=(u32)l2a[2]|((u32)l2a[3]<<16);
  lv2.z=(u32)l2a[4]|((u32)l2a[5]<<16); lv2.w=(u32)l2a[6]|((u32)l2a[7]<<16);
  ((uint4*)g_xh)[i] = hv;   ((uint4*)g_xl)[i] = lv;
  ((uint4*)g_x16h)[i] = hv2; ((uint4*)g_x16l)[i] = lv2;
}
// Wq,Wk,Wv -> bf16 split (slices 0..2)
__global__ void convertW8_kernel(const float* __restrict__ w0, const float* __restrict__ w1,
                                 const float* __restrict__ w2){
  int z = blockIdx.y;
  const float* src = (z==0)?w0:(z==1)?w1:w2;
  int i = blockIdx.x*blockDim.x + threadIdx.x;
  if(i >= Ec*Ec/8) return;
  float4 x0 = ((const float4*)src)[i*2];
  float4 x1 = ((const float4*)src)[i*2+1];
  u16 ha[8], la[8];
  float xs[8] = {x0.x,x0.y,x0.z,x0.w,x1.x,x1.y,x1.z,x1.w};
  #pragma unroll
  for(int k=0;k<8;k++){ ha[k]=f2bf(xs[k]); la[k]=f2bf(xs[k]-bf2f(ha[k])); }
  uint4 hv, lv;
  hv.x=(u32)ha[0]|((u32)ha[1]<<16); hv.y=(u32)ha[2]|((u32)ha[3]<<16);
  hv.z=(u32)ha[4]|((u32)ha[5]<<16); hv.w=(u32)ha[6]|((u32)ha[7]<<16);
  lv.x=(u32)la[0]|((u32)la[1]<<16); lv.y=(u32)la[2]|((u32)la[3]<<16);
  lv.z=(u32)la[4]|((u32)la[5]<<16); lv.w=(u32)la[6]|((u32)la[7]<<16);
  size_t base = (size_t)z*(Ec*Ec/8);
  ((uint4*)g_Wh)[base + i] = hv;
  ((uint4*)g_Wl)[base + i] = lv;
}
// Wg, Wo -> single fp16
__global__ void convertW16_kernel(const float* __restrict__ wg, const float* __restrict__ wo){
  int z = blockIdx.y;
  const float* src = (z==0)?wg:wo;
  int i = blockIdx.x*blockDim.x + threadIdx.x;
  if(i >= Ec*Ec/8) return;
  float4 x0 = ((const float4*)src)[i*2];
  float4 x1 = ((const float4*)src)[i*2+1];
  float xs[8] = {x0.x,x0.y,x0.z,x0.w,x1.x,x1.y,x1.z,x1.w};
  u16 ha[8];
  #pragma unroll
  for(int k=0;k<8;k++) ha[k]=f2h(xs[k]);
  uint4 hv;
  hv.x=(u32)ha[0]|((u32)ha[1]<<16); hv.y=(u32)ha[2]|((u32)ha[3]<<16);
  hv.z=(u32)ha[4]|((u32)ha[5]<<16); hv.w=(u32)ha[6]|((u32)ha[7]<<16);
  ((uint4*)g_W16)[(size_t)z*(Ec*Ec/8) + i] = hv;
}

// ============================================================
// Tensor-core GEMM: C[m,n] = sum_k A[m,k]*W[n,k] + bias[n]
// tiles 128x128x32, 256 threads (8 warps, 2x4), warp tile 64x32.
// w = zoff + blockIdx.z:
//   w=0: Q bf16 3-term (bias+RoPE -> g_Qh/g_Ql)
//   w=1: K bf16 3-term (bias+RoPE -> g_Kh/g_Kl)
//   w=2: V bf16 3-term (bias -> transposed g_Vth/g_Vtl, smem-restaged)
//   w=3: G fp16 2-term (A=g_x16, B=g_W16[0], bias -> g_G fp32)
//   w=4: O fp16 2-term (A=g_Yh/Yl, B=g_W16[1], bias -> outf fp32)
// ============================================================
#define GPITCH 40   // halves per smem row (32 data + 8 pad) -> conflict-free
#define VP 136      // V-restage smem pitch in halves
__global__ void __launch_bounds__(256, 2)
gemm_bs(const u16* __restrict__ Ah, const u16* __restrict__ Al,
        const float* __restrict__ b0, const float* __restrict__ b1,
        const float* __restrict__ b2, const float* __restrict__ b3,
        int zoff, float* __restrict__ outf)
{
  extern __shared__ u16 sm[];
  const int K = Ec;
  int tid = threadIdx.x, lane = tid & 31, wid = tid >> 5;
  int bm = blockIdx.y * 128, bn = blockIdx.x * 128;
  int wm = wid >> 2, wn = wid & 3;
  int z = blockIdx.z, w = zoff + z;
  bool f16p = (w >= 3);
  const u16* Bh = g_Wh + (size_t)w*Ec*Ec;
  const u16* Bl = g_Wl + (size_t)w*Ec*Ec;
  const u16* A2h = (w==4) ? g_Yh : g_x16h;
  const u16* A2l = (w==4) ? g_Yl : g_x16l;
  const u16* B16 = g_W16 + (size_t)((w==4)?1:0)*Ec*Ec;
  const float* bias = (z==0)?b0:(z==1)?b1:(z==2)?b2:b3;

  float acc[4][4][4];
  #pragma unroll
  for(int i=0;i<4;i++)
    #pragma unroll
    for(int j=0;j<4;j++)
      #pragma unroll
      for(int k=0;k<4;k++) acc[i][j][k] = 0.f;

  auto load_stage = [&](int s, int k0){
    u16* st = sm + s*20480;
    if (f16p){
      const u16* srcs[3] = { A2h + (size_t)bm*K + k0, A2l + (size_t)bm*K + k0,
                             B16 + (size_t)bn*K + k0 };
      #pragma unroll
      for(int tl=0; tl<3; tl++){
        #pragma unroll
        for(int i=0;i<2;i++){
          int c = tid*2 + i;
          int r = c >> 2, seg = c & 3;
          cp16(smaddr(st + tl*5120 + r*GPITCH + seg*8),
               srcs[tl] + (size_t)r*K + seg*8);
        }
      }
    } else {
      const u16* srcs[4] = { Ah + (size_t)bm*K + k0, Al + (size_t)bm*K + k0,
                             Bh + (size_t)bn*K + k0, Bl + (size_t)bn*K + k0 };
      #pragma unroll
      for(int tl=0; tl<4; tl++){
        #pragma unroll
        for(int i=0;i<2;i++){
          int c = tid*2 + i;
          int r = c >> 2, seg = c & 3;
          cp16(smaddr(st + tl*5120 + r*GPITCH + seg*8),
               srcs[tl] + (size_t)r*K + seg*8);
        }
      }
    }
  };

  load_stage(0, 0); cpcommit();
  const int NK = K/32;   // 32
  for(int kt=0; kt<NK; kt++){
    if(kt+1 < NK) load_stage((kt+1)&1, (kt+1)*32);
    cpcommit(); cpwait1(); __syncthreads();
    u16* st  = sm + (kt&1)*20480;

    if (f16p){
      u16* sAh = st; u16* sAl = st + 5120; u16* sB = st + 10240;
      #pragma unroll
      for(int ks=0; ks<2; ks++){
        int koff = ks*16;
        u32 ah[4][4], al[4][4];
        #pragma unroll
        for(int mi=0; mi<4; mi++){
          int r = wm*64 + mi*16 + (lane & 15);
          int cc = koff + (lane >> 4)*8;
          ldsm4(ah[mi][0],ah[mi][1],ah[mi][2],ah[mi][3], smaddr(sAh + r*GPITCH + cc));
          ldsm4(al[mi][0],al[mi][1],al[mi][2],al[mi][3], smaddr(sAl + r*GPITCH + cc));
        }
        u32 bh[4][2];
        #pragma unroll
        for(int np=0; np<2; np++){
          int r = wn*32 + np*16 + (lane & 7) + ((lane >> 4)*8);
          int cc = koff + ((lane >> 3) & 1)*8;
          u32 r0,r1,r2,r3;
          ldsm4(r0,r1,r2,r3, smaddr(sB + r*GPITCH + cc));
          bh[np*2][0]=r0; bh[np*2][1]=r1; bh[np*2+1][0]=r2; bh[np*2+1][1]=r3;
        }
        #pragma unroll
        for(int mi=0; mi<4; mi++)
          #pragma unroll
          for(int nj=0; nj<4; nj++)
            mma_f16(acc[mi][nj], ah[mi], bh[nj][0], bh[nj][1]);
        #pragma unroll
        for(int mi=0; mi<4; mi++)
          #pragma unroll
          for(int nj=0; nj<4; nj++)
            mma_f16(acc[mi][nj], al[mi], bh[nj][0], bh[nj][1]);
      }
    } else {
      u16* sAh = st;          u16* sAl = st + 5120;
      u16* sBh = st + 10240;  u16* sBl = st + 15360;
      #pragma unroll
      for(int ks=0; ks<2; ks++){
        int koff = ks*16;
        u32 ah[4][4], al[4][4];
        #pragma unroll
        for(int mi=0; mi<4; mi++){
          int r = wm*64 + mi*16 + (lane & 15);
          int cc = koff + (lane >> 4)*8;
          ldsm4(ah[mi][0],ah[mi][1],ah[mi][2],ah[mi][3], smaddr(sAh + r*GPITCH + cc));
          ldsm4(al[mi][0],al[mi][1],al[mi][2],al[mi][3], smaddr(sAl + r*GPITCH + cc));
        }
        u32 bh[4][2], bl[4][2];
        #pragma unroll
        for(int np=0; np<2; np++){
          int r = wn*32 + np*16 + (lane & 7) + ((lane >> 4)*8);
          int cc = koff + ((lane >> 3) & 1)*8;
          u32 r0,r1,r2,r3;
          ldsm4(r0,r1,r2,r3, smaddr(sBh + r*GPITCH + cc));
          bh[np*2][0]=r0; bh[np*2][1]=r1; bh[np*2+1][0]=r2; bh[np*2+1][1]=r3;
          ldsm4(r0,r1,r2,r3, smaddr(sBl + r*GPITCH + cc));
          bl[np*2][0]=r0; bl[np*2][1]=r1; bl[np*2+1][0]=r2; bl[np*2+1][1]=r3;
        }
        #pragma unroll
        for(int mi=0; mi<4; mi++)
          #pragma unroll
          for(int nj=0; nj<4; nj++)
            mma_bf(acc[mi][nj], ah[mi], bh[nj][0], bh[nj][1]);
        #pragma unroll
        for(int mi=0; mi<4; mi++)
          #pragma unroll
          for(int nj=0; nj<4; nj++)
            mma_bf(acc[mi][nj], ah[mi], bl[nj][0], bl[nj][1]);
        #pragma unroll
        for(int mi=0; mi<4; mi++)
          #pragma unroll
          for(int nj=0; nj<4; nj++)
            mma_bf(acc[mi][nj], al[mi], bh[nj][0], bh[nj][1]);
      }
    }
    __syncthreads();
  }
  cpwait0();

  // epilogue
  int mode = (w < 2) ? 1 : ((w == 2) ? 2 : 0);
  if (mode == 2){
    // restage V tile through smem -> coalesced transposed stores
    __syncthreads();
    u16* svh = sm;
    u16* svl = sm + 128*VP;
    #pragma unroll
    for(int mi=0; mi<4; mi++){
      int r0l = wm*64 + mi*16 + (lane >> 2);
      #pragma unroll
      for(int nj=0; nj<4; nj++){
        int cl = wn*32 + nj*8 + (lane & 3)*2;
        int colg = bn + cl;
        float bv0 = bias[colg], bv1 = bias[colg+1];
        float v00 = acc[mi][nj][0] + bv0, v01 = acc[mi][nj][1] + bv1;
        float v10 = acc[mi][nj][2] + bv0, v11 = acc[mi][nj][3] + bv1;
        u16 h00=f2bf(v00), h01=f2bf(v01), h10=f2bf(v10), h11=f2bf(v11);
        svh[cl*VP + r0l]         = h00;  svl[cl*VP + r0l]         = f2bf(v00 - bf2f(h00));
        svh[(cl+1)*VP + r0l]     = h01;  svl[(cl+1)*VP + r0l]     = f2bf(v01 - bf2f(h01));
        svh[cl*VP + r0l + 8]     = h10;  svl[cl*VP + r0l + 8]     = f2bf(v10 - bf2f(h10));
        svh[(cl+1)*VP + r0l + 8] = h11;  svl[(cl+1)*VP + r0l + 8] = f2bf(v11 - bf2f(h11));
      }
    }
    __syncthreads();
    int bi = bm >> 11;
    int tbase = bm & (Tc-1);
    int colIdx = tid >> 1, half = tid & 1;
    size_t gbase = (size_t)bi*Ec*Tc + (size_t)(bn + colIdx)*Tc + tbase + half*64;
    const uint4* sh = (const uint4*)(svh + colIdx*VP + half*64);
    const uint4* sl = (const uint4*)(svl + colIdx*VP + half*64);
    uint4* dh = (uint4*)(g_Vth + gbase);
    uint4* dl = (uint4*)(g_Vtl + gbase);
    #pragma unroll
    for(int i=0;i<8;i++) dh[i] = sh[i];
    #pragma unroll
    for(int i=0;i<8;i++) dl[i] = sl[i];
  } else {
    #pragma unroll
    for(int mi=0; mi<4; mi++){
      int row0 = bm + wm*64 + mi*16 + (lane >> 2);
      #pragma unroll
      for(int nj=0; nj<4; nj++){
        int col = bn + wn*32 + nj*8 + (lane & 3)*2;
        float bv0 = bias[col], bv1 = bias[col+1];
        float v00 = acc[mi][nj][0] + bv0, v01 = acc[mi][nj][1] + bv1;
        float v10 = acc[mi][nj][2] + bv0, v11 = acc[mi][nj][3] + bv1;
        if (mode == 0){
          float* dst = (w == 3) ? g_G : outf;
          *(float2*)&dst[(size_t)row0*Ec + col]     = make_float2(v00, v01);
          *(float2*)&dst[(size_t)(row0+8)*Ec + col] = make_float2(v10, v11);
        } else { // mode 1: RoPE + split
          u16* oh = (w == 0) ? g_Qh : g_Kh;
          u16* ol = (w == 0) ? g_Ql : g_Kl;
          int dd = col & 63;
          int t0 = row0 & (Tc-1), t1 = (row0+8) & (Tc-1);
          float c0 = g_rc[t0*HDc+dd],   s0 = g_rs[t0*HDc+dd];
          float c1 = g_rc[t0*HDc+dd+1], s1 = g_rs[t0*HDc+dd+1];
          float y0 = v00*c0 - v01*s0;
          float y1 = v01*c1 + v00*s1;
          u32 hi, lo; split_pack(y0, y1, hi, lo);
          ((u32*)oh)[((size_t)row0*Ec + col) >> 1] = hi;
          ((u32*)ol)[((size_t)row0*Ec + col) >> 1] = lo;
          float d0 = g_rc[t1*HDc+dd],   e0 = g_rs[t1*HDc+dd];
          float d1 = g_rc[t1*HDc+dd+1], e1 = g_rs[t1*HDc+dd+1];
          float z0 = v10*d0 - v11*e0;
          float z1 = v11*d1 + v10*e1;
          split_pack(z0, z1, hi, lo);
          ((u32*)oh)[((size_t)(row0+8)*Ec + col) >> 1] = hi;
          ((u32*)ol)[((size_t)(row0+8)*Ec + col) >> 1] = lo;
        }
      }
    }
  }
}

// ============================================================
// Retention, mma.sync, split-bf16, 8 warps (warp tile 16x32):
//   O[b,h,i,:] = sum_{j>=i} gamma_h^{j-i} (Q_i.K_j/8) V_j
// + fused groupnorm partial sums (double atomicAdd into g_part2)
// ============================================================
#define RPITCH 72
__global__ void __launch_bounds__(256, 2)
retention_mma(const u16* __restrict__ Qh_, const u16* __restrict__ Ql_,
              const u16* __restrict__ Kh_, const u16* __restrict__ Kl_,
              const u16* __restrict__ Vth, const u16* __restrict__ Vtl,
              float* __restrict__ O)
{
  extern __shared__ u16 sm[];
  int tid = threadIdx.x, lane = tid & 31, wid = tid >> 5;
  int wi = wid >> 1, wj = wid & 1;
  int yy = blockIdx.y;
  int h = 15 - (yy >> 1), b = yy & 1;        // longest (h=15) first
  int it = blockIdx.x; int i0 = it*64;

  float lg2;
  { double g = 1.0 - ldexp(1.0, -(5+h)); lg2 = (float)log2(g); }

  // Q tile loads (once)
  {
    #pragma unroll
    for(int tl=0; tl<2; tl++){
      const u16* src = (tl ? Ql_ : Qh_) + (size_t)(b*Tc + i0)*Ec + h*64;
      u16* dst = sm + tl*4608;
      #pragma unroll
      for(int i=0;i<2;i++){
        int c = tid*2 + i;
        int r = c >> 3, seg = c & 7;
        cp16(smaddr(dst + r*RPITCH + seg*8), src + (size_t)r*Ec + seg*8);
      }
    }
  }
  auto load_K = [&](int s, int j0){
    u16* st = sm + 9216 + s*9216;
    const u16* sK[2] = { Kh_ + (size_t)(b*Tc + j0)*Ec + h*64,
                         Kl_ + (size_t)(b*Tc + j0)*Ec + h*64 };
    #pragma unroll
    for(int tl=0; tl<2; tl++){
      #pragma unroll
      for(int i=0;i<2;i++){
        int c = tid*2 + i;
        int r = c >> 3, seg = c & 7;
        cp16(smaddr(st + tl*4608 + r*RPITCH + seg*8), sK[tl] + (size_t)r*Ec + seg*8);
      }
    }
  };
  auto load_V = [&](int j0){
    u16* st = sm + 27648;
    const u16* sV[2] = { Vth + (size_t)b*Ec*Tc + (size_t)(h*64)*Tc + j0,
                         Vtl + (size_t)b*Ec*Tc + (size_t)(h*64)*Tc + j0 };
    #pragma unroll
    for(int tl=0; tl<2; tl++){
      #pragma unroll
      for(int i=0;i<2;i++){
        int c = tid*2 + i;
        int r = c >> 3, seg = c & 7;
        cp16(smaddr(st + tl*4608 + r*RPITCH + seg*8), sV[tl] + (size_t)r*Tc + seg*8);
      }
    }
  };

  float inv = -lg2;
  int jtEnd = (i0 + 63 + (int)(20.0f/inv)) / 64;
  if (jtEnd > Tc/64 - 1) jtEnd = Tc/64 - 1;

  load_K(0, it*64);
  cpcommit();

  float rowF[2], colF[4][2];
  int   ilv[2],  jlv[4][2];
  #pragma unroll
  for(int hf=0; hf<2; hf++){
    int il = wi*16 + (lane >> 2) + hf*8;
    ilv[hf] = il;
    rowF[hf] = exp2f(-(float)il * lg2);
  }
  #pragma unroll
  for(int nj=0; nj<4; nj++)
    #pragma unroll
    for(int cp=0; cp<2; cp++){
      int jl = wj*32 + nj*8 + (lane & 3)*2 + cp;
      jlv[nj][cp] = jl;
      colF[nj][cp] = exp2f((float)jl * lg2);
    }

  float oacc[8][4];
  #pragma unroll
  for(int j=0;j<8;j++)
    #pragma unroll
    for(int k=0;k<4;k++) oacc[j][k]=0.f;

  u16* sQh = sm; u16* sQl = sm + 4608;
  u16* sVh = sm + 27648; u16* sVl = sm + 32256;

  for(int jt = it; jt <= jtEnd; jt++){
    int s = (jt - it) & 1;
    load_V(jt*64); cpcommit();
    bool havK = (jt + 1 <= jtEnd);
    if (havK){ load_K(s^1, (jt+1)*64); cpcommit(); }
    if (havK) cpwait2(); else cpwait1();
    __syncthreads();
    u16 *sKh = sm + 9216 + s*9216, *sKl = sKh + 4608;

    // ---- phase A: S = Q K^T ----
    float sacc[4][4];
    #pragma unroll
    for(int j=0;j<4;j++)
      #pragma unroll
      for(int k=0;k<4;k++) sacc[j][k]=0.f;

    #pragma unroll
    for(int ks=0; ks<4; ks++){
      int koff = ks*16;
      u32 qh[4], ql[4];
      {
        int r = wi*16 + (lane & 15);
        int cc = koff + (lane >> 4)*8;
        ldsm4(qh[0],qh[1],qh[2],qh[3], smaddr(sQh + r*RPITCH + cc));
        ldsm4(ql[0],ql[1],ql[2],ql[3], smaddr(sQl + r*RPITCH + cc));
      }
      u32 kh[4][2], kl[4][2];
      #pragma unroll
      for(int np=0; np<2; np++){
        int r = wj*32 + np*16 + (lane & 7) + ((lane >> 4)*8);
        int cc = koff + ((lane >> 3) & 1)*8;
        u32 r0,r1,r2,r3;
        ldsm4(r0,r1,r2,r3, smaddr(sKh + r*RPITCH + cc));
        kh[np*2][0]=r0; kh[np*2][1]=r1; kh[np*2+1][0]=r2; kh[np*2+1][1]=r3;
        ldsm4(r0,r1,r2,r3, smaddr(sKl + r*RPITCH + cc));
        kl[np*2][0]=r0; kl[np*2][1]=r1; kl[np*2+1][0]=r2; kl[np*2+1][1]=r3;
      }
      #pragma unroll
      for(int nj=0; nj<4; nj++) mma_bf(sacc[nj], qh, kh[nj][0], kh[nj][1]);
      #pragma unroll
      for(int nj=0; nj<4; nj++) mma_bf(sacc[nj], qh, kl[nj][0], kl[nj][1]);
      #pragma unroll
      for(int nj=0; nj<4; nj++) mma_bf(sacc[nj], ql, kh[nj][0], kh[nj][1]);
    }

    // ---- decay + mask + 1/8 ----
    float base = exp2f((float)((jt-it)*64) * lg2) * 0.125f;
    bool diag = (jt == it);
    #pragma unroll
    for(int nj=0; nj<4; nj++){
      float f00 = base*rowF[0]*colF[nj][0];
      float f01 = base*rowF[0]*colF[nj][1];
      float f10 = base*rowF[1]*colF[nj][0];
      float f11 = base*rowF[1]*colF[nj][1];
      if (diag){
        if (jlv[nj][0] < ilv[0]) f00 = 0.f;
        if (jlv[nj][1] < ilv[0]) f01 = 0.f;
        if (jlv[nj][0] < ilv[1]) f10 = 0.f;
        if (jlv[nj][1] < ilv[1]) f11 = 0.f;
      }
      sacc[nj][0] *= f00; sacc[nj][1] *= f01;
      sacc[nj][2] *= f10; sacc[nj][3] *= f11;
    }

    if (havK) cpwait1(); else cpwait0();
    __syncthreads();

    // ---- phase B: O += S V ----
    #pragma unroll
    for(int kt=0; kt<2; kt++){
      int koff = wj*32 + kt*16;
      u32 sh[4], sl[4];
      split_pack(sacc[2*kt][0],   sacc[2*kt][1],   sh[0], sl[0]);
      split_pack(sacc[2*kt][2],   sacc[2*kt][3],   sh[1], sl[1]);
      split_pack(sacc[2*kt+1][0], sacc[2*kt+1][1], sh[2], sl[2]);
      split_pack(sacc[2*kt+1][2], sacc[2*kt+1][3], sh[3], sl[3]);
      u32 vh[8][2], vl[8][2];
      #pragma unroll
      for(int np=0; np<4; np++){
        int r = np*16 + (lane & 7) + ((lane >> 4)*8);
        int cc = koff + ((lane >> 3) & 1)*8;
        u32 r0,r1,r2,r3;
        ldsm4(r0,r1,r2,r3, smaddr(sVh + r*RPITCH + cc));
        vh[np*2][0]=r0; vh[np*2][1]=r1; vh[np*2+1][0]=r2; vh[np*2+1][1]=r3;
        ldsm4(r0,r1,r2,r3, smaddr(sVl + r*RPITCH + cc));
        vl[np*2][0]=r0; vl[np*2][1]=r1; vl[np*2+1][0]=r2; vl[np*2+1][1]=r3;
      }
      #pragma unroll
      for(int nd=0; nd<8; nd++) mma_bf(oacc[nd], sh, vh[nd][0], vh[nd][1]);
      #pragma unroll
      for(int nd=0; nd<8; nd++) mma_bf(oacc[nd], sh, vl[nd][0], vl[nd][1]);
      #pragma unroll
      for(int nd=0; nd<8; nd++) mma_bf(oacc[nd], sl, vh[nd][0], vh[nd][1]);
    }
    __syncthreads();
  }
  cpwait0();

  // ---- cross-warp combine + O write + fused gn partials ----
  float* Op = (float*)sm;
  if (wj == 0){
    #pragma unroll
    for(int nd=0; nd<8; nd++){
      int row = wi*16 + (lane >> 2);
      int d   = nd*8 + (lane & 3)*2;
      Op[row*66 + d]     = oacc[nd][0];
      Op[row*66 + d + 1] = oacc[nd][1];
      Op[(row+8)*66 + d]     = oacc[nd][2];
      Op[(row+8)*66 + d + 1] = oacc[nd][3];
    }
  }
  __syncthreads();
  if (wj == 1){
    double ls = 0.0, ls2 = 0.0;
    #pragma unroll
    for(int nd=0; nd<8; nd++){
      int row = wi*16 + (lane >> 2);
      int d   = nd*8 + (lane & 3)*2;
      float a0 = oacc[nd][0] + Op[row*66 + d];
      float a1 = oacc[nd][1] + Op[row*66 + d + 1];
      float a2 = oacc[nd][2] + Op[(row+8)*66 + d];
      float a3 = oacc[nd][3] + Op[(row+8)*66 + d + 1];
      size_t r0 = (size_t)(b*Tc + i0 + row)*Ec + h*64 + d;
      size_t r1 = (size_t)(b*Tc + i0 + row + 8)*Ec + h*64 + d;
      *(float2*)&O[r0] = make_float2(a0, a1);
      *(float2*)&O[r1] = make_float2(a2, a3);
      ls  += (double)a0 + (double)a1 + (double)a2 + (double)a3;
      ls2 += (double)a0*a0 + (double)a1*a1 + (double)a2*a2 + (double)a3*a3;
    }
    #pragma unroll
    for(int off=16; off>0; off>>=1){
      ls  += __shfl_xor_sync(0xffffffffu, ls,  off);
      ls2 += __shfl_xor_sync(0xffffffffu, ls2, off);
    }
    if (lane == 0){
      int g = b*Hc + h;
      atomicAdd(&g_part2[g*2 + 0], ls);
      atomicAdd(&g_part2[g*2 + 1], ls2);
    }
  }
}

// ============================================================
// GroupNorm final stats from fused partials
// ============================================================
__global__ void gn_final_kernel(){
  int g = threadIdx.x;
  if(g >= Bc*Hc) return;
  double s = g_part2[g*2 + 0], s2 = g_part2[g*2 + 1];
  double N = (double)(Tc*HDc);
  double mean = s/N;
  double var  = s2/N - mean*mean;
  g_stats[g*2+0] = (float)mean;
  g_stats[g*2+1] = (float)(1.0 / sqrt(var + 1e-5));
}

// ============================================================
// Y = silu(G) * groupnorm(O)  -> fp16 split, 4-wide
// ============================================================
__global__ void gate_norm4_kernel(const float* __restrict__ O, const float* __restrict__ G,
                                  const float* __restrict__ w, const float* __restrict__ bb,
                                  u16* __restrict__ Yh, u16* __restrict__ Yl)
{
  int i4 = blockIdx.x*blockDim.x + threadIdx.x;
  if(i4 >= Mc*Ec/4) return;
  int idx = i4*4;
  int row = idx >> 10, e = idx & 1023;
  int b = row >> 11;
  int g = b*Hc + (e >> 6);
  float mean = g_stats[g*2+0], rstd = g_stats[g*2+1];
  float4 ov = ((const float4*)O)[i4];
  float4 gv = ((const float4*)G)[i4];
  float4 wv = *(const float4*)&w[e];
  float4 bv = *(const float4*)&bb[e];
  float o0 = (ov.x - mean)*rstd*wv.x + bv.x;
  float o1 = (ov.y - mean)*rstd*wv.y + bv.y;
  float o2 = (ov.z - mean)*rstd*wv.z + bv.z;
  float o3 = (ov.w - mean)*rstd*wv.w + bv.w;
  float y0 = (gv.x / (1.f + __expf(-gv.x))) * o0;
  float y1 = (gv.y / (1.f + __expf(-gv.y))) * o1;
  float y2 = (gv.z / (1.f + __expf(-gv.z))) * o2;
  float y3 = (gv.w / (1.f + __expf(-gv.w))) * o3;
  u32 h01,l01,h23,l23;
  split_pack_h(y0, y1, h01, l01);
  split_pack_h(y2, y3, h23, l23);
  uint2 hv = make_uint2(h01, h23), lv = make_uint2(l01, l23);
  ((uint2*)Yh)[i4] = hv;
  ((uint2*)Yl)[i4] = lv;
}

// ============================================================
extern "C" void kernel_launch(void* const* d_in, const int* in_sizes, int n_in,
                              void* d_out, int out_size)
{
  const float* x   = (const float*)d_in[0];
  const float* Wq  = (const float*)d_in[1];
  const float* bq  = (const float*)d_in[2];
  const float* Wk  = (const float*)d_in[3];
  const float* bk  = (const float*)d_in[4];
  const float* Wv  = (const float*)d_in[5];
  const float* bv  = (const float*)d_in[6];
  const float* Wg  = (const float*)d_in[7];
  const float* bg  = (const float*)d_in[8];
  const float* Wo  = (const float*)d_in[9];
  const float* bo  = (const float*)d_in[10];
  const float* gnw = (const float*)d_in[11];
  const float* gnb = (const float*)d_in[12];
  float* out = (float*)d_out;

  u16 *xh,*xl,*Qh,*Ql,*Kh,*Kl,*Vth,*Vtl,*Yh,*Yl;
  float *Gp,*Op;
  cudaGetSymbolAddress((void**)&xh, g_xh);   cudaGetSymbolAddress((void**)&xl, g_xl);
  cudaGetSymbolAddress((void**)&Qh, g_Qh);   cudaGetSymbolAddress((void**)&Ql, g_Ql);
  cudaGetSymbolAddress((void**)&Kh, g_Kh);   cudaGetSymbolAddress((void**)&Kl, g_Kl);
  cudaGetSymbolAddress((void**)&Vth, g_Vth); cudaGetSymbolAddress((void**)&Vtl, g_Vtl);
  cudaGetSymbolAddress((void**)&Yh, g_Yh);   cudaGetSymbolAddress((void**)&Yl, g_Yl);
  cudaGetSymbolAddress((void**)&Gp, g_G);    cudaGetSymbolAddress((void**)&Op, g_O);

  convertW8_kernel<<<dim3((Ec*Ec/8 + 255)/256, 3), 256>>>(Wq, Wk, Wv);          // 1
  convertW16_kernel<<<dim3((Ec*Ec/8 + 255)/256, 2), 256>>>(Wg, Wo);             // 2
  convertX8_kernel<<<(Mc*Ec/8 + 255)/256, 256>>>(x, Mc*Ec/8);                   // 3
  rope_table_kernel<<<(Tc*HDc + 255)/256, 256>>>();                             // 4

  size_t gsm = 81920;
  cudaFuncSetAttribute(gemm_bs, cudaFuncAttributeMaxDynamicSharedMemorySize, (int)gsm);
  // batched projections: z -> {Q, K, V, G(fp16 2-term)}                        // 5
  gemm_bs<<<dim3(Ec/128, Mc/128, 4), 256, gsm>>>(xh, xl, bq, bk, bv, bg, 0, nullptr);

  size_t rsm = 73728;
  cudaFuncSetAttribute(retention_mma, cudaFuncAttributeMaxDynamicSharedMemorySize, (int)rsm);
  retention_mma<<<dim3(Tc/64, Bc*Hc), 256, rsm>>>(Qh, Ql, Kh, Kl, Vth, Vtl, Op);   // 6

  gn_final_kernel<<<1, 32>>>();                                                 // 7

  gate_norm4_kernel<<<(Mc*Ec/4 + 255)/256, 256>>>(Op, Gp, gnw, gnb, Yh, Yl);    // 8

  // final: out = Y @ Wo^T + bo  (fp16 2-term, w = 4)                           // 9
  gemm_bs<<<dim3(Ec/128, Mc/128, 1), 256, gsm>>>(Yh, Yl, bo, bo, bo, bo, 4, out);
}

// round 16
// speedup vs baseline: 3.6406x; 1.2121x over previous
#include <cuda_runtime.h>
#include <cuda_bf16.h>
#include <cuda_fp16.h>
#include <math.h>
#include <stdint.h>

// Problem dims (fixed)
#define Bc 2
#define Tc 2048
#define Ec 1024
#define Hc 16
#define HDc 64
#define Mc (Bc*Tc)   // 4096

typedef unsigned short u16;
typedef unsigned int   u32;

// -------- scratch (device globals; no allocation allowed) --------
__device__ u16 g_x16h[Mc*Ec], g_x16l[Mc*Ec];     // x fp16 split
__device__ u16 g_W16[5*Ec*Ec];                   // Wq,Wk,Wv,Wg,Wo single fp16
__device__ u16 g_Qh[Mc*Ec], g_Ql[Mc*Ec];         // fp16 split
__device__ u16 g_Kh[Mc*Ec], g_Kl[Mc*Ec];         // fp16 split
__device__ u16 g_Vth[Mc*Ec], g_Vtl[Mc*Ec];       // V transposed [b][e][t], fp16 split
__device__ u16 g_Yh[Mc*Ec], g_Yl[Mc*Ec];         // Y fp16 split
__device__ float g_G[Mc*Ec];
__device__ float g_O[Mc*Ec];
__device__ double g_part2[Bc*Hc*2];
__device__ float g_stats[Bc*Hc*2];
__device__ float g_rc[Tc*HDc], g_rs[Tc*HDc];

// ------------------- helpers -------------------
__device__ __forceinline__ u32 smaddr(const void* p){ return (u32)__cvta_generic_to_shared(p); }
__device__ __forceinline__ void cp16(u32 d, const void* s){
  asm volatile("cp.async.cg.shared.global [%0], [%1], 16;\n"::"r"(d),"l"(s));
}
__device__ __forceinline__ void cpcommit(){ asm volatile("cp.async.commit_group;\n"); }
__device__ __forceinline__ void cpwait0(){ asm volatile("cp.async.wait_group 0;\n"); }
__device__ __forceinline__ void cpwait1(){ asm volatile("cp.async.wait_group 1;\n"); }
__device__ __forceinline__ void cpwait2(){ asm volatile("cp.async.wait_group 2;\n"); }
__device__ __forceinline__ void ldsm4(u32&r0,u32&r1,u32&r2,u32&r3,u32 a){
  asm volatile("ldmatrix.sync.aligned.m8n8.x4.shared.b16 {%0,%1,%2,%3},[%4];\n"
    :"=r"(r0),"=r"(r1),"=r"(r2),"=r"(r3):"r"(a));
}
__device__ __forceinline__ void mma_f16(float* c, const u32* a, u32 b0, u32 b1){
  asm volatile("mma.sync.aligned.m16n8k16.row.col.f32.f16.f16.f32 "
    "{%0,%1,%2,%3},{%4,%5,%6,%7},{%8,%9},{%0,%1,%2,%3};\n"
    :"+f"(c[0]),"+f"(c[1]),"+f"(c[2]),"+f"(c[3])
    :"r"(a[0]),"r"(a[1]),"r"(a[2]),"r"(a[3]),"r"(b0),"r"(b1));
}
__device__ __forceinline__ u16 f2h(float x){
  __half h = __float2half_rn(x);
  return *reinterpret_cast<u16*>(&h);
}
__device__ __forceinline__ float h2f(u16 u){
  __half h; *reinterpret_cast<u16*>(&h)=u; return __half2float(h);
}
__device__ __forceinline__ void split_pack_h(float a, float b, u32& hi, u32& lo){
  u16 ha = f2h(a), hb = f2h(b);
  u16 la = f2h(a - h2f(ha)), lb = f2h(b - h2f(hb));
  hi = (u32)ha | ((u32)hb << 16);
  lo = (u32)la | ((u32)lb << 16);
}

// ------------------- rope table (cheap fp64 + fp32 sincos) -------------------
__global__ void rope_table_kernel() {
  int idx = blockIdx.x * blockDim.x + threadIdx.x;
  if (idx < Bc*Hc*2) g_part2[idx] = 0.0;
  if (idx >= Tc*HDc) return;
  int t = idx / HDc;
  int e = (idx % HDc) & 31;
  // f = (10000^{-1/32})^e by pow-by-squaring (exact to ~5e-16)
  double f = 1.0, p = 0.74989420933245582;   // 10^-0.125
  int ee = e;
  #pragma unroll 5
  for(int it5=0; it5<5; it5++){ if(ee & 1) f *= p; p *= p; ee >>= 1; }
  double th = (double)t * f;
  const double TWO_PI = 6.2831853071795864769;
  double k = floor(th * (1.0/TWO_PI) + 0.5);
  float rr = (float)(th - k*TWO_PI);         // in [-pi, pi]
  float s, c;
  sincosf(rr, &s, &c);
  g_rc[idx] = c;
  g_rs[idx] = s;
}

// ------------------- x -> fp16 split, 8-wide -------------------
__global__ void convertX8_kernel(const float* __restrict__ in, int n8){
  int i = blockIdx.x*blockDim.x + threadIdx.x;
  if(i >= n8) return;
  float4 x0 = ((const float4*)in)[i*2];
  float4 x1 = ((const float4*)in)[i*2+1];
  float xs[8] = {x0.x,x0.y,x0.z,x0.w,x1.x,x1.y,x1.z,x1.w};
  u16 ha[8], la[8];
  #pragma unroll
  for(int k=0;k<8;k++){ ha[k]=f2h(xs[k]); la[k]=f2h(xs[k]-h2f(ha[k])); }
  uint4 hv, lv;
  hv.x=(u32)ha[0]|((u32)ha[1]<<16); hv.y=(u32)ha[2]|((u32)ha[3]<<16);
  hv.z=(u32)ha[4]|((u32)ha[5]<<16); hv.w=(u32)ha[6]|((u32)ha[7]<<16);
  lv.x=(u32)la[0]|((u32)la[1]<<16); lv.y=(u32)la[2]|((u32)la[3]<<16);
  lv.z=(u32)la[4]|((u32)la[5]<<16); lv.w=(u32)la[6]|((u32)la[7]<<16);
  ((uint4*)g_x16h)[i] = hv;
  ((uint4*)g_x16l)[i] = lv;
}
// all 5 weights -> single fp16
__global__ void convertW16_kernel(const float* __restrict__ w0, const float* __restrict__ w1,
                                  const float* __restrict__ w2, const float* __restrict__ w3,
                                  const float* __restrict__ w4){
  int z = blockIdx.y;
  const float* src = (z==0)?w0:(z==1)?w1:(z==2)?w2:(z==3)?w3:w4;
  int i = blockIdx.x*blockDim.x + threadIdx.x;
  if(i >= Ec*Ec/8) return;
  float4 x0 = ((const float4*)src)[i*2];
  float4 x1 = ((const float4*)src)[i*2+1];
  float xs[8] = {x0.x,x0.y,x0.z,x0.w,x1.x,x1.y,x1.z,x1.w};
  u16 ha[8];
  #pragma unroll
  for(int k=0;k<8;k++) ha[k]=f2h(xs[k]);
  uint4 hv;
  hv.x=(u32)ha[0]|((u32)ha[1]<<16); hv.y=(u32)ha[2]|((u32)ha[3]<<16);
  hv.z=(u32)ha[4]|((u32)ha[5]<<16); hv.w=(u32)ha[6]|((u32)ha[7]<<16);
  ((uint4*)g_W16)[(size_t)z*(Ec*Ec/8) + i] = hv;
}

// ============================================================
// fp16 2-term tensor-core GEMM: C = (Ah+Al) @ W16^T + bias
// tiles 128x128x32, 256 threads (8 warps, 2x4), warp tile 64x32.
// w = zoff + blockIdx.z:
//   w=0: Q (bias+RoPE -> g_Qh/g_Ql fp16 split)
//   w=1: K (bias+RoPE -> g_Kh/g_Kl)
//   w=2: V (bias -> transposed g_Vth/g_Vtl, smem-restaged)
//   w=3: G (bias -> g_G fp32)
//   w=4: O (A=g_Yh/Yl, bias -> outf fp32)
// ============================================================
#define GPITCH 40   // halves per smem row (32 data + 8 pad) -> conflict-free
#define VP 136      // V-restage smem pitch in halves
__global__ void __launch_bounds__(256, 2)
gemm_bs(const u16* __restrict__ Ah_, const u16* __restrict__ Al_,
        const float* __restrict__ b0, const float* __restrict__ b1,
        const float* __restrict__ b2, const float* __restrict__ b3,
        int zoff, float* __restrict__ outf)
{
  extern __shared__ u16 sm[];
  const int K = Ec;
  int tid = threadIdx.x, lane = tid & 31, wid = tid >> 5;
  int bm = blockIdx.y * 128, bn = blockIdx.x * 128;
  int wm = wid >> 2, wn = wid & 3;
  int z = blockIdx.z, w = zoff + z;
  const u16* Ah = (w==4) ? g_Yh : Ah_;
  const u16* Al = (w==4) ? g_Yl : Al_;
  const u16* B16 = g_W16 + (size_t)w*Ec*Ec;
  const float* bias = (z==0)?b0:(z==1)?b1:(z==2)?b2:b3;

  float acc[4][4][4];
  #pragma unroll
  for(int i=0;i<4;i++)
    #pragma unroll
    for(int j=0;j<4;j++)
      #pragma unroll
      for(int k=0;k<4;k++) acc[i][j][k] = 0.f;

  auto load_stage = [&](int s, int k0){
    u16* st = sm + s*15360;
    const u16* srcs[3] = { Ah + (size_t)bm*K + k0, Al + (size_t)bm*K + k0,
                           B16 + (size_t)bn*K + k0 };
    #pragma unroll
    for(int tl=0; tl<3; tl++){
      #pragma unroll
      for(int i=0;i<2;i++){
        int c = tid*2 + i;          // 0..511
        int r = c >> 2, seg = c & 3;
        cp16(smaddr(st + tl*5120 + r*GPITCH + seg*8),
             srcs[tl] + (size_t)r*K + seg*8);
      }
    }
  };

  load_stage(0, 0); cpcommit();
  const int NK = K/32;   // 32
  for(int kt=0; kt<NK; kt++){
    if(kt+1 < NK) load_stage((kt+1)&1, (kt+1)*32);
    cpcommit(); cpwait1(); __syncthreads();
    u16* st  = sm + (kt&1)*15360;
    u16* sAh = st; u16* sAl = st + 5120; u16* sB = st + 10240;

    #pragma unroll
    for(int ks=0; ks<2; ks++){
      int koff = ks*16;
      u32 ah[4][4], al[4][4];
      #pragma unroll
      for(int mi=0; mi<4; mi++){
        int r = wm*64 + mi*16 + (lane & 15);
        int cc = koff + (lane >> 4)*8;
        ldsm4(ah[mi][0],ah[mi][1],ah[mi][2],ah[mi][3], smaddr(sAh + r*GPITCH + cc));
        ldsm4(al[mi][0],al[mi][1],al[mi][2],al[mi][3], smaddr(sAl + r*GPITCH + cc));
      }
      u32 bh[4][2];
      #pragma unroll
      for(int np=0; np<2; np++){
        int r = wn*32 + np*16 + (lane & 7) + ((lane >> 4)*8);
        int cc = koff + ((lane >> 3) & 1)*8;
        u32 r0,r1,r2,r3;
        ldsm4(r0,r1,r2,r3, smaddr(sB + r*GPITCH + cc));
        bh[np*2][0]=r0; bh[np*2][1]=r1; bh[np*2+1][0]=r2; bh[np*2+1][1]=r3;
      }
      #pragma unroll
      for(int mi=0; mi<4; mi++)
        #pragma unroll
        for(int nj=0; nj<4; nj++)
          mma_f16(acc[mi][nj], ah[mi], bh[nj][0], bh[nj][1]);
      #pragma unroll
      for(int mi=0; mi<4; mi++)
        #pragma unroll
        for(int nj=0; nj<4; nj++)
          mma_f16(acc[mi][nj], al[mi], bh[nj][0], bh[nj][1]);
    }
    __syncthreads();
  }
  cpwait0();

  // epilogue
  int mode = (w < 2) ? 1 : ((w == 2) ? 2 : 0);
  if (mode == 2){
    // restage V tile through smem -> coalesced transposed stores (fp16 split)
    __syncthreads();
    u16* svh = sm;
    u16* svl = sm + 128*VP;
    #pragma unroll
    for(int mi=0; mi<4; mi++){
      int r0l = wm*64 + mi*16 + (lane >> 2);
      #pragma unroll
      for(int nj=0; nj<4; nj++){
        int cl = wn*32 + nj*8 + (lane & 3)*2;
        int colg = bn + cl;
        float bv0 = bias[colg], bv1 = bias[colg+1];
        float v00 = acc[mi][nj][0] + bv0, v01 = acc[mi][nj][1] + bv1;
        float v10 = acc[mi][nj][2] + bv0, v11 = acc[mi][nj][3] + bv1;
        u16 h00=f2h(v00), h01=f2h(v01), h10=f2h(v10), h11=f2h(v11);
        svh[cl*VP + r0l]         = h00;  svl[cl*VP + r0l]         = f2h(v00 - h2f(h00));
        svh[(cl+1)*VP + r0l]     = h01;  svl[(cl+1)*VP + r0l]     = f2h(v01 - h2f(h01));
        svh[cl*VP + r0l + 8]     = h10;  svl[cl*VP + r0l + 8]     = f2h(v10 - h2f(h10));
        svh[(cl+1)*VP + r0l + 8] = h11;  svl[(cl+1)*VP + r0l + 8] = f2h(v11 - h2f(h11));
      }
    }
    __syncthreads();
    int bi = bm >> 11;
    int tbase = bm & (Tc-1);
    int colIdx = tid >> 1, half = tid & 1;
    size_t gbase = (size_t)bi*Ec*Tc + (size_t)(bn + colIdx)*Tc + tbase + half*64;
    const uint4* sh = (const uint4*)(svh + colIdx*VP + half*64);
    const uint4* sl = (const uint4*)(svl + colIdx*VP + half*64);
    uint4* dh = (uint4*)(g_Vth + gbase);
    uint4* dl = (uint4*)(g_Vtl + gbase);
    #pragma unroll
    for(int i=0;i<8;i++) dh[i] = sh[i];
    #pragma unroll
    for(int i=0;i<8;i++) dl[i] = sl[i];
  } else {
    #pragma unroll
    for(int mi=0; mi<4; mi++){
      int row0 = bm + wm*64 + mi*16 + (lane >> 2);
      #pragma unroll
      for(int nj=0; nj<4; nj++){
        int col = bn + wn*32 + nj*8 + (lane & 3)*2;
        float bv0 = bias[col], bv1 = bias[col+1];
        float v00 = acc[mi][nj][0] + bv0, v01 = acc[mi][nj][1] + bv1;
        float v10 = acc[mi][nj][2] + bv0, v11 = acc[mi][nj][3] + bv1;
        if (mode == 0){
          float* dst = (w == 3) ? g_G : outf;
          *(float2*)&dst[(size_t)row0*Ec + col]     = make_float2(v00, v01);
          *(float2*)&dst[(size_t)(row0+8)*Ec + col] = make_float2(v10, v11);
        } else { // mode 1: RoPE + fp16 split
          u16* oh = (w == 0) ? g_Qh : g_Kh;
          u16* ol = (w == 0) ? g_Ql : g_Kl;
          int dd = col & 63;
          int t0 = row0 & (Tc-1), t1 = (row0+8) & (Tc-1);
          float c0 = g_rc[t0*HDc+dd],   s0 = g_rs[t0*HDc+dd];
          float c1 = g_rc[t0*HDc+dd+1], s1 = g_rs[t0*HDc+dd+1];
          float y0 = v00*c0 - v01*s0;
          float y1 = v01*c1 + v00*s1;
          u32 hi, lo; split_pack_h(y0, y1, hi, lo);
          ((u32*)oh)[((size_t)row0*Ec + col) >> 1] = hi;
          ((u32*)ol)[((size_t)row0*Ec + col) >> 1] = lo;
          float d0 = g_rc[t1*HDc+dd],   e0 = g_rs[t1*HDc+dd];
          float d1 = g_rc[t1*HDc+dd+1], e1 = g_rs[t1*HDc+dd+1];
          float z0 = v10*d0 - v11*e0;
          float z1 = v11*d1 + v10*e1;
          split_pack_h(z0, z1, hi, lo);
          ((u32*)oh)[((size_t)(row0+8)*Ec + col) >> 1] = hi;
          ((u32*)ol)[((size_t)(row0+8)*Ec + col) >> 1] = lo;
        }
      }
    }
  }
}

// ============================================================
// Retention, mma.sync fp16 3-term, 8 warps (warp tile 16x32):
//   O[b,h,i,:] = sum_{j>=i} gamma_h^{j-i} (Q_i.K_j/8) V_j
// + fused groupnorm partial sums (double atomicAdd into g_part2)
// ============================================================
#define RPITCH 72
__global__ void __launch_bounds__(256, 2)
retention_mma(const u16* __restrict__ Qh_, const u16* __restrict__ Ql_,
              const u16* __restrict__ Kh_, const u16* __restrict__ Kl_,
              const u16* __restrict__ Vth, const u16* __restrict__ Vtl,
              float* __restrict__ O)
{
  extern __shared__ u16 sm[];
  int tid = threadIdx.x, lane = tid & 31, wid = tid >> 5;
  int wi = wid >> 1, wj = wid & 1;
  int yy = blockIdx.y;
  int h = 15 - (yy >> 1), b = yy & 1;        // longest (h=15) first
  int it = blockIdx.x; int i0 = it*64;

  float lg2;
  { double g = 1.0 - ldexp(1.0, -(5+h)); lg2 = (float)log2(g); }

  // Q tile loads (once)
  {
    #pragma unroll
    for(int tl=0; tl<2; tl++){
      const u16* src = (tl ? Ql_ : Qh_) + (size_t)(b*Tc + i0)*Ec + h*64;
      u16* dst = sm + tl*4608;
      #pragma unroll
      for(int i=0;i<2;i++){
        int c = tid*2 + i;
        int r = c >> 3, seg = c & 7;
        cp16(smaddr(dst + r*RPITCH + seg*8), src + (size_t)r*Ec + seg*8);
      }
    }
  }
  auto load_K = [&](int s, int j0){
    u16* st = sm + 9216 + s*9216;
    const u16* sK[2] = { Kh_ + (size_t)(b*Tc + j0)*Ec + h*64,
                         Kl_ + (size_t)(b*Tc + j0)*Ec + h*64 };
    #pragma unroll
    for(int tl=0; tl<2; tl++){
      #pragma unroll
      for(int i=0;i<2;i++){
        int c = tid*2 + i;
        int r = c >> 3, seg = c & 7;
        cp16(smaddr(st + tl*4608 + r*RPITCH + seg*8), sK[tl] + (size_t)r*Ec + seg*8);
      }
    }
  };
  auto load_V = [&](int j0){
    u16* st = sm + 27648;
    const u16* sV[2] = { Vth + (size_t)b*Ec*Tc + (size_t)(h*64)*Tc + j0,
                         Vtl + (size_t)b*Ec*Tc + (size_t)(h*64)*Tc + j0 };
    #pragma unroll
    for(int tl=0; tl<2; tl++){
      #pragma unroll
      for(int i=0;i<2;i++){
        int c = tid*2 + i;
        int r = c >> 3, seg = c & 7;
        cp16(smaddr(st + tl*4608 + r*RPITCH + seg*8), sV[tl] + (size_t)r*Tc + seg*8);
      }
    }
  };

  float inv = -lg2;
  int jtEnd = (i0 + 63 + (int)(20.0f/inv)) / 64;
  if (jtEnd > Tc/64 - 1) jtEnd = Tc/64 - 1;

  load_K(0, it*64);
  cpcommit();

  float rowF[2], colF[4][2];
  int   ilv[2],  jlv[4][2];
  #pragma unroll
  for(int hf=0; hf<2; hf++){
    int il = wi*16 + (lane >> 2) + hf*8;
    ilv[hf] = il;
    rowF[hf] = exp2f(-(float)il * lg2);
  }
  #pragma unroll
  for(int nj=0; nj<4; nj++)
    #pragma unroll
    for(int cp=0; cp<2; cp++){
      int jl = wj*32 + nj*8 + (lane & 3)*2 + cp;
      jlv[nj][cp] = jl;
      colF[nj][cp] = exp2f((float)jl * lg2);
    }

  float oacc[8][4];
  #pragma unroll
  for(int j=0;j<8;j++)
    #pragma unroll
    for(int k=0;k<4;k++) oacc[j][k]=0.f;

  u16* sQh = sm; u16* sQl = sm + 4608;
  u16* sVh = sm + 27648; u16* sVl = sm + 32256;

  for(int jt = it; jt <= jtEnd; jt++){
    int s = (jt - it) & 1;
    load_V(jt*64); cpcommit();
    bool havK = (jt + 1 <= jtEnd);
    if (havK){ load_K(s^1, (jt+1)*64); cpcommit(); }
    if (havK) cpwait2(); else cpwait1();
    __syncthreads();
    u16 *sKh = sm + 9216 + s*9216, *sKl = sKh + 4608;

    // ---- phase A: S = Q K^T ----
    float sacc[4][4];
    #pragma unroll
    for(int j=0;j<4;j++)
      #pragma unroll
      for(int k=0;k<4;k++) sacc[j][k]=0.f;

    #pragma unroll
    for(int ks=0; ks<4; ks++){
      int koff = ks*16;
      u32 qh[4], ql[4];
      {
        int r = wi*16 + (lane & 15);
        int cc = koff + (lane >> 4)*8;
        ldsm4(qh[0],qh[1],qh[2],qh[3], smaddr(sQh + r*RPITCH + cc));
        ldsm4(ql[0],ql[1],ql[2],ql[3], smaddr(sQl + r*RPITCH + cc));
      }
      u32 kh[4][2], kl[4][2];
      #pragma unroll
      for(int np=0; np<2; np++){
        int r = wj*32 + np*16 + (lane & 7) + ((lane >> 4)*8);
        int cc = koff + ((lane >> 3) & 1)*8;
        u32 r0,r1,r2,r3;
        ldsm4(r0,r1,r2,r3, smaddr(sKh + r*RPITCH + cc));
        kh[np*2][0]=r0; kh[np*2][1]=r1; kh[np*2+1][0]=r2; kh[np*2+1][1]=r3;
        ldsm4(r0,r1,r2,r3, smaddr(sKl + r*RPITCH + cc));
        kl[np*2][0]=r0; kl[np*2][1]=r1; kl[np*2+1][0]=r2; kl[np*2+1][1]=r3;
      }
      #pragma unroll
      for(int nj=0; nj<4; nj++) mma_f16(sacc[nj], qh, kh[nj][0], kh[nj][1]);
      #pragma unroll
      for(int nj=0; nj<4; nj++) mma_f16(sacc[nj], qh, kl[nj][0], kl[nj][1]);
      #pragma unroll
      for(int nj=0; nj<4; nj++) mma_f16(sacc[nj], ql, kh[nj][0], kh[nj][1]);
    }

    // ---- decay + mask + 1/8 ----
    float base = exp2f((float)((jt-it)*64) * lg2) * 0.125f;
    bool diag = (jt == it);
    #pragma unroll
    for(int nj=0; nj<4; nj++){
      float f00 = base*rowF[0]*colF[nj][0];
      float f01 = base*rowF[0]*colF[nj][1];
      float f10 = base*rowF[1]*colF[nj][0];
      float f11 = base*rowF[1]*colF[nj][1];
      if (diag){
        if (jlv[nj][0] < ilv[0]) f00 = 0.f;
        if (jlv[nj][1] < ilv[0]) f01 = 0.f;
        if (jlv[nj][0] < ilv[1]) f10 = 0.f;
        if (jlv[nj][1] < ilv[1]) f11 = 0.f;
      }
      sacc[nj][0] *= f00; sacc[nj][1] *= f01;
      sacc[nj][2] *= f10; sacc[nj][3] *= f11;
    }

    if (havK) cpwait1(); else cpwait0();
    __syncthreads();

    // ---- phase B: O += S V (fp16 split repack) ----
    #pragma unroll
    for(int kt=0; kt<2; kt++){
      int koff = wj*32 + kt*16;
      u32 sh[4], sl[4];
      split_pack_h(sacc[2*kt][0],   sacc[2*kt][1],   sh[0], sl[0]);
      split_pack_h(sacc[2*kt][2],   sacc[2*kt][3],   sh[1], sl[1]);
      split_pack_h(sacc[2*kt+1][0], sacc[2*kt+1][1], sh[2], sl[2]);
      split_pack_h(sacc[2*kt+1][2], sacc[2*kt+1][3], sh[3], sl[3]);
      u32 vh[8][2], vl[8][2];
      #pragma unroll
      for(int np=0; np<4; np++){
        int r = np*16 + (lane & 7) + ((lane >> 4)*8);
        int cc = koff + ((lane >> 3) & 1)*8;
        u32 r0,r1,r2,r3;
        ldsm4(r0,r1,r2,r3, smaddr(sVh + r*RPITCH + cc));
        vh[np*2][0]=r0; vh[np*2][1]=r1; vh[np*2+1][0]=r2; vh[np*2+1][1]=r3;
        ldsm4(r0,r1,r2,r3, smaddr(sVl + r*RPITCH + cc));
        vl[np*2][0]=r0; vl[np*2][1]=r1; vl[np*2+1][0]=r2; vl[np*2+1][1]=r3;
      }
      #pragma unroll
      for(int nd=0; nd<8; nd++) mma_f16(oacc[nd], sh, vh[nd][0], vh[nd][1]);
      #pragma unroll
      for(int nd=0; nd<8; nd++) mma_f16(oacc[nd], sh, vl[nd][0], vl[nd][1]);
      #pragma unroll
      for(int nd=0; nd<8; nd++) mma_f16(oacc[nd], sl, vh[nd][0], vh[nd][1]);
    }
    __syncthreads();
  }
  cpwait0();

  // ---- cross-warp combine + O write + fused gn partials ----
  float* Op = (float*)sm;
  if (wj == 0){
    #pragma unroll
    for(int nd=0; nd<8; nd++){
      int row = wi*16 + (lane >> 2);
      int d   = nd*8 + (lane & 3)*2;
      Op[row*66 + d]     = oacc[nd][0];
      Op[row*66 + d + 1] = oacc[nd][1];
      Op[(row+8)*66 + d]     = oacc[nd][2];
      Op[(row+8)*66 + d + 1] = oacc[nd][3];
    }
  }
  __syncthreads();
  if (wj == 1){
    double ls = 0.0, ls2 = 0.0;
    #pragma unroll
    for(int nd=0; nd<8; nd++){
      int row = wi*16 + (lane >> 2);
      int d   = nd*8 + (lane & 3)*2;
      float a0 = oacc[nd][0] + Op[row*66 + d];
      float a1 = oacc[nd][1] + Op[row*66 + d + 1];
      float a2 = oacc[nd][2] + Op[(row+8)*66 + d];
      float a3 = oacc[nd][3] + Op[(row+8)*66 + d + 1];
      size_t r0 = (size_t)(b*Tc + i0 + row)*Ec + h*64 + d;
      size_t r1 = (size_t)(b*Tc + i0 + row + 8)*Ec + h*64 + d;
      *(float2*)&O[r0] = make_float2(a0, a1);
      *(float2*)&O[r1] = make_float2(a2, a3);
      ls  += (double)a0 + (double)a1 + (double)a2 + (double)a3;
      ls2 += (double)a0*a0 + (double)a1*a1 + (double)a2*a2 + (double)a3*a3;
    }
    #pragma unroll
    for(int off=16; off>0; off>>=1){
      ls  += __shfl_xor_sync(0xffffffffu, ls,  off);
      ls2 += __shfl_xor_sync(0xffffffffu, ls2, off);
    }
    if (lane == 0){
      int g = b*Hc + h;
      atomicAdd(&g_part2[g*2 + 0], ls);
      atomicAdd(&g_part2[g*2 + 1], ls2);
    }
  }
}

// ============================================================
// GroupNorm final stats from fused partials
// ============================================================
__global__ void gn_final_kernel(){
  int g = threadIdx.x;
  if(g >= Bc*Hc) return;
  double s = g_part2[g*2 + 0], s2 = g_part2[g*2 + 1];
  double N = (double)(Tc*HDc);
  double mean = s/N;
  double var  = s2/N - mean*mean;
  g_stats[g*2+0] = (float)mean;
  g_stats[g*2+1] = (float)(1.0 / sqrt(var + 1e-5));
}

// ============================================================
// Y = silu(G) * groupnorm(O)  -> fp16 split, 4-wide
// ============================================================
__global__ void gate_norm4_kernel(const float* __restrict__ O, const float* __restrict__ G,
                                  const float* __restrict__ w, const float* __restrict__ bb,
                                  u16* __restrict__ Yh, u16* __restrict__ Yl)
{
  int i4 = blockIdx.x*blockDim.x + threadIdx.x;
  if(i4 >= Mc*Ec/4) return;
  int idx = i4*4;
  int row = idx >> 10, e = idx & 1023;
  int b = row >> 11;
  int g = b*Hc + (e >> 6);
  float mean = g_stats[g*2+0], rstd = g_stats[g*2+1];
  float4 ov = ((const float4*)O)[i4];
  float4 gv = ((const float4*)G)[i4];
  float4 wv = *(const float4*)&w[e];
  float4 bv = *(const float4*)&bb[e];
  float o0 = (ov.x - mean)*rstd*wv.x + bv.x;
  float o1 = (ov.y - mean)*rstd*wv.y + bv.y;
  float o2 = (ov.z - mean)*rstd*wv.z + bv.z;
  float o3 = (ov.w - mean)*rstd*wv.w + bv.w;
  float y0 = (gv.x / (1.f + __expf(-gv.x))) * o0;
  float y1 = (gv.y / (1.f + __expf(-gv.y))) * o1;
  float y2 = (gv.z / (1.f + __expf(-gv.z))) * o2;
  float y3 = (gv.w / (1.f + __expf(-gv.w))) * o3;
  u32 h01,l01,h23,l23;
  split_pack_h(y0, y1, h01, l01);
  split_pack_h(y2, y3, h23, l23);
  uint2 hv = make_uint2(h01, h23), lv = make_uint2(l01, l23);
  ((uint2*)Yh)[i4] = hv;
  ((uint2*)Yl)[i4] = lv;
}

// ============================================================
extern "C" void kernel_launch(void* const* d_in, const int* in_sizes, int n_in,
                              void* d_out, int out_size)
{
  const float* x   = (const float*)d_in[0];
  const float* Wq  = (const float*)d_in[1];
  const float* bq  = (const float*)d_in[2];
  const float* Wk  = (const float*)d_in[3];
  const float* bk  = (const float*)d_in[4];
  const float* Wv  = (const float*)d_in[5];
  const float* bv  = (const float*)d_in[6];
  const float* Wg  = (const float*)d_in[7];
  const float* bg  = (const float*)d_in[8];
  const float* Wo  = (const float*)d_in[9];
  const float* bo  = (const float*)d_in[10];
  const float* gnw = (const float*)d_in[11];
  const float* gnb = (const float*)d_in[12];
  float* out = (float*)d_out;

  u16 *xh,*xl,*Qh,*Ql,*Kh,*Kl,*Vth,*Vtl,*Yh,*Yl;
  float *Gp,*Op;
  cudaGetSymbolAddress((void**)&xh, g_x16h); cudaGetSymbolAddress((void**)&xl, g_x16l);
  cudaGetSymbolAddress((void**)&Qh, g_Qh);   cudaGetSymbolAddress((void**)&Ql, g_Ql);
  cudaGetSymbolAddress((void**)&Kh, g_Kh);   cudaGetSymbolAddress((void**)&Kl, g_Kl);
  cudaGetSymbolAddress((void**)&Vth, g_Vth); cudaGetSymbolAddress((void**)&Vtl, g_Vtl);
  cudaGetSymbolAddress((void**)&Yh, g_Yh);   cudaGetSymbolAddress((void**)&Yl, g_Yl);
  cudaGetSymbolAddress((void**)&Gp, g_G);    cudaGetSymbolAddress((void**)&Op, g_O);

  convertW16_kernel<<<dim3((Ec*Ec/8 + 255)/256, 5), 256>>>(Wq, Wk, Wv, Wg, Wo); // 1
  convertX8_kernel<<<(Mc*Ec/8 + 255)/256, 256>>>(x, Mc*Ec/8);                   // 2
  rope_table_kernel<<<(Tc*HDc + 255)/256, 256>>>();                             // 3

  size_t gsm = 81920;
  cudaFuncSetAttribute(gemm_bs, cudaFuncAttributeMaxDynamicSharedMemorySize, (int)gsm);
  // batched projections: z -> {Q, K, V, G}                                     // 4
  gemm_bs<<<dim3(Ec/128, Mc/128, 4), 256, gsm>>>(xh, xl, bq, bk, bv, bg, 0, nullptr);

  size_t rsm = 73728;
  cudaFuncSetAttribute(retention_mma, cudaFuncAttributeMaxDynamicSharedMemorySize, (int)rsm);
  retention_mma<<<dim3(Tc/64, Bc*Hc), 256, rsm>>>(Qh, Ql, Kh, Kl, Vth, Vtl, Op);   // 5

  gn_final_kernel<<<1, 32>>>();                                                 // 6

  gate_norm4_kernel<<<(Mc*Ec/4 + 255)/256, 256>>>(Op, Gp, gnw, gnb, Yh, Yl);    // 7

  // final: out = Y @ Wo^T + bo  (w = 4)                                        // 8
  gemm_bs<<<dim3(Ec/128, Mc/128, 1), 256, gsm>>>(Yh, Yl, bo, bo, bo, bo, 4, out);
}